// round 12
// baseline (speedup 1.0000x reference)
#include <cuda_runtime.h>
#include <cuda_bf16.h>
#include <math.h>
#include <stdint.h>

// Shapes (fixed)
#define Bc   2
#define Lc   4096
#define Dc   1024
#define Hc   16
#define DHc  64
#define Mc   256
#define BHc  32
#define ROWS 8192   // B*L

typedef __nv_bfloat16 bf16;

// -------- scratch (device globals; no allocations allowed) --------
__device__ bf16  g_qfhi [(size_t)BHc * Lc * Mc];
__device__ bf16  g_qflo [(size_t)BHc * Lc * Mc];
__device__ bf16  g_kfthi[(size_t)BHc * Mc * Lc];
__device__ bf16  g_kftlo[(size_t)BHc * Mc * Lc];
__device__ bf16  g_vthi [(size_t)BHc * DHc * Lc];
__device__ bf16  g_vtlo [(size_t)BHc * DHc * Lc];
__device__ float g_kvtf [(size_t)BHc * DHc * Mc];
__device__ bf16  g_kvthi[(size_t)BHc * DHc * Mc];
__device__ bf16  g_kvtlo[(size_t)BHc * DHc * Mc];
__device__ float g_ksum [(size_t)BHc * Mc];
__device__ float g_z    [(size_t)BHc * Lc];
__device__ float g_y    [(size_t)ROWS * Dc];
__device__ bf16  g_ahi  [(size_t)ROWS * Dc];
__device__ bf16  g_alo  [(size_t)ROWS * Dc];
__device__ bf16  g_bthi [(size_t)4 * Dc * Dc];
__device__ bf16  g_btlo [(size_t)4 * Dc * Dc];
__device__ bf16  g_qhi  [(size_t)ROWS * Dc];
__device__ bf16  g_qlo  [(size_t)ROWS * Dc];
__device__ bf16  g_khi  [(size_t)ROWS * Dc];
__device__ bf16  g_klo  [(size_t)ROWS * Dc];
__device__ bf16  g_phi  [(size_t)Hc * Mc * DHc];
__device__ bf16  g_plo  [(size_t)Hc * Mc * DHc];

// ================= baseline-PTX tensor-core helpers (sm_80+) ==========
__device__ __forceinline__ uint32_t smem_u32(const void* p) {
    uint32_t a;
    asm("{ .reg .u64 t; cvta.to.shared.u64 t, %1; cvt.u32.u64 %0, t; }"
        : "=r"(a) : "l"(p));
    return a;
}
__device__ __forceinline__ void cp_async16(uint32_t saddr, const void* g) {
    asm volatile("cp.async.cg.shared.global [%0], [%1], 16;"
                 :: "r"(saddr), "l"(g) : "memory");
}
#define CP_COMMIT() asm volatile("cp.async.commit_group;" ::: "memory")
#define CP_WAIT(n)  asm volatile("cp.async.wait_group %0;" :: "n"(n) : "memory")

__device__ __forceinline__ void ldsm_x4(uint32_t r[4], uint32_t addr) {
    asm volatile("ldmatrix.sync.aligned.m8n8.x4.shared.b16 {%0,%1,%2,%3}, [%4];"
                 : "=r"(r[0]), "=r"(r[1]), "=r"(r[2]), "=r"(r[3]) : "r"(addr));
}
__device__ __forceinline__ void mma16816(float c[4], const uint32_t a[4],
                                         uint32_t b0, uint32_t b1) {
    asm volatile(
        "mma.sync.aligned.m16n8k16.row.col.f32.bf16.bf16.f32 "
        "{%0,%1,%2,%3}, {%4,%5,%6,%7}, {%8,%9}, {%0,%1,%2,%3};"
        : "+f"(c[0]), "+f"(c[1]), "+f"(c[2]), "+f"(c[3])
        : "r"(a[0]), "r"(a[1]), "r"(a[2]), "r"(a[3]), "r"(b0), "r"(b1));
}
__device__ __forceinline__ void split2(float v, bf16& h, bf16& l) {
    h = __float2bfloat16_rn(v);
    l = __float2bfloat16_rn(v - __bfloat162float(h));
}

// ============================================================
// fp32 -> (hi, lo) bf16 split
// ============================================================
__global__ __launch_bounds__(256) void split_kernel(
    const float* __restrict__ in, bf16* __restrict__ hi,
    bf16* __restrict__ lo, int n4)
{
    int i = blockIdx.x * 256 + threadIdx.x;
    if (i >= n4) return;
    float4 v = ((const float4*)in)[i];
    bf16 h0, h1, h2, h3, l0, l1, l2, l3;
    split2(v.x, h0, l0); split2(v.y, h1, l1);
    split2(v.z, h2, l2); split2(v.w, h3, l3);
    ((__nv_bfloat162*)hi)[2*i]   = __halves2bfloat162(h0, h1);
    ((__nv_bfloat162*)hi)[2*i+1] = __halves2bfloat162(h2, h3);
    ((__nv_bfloat162*)lo)[2*i]   = __halves2bfloat162(l0, l1);
    ((__nv_bfloat162*)lo)[2*i+1] = __halves2bfloat162(l2, l3);
}

// ============================================================
// 4 weights [K,N] -> W^T [N,K] bf16 hi/lo, single launch (z = which W)
// ============================================================
__global__ void tsplit4_kernel(
    const float* __restrict__ W0, const float* __restrict__ W1,
    const float* __restrict__ W2, const float* __restrict__ W3,
    bf16* __restrict__ Thi, bf16* __restrict__ Tlo)
{
    __shared__ float t[32][33];
    const float* W = (blockIdx.z == 0) ? W0 : (blockIdx.z == 1) ? W1
                    : (blockIdx.z == 2) ? W2 : W3;
    bf16* th = Thi + (size_t)blockIdx.z * Dc * Dc;
    bf16* tl = Tlo + (size_t)blockIdx.z * Dc * Dc;
    int bx = blockIdx.x * 32, by = blockIdx.y * 32;
    int tx = threadIdx.x, ty = threadIdx.y;   // 32 x 8
#pragma unroll
    for (int i = 0; i < 32; i += 8)
        t[ty + i][tx] = W[(size_t)(by + ty + i) * Dc + bx + tx];
    __syncthreads();
#pragma unroll
    for (int i = 0; i < 32; i += 8) {
        float v = t[tx][ty + i];
        int orow = bx + ty + i, ocol = by + tx;
        bf16 h, l; split2(v, h, l);
        th[(size_t)orow * Dc + ocol] = h;
        tl[(size_t)orow * Dc + ocol] = l;
    }
}

// ============================================================
// bf16x3 FUSED-PASS tensor-core GEMM.
// MODE 0 (fused QKV): which=bn>>10: 0->Qhi/Qlo, 1->Khi/Klo (x qalpha),
//                     2 -> V transposed hi/lo DIRECTLY to vthi/vtlo [bh][d][l]
// MODE 1: fp32 C with exact GELU. 2 CTAs/SM.
// ============================================================
#define LDT 40
#define GNITF 32                           // 1024 / 32 k-tiles
#define GEMM_MSTG (128 * LDT * 2)          // 10240 B per matrix
#define GEMM_STAGE (4 * GEMM_MSTG)         // 40960 B per stage
#define GEMM_SMEMF (2 * GEMM_STAGE)        // 81920 B
#define VT_LDS 136                         // transpose smem stride (272 B)

template<int MODE>
__global__ __launch_bounds__(256, 2) void mma_gemm_kernel(
    const bf16* __restrict__ Ahi, const bf16* __restrict__ Alo,
    const bf16* __restrict__ Bhi, const bf16* __restrict__ Blo,
    float* __restrict__ Cv,
    bf16* __restrict__ Qhi, bf16* __restrict__ Qlo,
    bf16* __restrict__ Khi, bf16* __restrict__ Klo,
    bf16* __restrict__ Vhi, bf16* __restrict__ Vlo,
    float qalpha)
{
    extern __shared__ char gsm[];
    const int tid  = threadIdx.x;
    const int lane = tid & 31, wid = tid >> 5;
    const int bm = blockIdx.y * 128;
    const int bn = blockIdx.x * 128;
    const int wm = (wid >> 2) * 64;
    const int wn = (wid & 3) * 32;

    uint32_t ah_b[2], al_b[2], bh_b[2], bl_b[2];
#pragma unroll
    for (int s = 0; s < 2; s++) {
        uint32_t base = smem_u32(gsm + s * GEMM_STAGE);
        ah_b[s] = base;
        al_b[s] = base + GEMM_MSTG;
        bh_b[s] = base + 2 * GEMM_MSTG;
        bl_b[s] = base + 3 * GEMM_MSTG;
    }

    const int a_row = wm + (lane & 15);
    const int a_col = (lane >> 4) << 3;
    const int b_row = wn + (lane & 7) + ((lane >> 4) << 3);
    const int b_col = ((lane >> 3) & 1) << 3;

    const int g_row0 = tid >> 2;
    const int g_c8   = (tid & 3) << 3;

    auto stage = [&](int kt) {
        const int s  = kt & 1;
        const int kk = kt << 5;
#pragma unroll
        for (int i = 0; i < 2; i++) {
            int row = g_row0 + i * 64;
            uint32_t soff = (uint32_t)(row * LDT + g_c8) * 2;
            const size_t ga = (size_t)(bm + row) * Dc + kk + g_c8;
            const size_t gb = (size_t)(bn + row) * Dc + kk + g_c8;
            cp_async16(ah_b[s] + soff, Ahi + ga);
            cp_async16(al_b[s] + soff, Alo + ga);
            cp_async16(bh_b[s] + soff, Bhi + gb);
            cp_async16(bl_b[s] + soff, Blo + gb);
        }
        CP_COMMIT();
    };

    float acc[4][4][4];
#pragma unroll
    for (int mi = 0; mi < 4; mi++)
#pragma unroll
        for (int ni = 0; ni < 4; ni++)
#pragma unroll
            for (int e = 0; e < 4; e++) acc[mi][ni][e] = 0.f;

    stage(0); stage(1);

    for (int kt = 0; kt < GNITF; kt++) {
        const int s = kt & 1;
        if (kt + 1 < GNITF) CP_WAIT(1); else CP_WAIT(0);
        __syncthreads();

#pragma unroll
        for (int k0 = 0; k0 < 32; k0 += 16) {
            uint32_t bh_[2][4], bl_[2][4];
#pragma unroll
            for (int pr = 0; pr < 2; pr++) {
                uint32_t boff = (uint32_t)((b_row + pr * 16) * LDT + k0 + b_col) * 2;
                ldsm_x4(bh_[pr], bh_b[s] + boff);
                ldsm_x4(bl_[pr], bl_b[s] + boff);
            }
            uint32_t a[4][4];
#pragma unroll
            for (int mi = 0; mi < 4; mi++)
                ldsm_x4(a[mi], ah_b[s] +
                        (uint32_t)((a_row + mi * 16) * LDT + k0 + a_col) * 2);
#pragma unroll
            for (int mi = 0; mi < 4; mi++) {
                mma16816(acc[mi][0], a[mi], bh_[0][0], bh_[0][1]);
                mma16816(acc[mi][1], a[mi], bh_[0][2], bh_[0][3]);
                mma16816(acc[mi][2], a[mi], bh_[1][0], bh_[1][1]);
                mma16816(acc[mi][3], a[mi], bh_[1][2], bh_[1][3]);
            }
#pragma unroll
            for (int mi = 0; mi < 4; mi++) {
                mma16816(acc[mi][0], a[mi], bl_[0][0], bl_[0][1]);
                mma16816(acc[mi][1], a[mi], bl_[0][2], bl_[0][3]);
                mma16816(acc[mi][2], a[mi], bl_[1][0], bl_[1][1]);
                mma16816(acc[mi][3], a[mi], bl_[1][2], bl_[1][3]);
            }
#pragma unroll
            for (int mi = 0; mi < 4; mi++)
                ldsm_x4(a[mi], al_b[s] +
                        (uint32_t)((a_row + mi * 16) * LDT + k0 + a_col) * 2);
#pragma unroll
            for (int mi = 0; mi < 4; mi++) {
                mma16816(acc[mi][0], a[mi], bh_[0][0], bh_[0][1]);
                mma16816(acc[mi][1], a[mi], bh_[0][2], bh_[0][3]);
                mma16816(acc[mi][2], a[mi], bh_[1][0], bh_[1][1]);
                mma16816(acc[mi][3], a[mi], bh_[1][2], bh_[1][3]);
            }
        }
        __syncthreads();
        if (kt + 2 < GNITF) stage(kt + 2);
    }

    const int orow = bm + wm + (lane >> 2);
    const int occ0 = wn + ((lane & 3) << 1);

    if (MODE == 0) {
        const int which = bn >> 10;        // 0 q, 1 k, 2 v
        const int bnl = bn & 1023;
        if (which < 2) {
            bf16* Oh = which ? Khi : Qhi;
            bf16* Ol = which ? Klo : Qlo;
#pragma unroll
            for (int mi = 0; mi < 4; mi++)
#pragma unroll
                for (int ni = 0; ni < 4; ni++) {
                    const size_t i0 = (size_t)(orow + mi * 16) * Dc + bnl + occ0 + ni * 8;
                    const size_t i1 = (size_t)(orow + mi * 16 + 8) * Dc + bnl + occ0 + ni * 8;
                    bf16 h0,l0,h1,l1,h2,l2,h3,l3;
                    split2(acc[mi][ni][0] * qalpha, h0, l0);
                    split2(acc[mi][ni][1] * qalpha, h1, l1);
                    split2(acc[mi][ni][2] * qalpha, h2, l2);
                    split2(acc[mi][ni][3] * qalpha, h3, l3);
                    *(__nv_bfloat162*)&Oh[i0] = __halves2bfloat162(h0, h1);
                    *(__nv_bfloat162*)&Oh[i1] = __halves2bfloat162(h2, h3);
                    *(__nv_bfloat162*)&Ol[i0] = __halves2bfloat162(l0, l1);
                    *(__nv_bfloat162*)&Ol[i1] = __halves2bfloat162(l2, l3);
                }
        } else {
            // V: transpose+split in (now free) smem, then coalesced store
            // to vthi/vtlo [bh][d][l].  trans layout: [128 d][VT_LDS l] bf16.
            bf16* th = (bf16*)gsm;
            bf16* tl = th + 128 * VT_LDS;
            const int lr  = wm + (lane >> 2);          // local l row
            const int cc0 = wn + ((lane & 3) << 1);    // local d col
#pragma unroll
            for (int mi = 0; mi < 4; mi++) {
                const int r0 = lr + mi * 16;
                const int r1 = r0 + 8;
#pragma unroll
                for (int ni = 0; ni < 4; ni++) {
                    const int c = cc0 + ni * 8;
                    bf16 h, l;
                    split2(acc[mi][ni][0], h, l);
                    th[c * VT_LDS + r0] = h;       tl[c * VT_LDS + r0] = l;
                    split2(acc[mi][ni][1], h, l);
                    th[(c + 1) * VT_LDS + r0] = h; tl[(c + 1) * VT_LDS + r0] = l;
                    split2(acc[mi][ni][2], h, l);
                    th[c * VT_LDS + r1] = h;       tl[c * VT_LDS + r1] = l;
                    split2(acc[mi][ni][3], h, l);
                    th[(c + 1) * VT_LDS + r1] = h; tl[(c + 1) * VT_LDS + r1] = l;
                }
            }
            __syncthreads();
            const int b   = bm >> 12;        // tile fits in one b (4096%128==0)
            const int l0g = bm & 4095;
#pragma unroll
            for (int i = 0; i < 8; i++) {
                int idx  = tid + i * 256;        // 0..2047
                int drow = idx >> 4;             // 0..127
                int c16  = (idx & 15) << 3;      // l offset, 8 bf16 = 16B
                int dg = bnl + drow;
                int hh = dg >> 6, dd = dg & 63;
                size_t o = ((size_t)(b * 16 + hh) * 64 + dd) * Lc + l0g + c16;
                *(uint4*)&Vhi[o] = *(uint4*)&th[drow * VT_LDS + c16];
                *(uint4*)&Vlo[o] = *(uint4*)&tl[drow * VT_LDS + c16];
            }
        }
    } else {
#pragma unroll
        for (int mi = 0; mi < 4; mi++)
#pragma unroll
            for (int ni = 0; ni < 4; ni++) {
                float v0 = acc[mi][ni][0], v1 = acc[mi][ni][1];
                float v2 = acc[mi][ni][2], v3 = acc[mi][ni][3];
                v0 = 0.5f * v0 * (1.f + erff(v0 * 0.70710678118654752f));
                v1 = 0.5f * v1 * (1.f + erff(v1 * 0.70710678118654752f));
                v2 = 0.5f * v2 * (1.f + erff(v2 * 0.70710678118654752f));
                v3 = 0.5f * v3 * (1.f + erff(v3 * 0.70710678118654752f));
                const size_t i0 = (size_t)(orow + mi * 16) * Dc + bn + occ0 + ni * 8;
                const size_t i1 = (size_t)(orow + mi * 16 + 8) * Dc + bn + occ0 + ni * 8;
                *(float2*)&Cv[i0] = make_float2(v0, v1);
                *(float2*)&Cv[i1] = make_float2(v2, v3);
            }
    }
}

// ============================================================
// FAVOR+ feature via mma.sync bf16x3 — fused passes (R11, unchanged)
// ============================================================
#define FLDK 72
#define FEAT2_SMEM ((128 + 128 + 256 + 256) * FLDK * 2 + 128 * 4 + 4 * 128 * 4 + 256 * 4)

template<int OMODE>
__global__ __launch_bounds__(256) void feature_mma_kernel(
    const bf16* __restrict__ Uhi, const bf16* __restrict__ Ulo,
    const bf16* __restrict__ Phi, const bf16* __restrict__ Plo,
    bf16* __restrict__ Fhi, bf16* __restrict__ Flo,
    float* __restrict__ ksum)
{
    extern __shared__ char fsm[];
    bf16* us_h = (bf16*)fsm;
    bf16* us_l = us_h + 128 * FLDK;
    bf16* ps_h = us_l + 128 * FLDK;
    bf16* ps_l = ps_h + 256 * FLDK;
    float* diag   = (float*)(ps_l + 256 * FLDK);
    float* rmaxp  = diag + 128;
    float* colsum = rmaxp + 4 * 128;

    const int bh = blockIdx.y;
    const int b = bh >> 4, h = bh & 15;
    const int l0 = blockIdx.x * 128;
    const int tid = threadIdx.x;
    const int lane = tid & 31, wid = tid >> 5;

#pragma unroll
    for (int i = 0; i < 4; i++) {
        int s = tid + i * 256;
        int r = s >> 3, c8 = (s & 7) << 3;
        size_t gi = (size_t)(b * Lc + l0 + r) * Dc + h * DHc + c8;
        *(uint4*)&us_h[r * FLDK + c8] = *(const uint4*)&Uhi[gi];
        *(uint4*)&us_l[r * FLDK + c8] = *(const uint4*)&Ulo[gi];
    }
#pragma unroll
    for (int i = 0; i < 8; i++) {
        int s = tid + i * 256;
        int r = s >> 3, c8 = (s & 7) << 3;
        size_t gi = (size_t)(h * Mc + r) * DHc + c8;
        *(uint4*)&ps_h[r * FLDK + c8] = *(const uint4*)&Phi[gi];
        *(uint4*)&ps_l[r * FLDK + c8] = *(const uint4*)&Plo[gi];
    }
    __syncthreads();

    if (tid < 128) {
        float s = 0.f;
#pragma unroll
        for (int d2 = 0; d2 < 32; d2++) {
            __nv_bfloat162 hh = *(__nv_bfloat162*)&us_h[tid * FLDK + d2 * 2];
            __nv_bfloat162 ll = *(__nv_bfloat162*)&us_l[tid * FLDK + d2 * 2];
            float u0 = __bfloat162float(hh.x) + __bfloat162float(ll.x);
            float u1 = __bfloat162float(hh.y) + __bfloat162float(ll.y);
            s += u0 * u0 + u1 * u1;
        }
        diag[tid] = 0.5f * s;
    }

    const int wm = (wid >> 2) * 64;
    const int wn = (wid & 3) * 64;
    const int a_row = wm + (lane & 15);
    const int a_col = (lane >> 4) << 3;
    const int b_row = wn + (lane & 7) + ((lane >> 4) << 3);
    const int b_col = ((lane >> 3) & 1) << 3;

    float acc[4][8][4];
#pragma unroll
    for (int mi = 0; mi < 4; mi++)
#pragma unroll
        for (int ni = 0; ni < 8; ni++)
#pragma unroll
            for (int e = 0; e < 4; e++) acc[mi][ni][e] = 0.f;

    const uint32_t ush = smem_u32(us_h), usl = smem_u32(us_l);
    const uint32_t psh = smem_u32(ps_h), psl = smem_u32(ps_l);
    __syncthreads();

#pragma unroll
    for (int k0 = 0; k0 < 64; k0 += 16) {
        uint32_t ah[4][4], al[4][4], bfr[4][4];
#pragma unroll
        for (int mi = 0; mi < 4; mi++) {
            uint32_t aoff = (uint32_t)((a_row + mi * 16) * FLDK + k0 + a_col) * 2;
            ldsm_x4(ah[mi], ush + aoff);
            ldsm_x4(al[mi], usl + aoff);
        }
#pragma unroll
        for (int pr = 0; pr < 4; pr++)
            ldsm_x4(bfr[pr], psh + (uint32_t)((b_row + pr * 16) * FLDK + k0 + b_col) * 2);
#pragma unroll
        for (int mi = 0; mi < 4; mi++)
#pragma unroll
            for (int pr = 0; pr < 4; pr++) {
                mma16816(acc[mi][2 * pr],     ah[mi], bfr[pr][0], bfr[pr][1]);
                mma16816(acc[mi][2 * pr + 1], ah[mi], bfr[pr][2], bfr[pr][3]);
            }
#pragma unroll
        for (int mi = 0; mi < 4; mi++)
#pragma unroll
            for (int pr = 0; pr < 4; pr++) {
                mma16816(acc[mi][2 * pr],     al[mi], bfr[pr][0], bfr[pr][1]);
                mma16816(acc[mi][2 * pr + 1], al[mi], bfr[pr][2], bfr[pr][3]);
            }
#pragma unroll
        for (int pr = 0; pr < 4; pr++)
            ldsm_x4(bfr[pr], psl + (uint32_t)((b_row + pr * 16) * FLDK + k0 + b_col) * 2);
#pragma unroll
        for (int mi = 0; mi < 4; mi++)
#pragma unroll
            for (int pr = 0; pr < 4; pr++) {
                mma16816(acc[mi][2 * pr],     ah[mi], bfr[pr][0], bfr[pr][1]);
                mma16816(acc[mi][2 * pr + 1], ah[mi], bfr[pr][2], bfr[pr][3]);
            }
    }

    float tmax[4][2];
#pragma unroll
    for (int mi = 0; mi < 4; mi++) {
        float m0 = -1e30f, m1 = -1e30f;
#pragma unroll
        for (int ni = 0; ni < 8; ni++) {
            m0 = fmaxf(m0, fmaxf(acc[mi][ni][0], acc[mi][ni][1]));
            m1 = fmaxf(m1, fmaxf(acc[mi][ni][2], acc[mi][ni][3]));
        }
#pragma unroll
        for (int off = 1; off <= 2; off <<= 1) {
            m0 = fmaxf(m0, __shfl_xor_sync(0xffffffffu, m0, off));
            m1 = fmaxf(m1, __shfl_xor_sync(0xffffffffu, m1, off));
        }
        tmax[mi][0] = m0; tmax[mi][1] = m1;
    }
    if ((lane & 3) == 0) {
        const int slab = wid & 3;
#pragma unroll
        for (int mi = 0; mi < 4; mi++) {
            int r = wm + mi * 16 + (lane >> 2);
            rmaxp[slab * 128 + r]     = tmax[mi][0];
            rmaxp[slab * 128 + r + 8] = tmax[mi][1];
        }
    }
    if (OMODE == 2 && tid < 256) colsum[tid] = 0.f;
    __syncthreads();

    float base[4][2];
#pragma unroll
    for (int mi = 0; mi < 4; mi++) {
        const int r0 = wm + mi * 16 + (lane >> 2);
        const int r1 = r0 + 8;
        float rm0 = fmaxf(fmaxf(rmaxp[r0], rmaxp[128 + r0]),
                          fmaxf(rmaxp[256 + r0], rmaxp[384 + r0]));
        float rm1 = fmaxf(fmaxf(rmaxp[r1], rmaxp[128 + r1]),
                          fmaxf(rmaxp[256 + r1], rmaxp[384 + r1]));
        base[mi][0] = -diag[r0] - rm0;
        base[mi][1] = -diag[r1] - rm1;
    }

    if (OMODE == 1) {
#pragma unroll
        for (int mi = 0; mi < 4; mi++) {
            const int r0 = wm + mi * 16 + (lane >> 2);
            const size_t o0 = ((size_t)bh * Lc + l0 + r0) * Mc;
            const size_t o1 = ((size_t)bh * Lc + l0 + r0 + 8) * Mc;
            const int c0 = wn + ((lane & 3) << 1);
#pragma unroll
            for (int ni = 0; ni < 8; ni++) {
                int c = c0 + ni * 8;
                float f0 = __expf(acc[mi][ni][0] + base[mi][0]) * 0.0625f;
                float f1 = __expf(acc[mi][ni][1] + base[mi][0]) * 0.0625f;
                float f2 = __expf(acc[mi][ni][2] + base[mi][1]) * 0.0625f;
                float f3 = __expf(acc[mi][ni][3] + base[mi][1]) * 0.0625f;
                bf16 h0,l0b,h1,l1b,h2,l2b,h3,l3b;
                split2(f0, h0, l0b); split2(f1, h1, l1b);
                split2(f2, h2, l2b); split2(f3, h3, l3b);
                *(__nv_bfloat162*)&Fhi[o0 + c] = __halves2bfloat162(h0, h1);
                *(__nv_bfloat162*)&Fhi[o1 + c] = __halves2bfloat162(h2, h3);
                *(__nv_bfloat162*)&Flo[o0 + c] = __halves2bfloat162(l0b, l1b);
                *(__nv_bfloat162*)&Flo[o1 + c] = __halves2bfloat162(l2b, l3b);
            }
        }
    } else {
        const int lr = lane >> 2;
#pragma unroll
        for (int ni = 0; ni < 8; ni++) {
            const int c = wn + ((lane & 3) << 1) + ni * 8;
            float s0 = 0.f, s1 = 0.f;
#pragma unroll
            for (int mi = 0; mi < 4; mi++) {
                const int r0 = wm + mi * 16 + lr;
                float f0 = __expf(acc[mi][ni][0] + base[mi][0]) * 0.0625f;
                float f1 = __expf(acc[mi][ni][1] + base[mi][0]) * 0.0625f;
                float f2 = __expf(acc[mi][ni][2] + base[mi][1]) * 0.0625f;
                float f3 = __expf(acc[mi][ni][3] + base[mi][1]) * 0.0625f;
                s0 += f0 + f2; s1 += f1 + f3;
                const size_t t0 = ((size_t)bh * Mc + c) * Lc + l0;
                const size_t t1 = t0 + Lc;
                bf16 hh, ll;
                split2(f0, hh, ll); Fhi[t0 + r0] = hh;     Flo[t0 + r0] = ll;
                split2(f2, hh, ll); Fhi[t0 + r0 + 8] = hh; Flo[t0 + r0 + 8] = ll;
                split2(f1, hh, ll); Fhi[t1 + r0] = hh;     Flo[t1 + r0] = ll;
                split2(f3, hh, ll); Fhi[t1 + r0 + 8] = hh; Flo[t1 + r0 + 8] = ll;
            }
            atomicAdd(&colsum[c], s0);
            atomicAdd(&colsum[c + 1], s1);
        }
        __syncthreads();
        if (tid < 256) atomicAdd(&ksum[bh * Mc + tid], colsum[tid]);
    }
}

// ============================================================
// kv via mma bf16x3 — fused-pass (R11, unchanged)
// ============================================================
#define KVNITF 16
#define KV_AMS (64 * LDT * 2)
#define KV_BMS (256 * LDT * 2)
#define KV_STAGEF (2 * KV_AMS + 2 * KV_BMS)
#define KV_SMEMF (2 * KV_STAGEF)

__global__ __launch_bounds__(256, 2) void kv_mma_kernel(
    const bf16* __restrict__ vthi, const bf16* __restrict__ vtlo,
    const bf16* __restrict__ kfthi, const bf16* __restrict__ kftlo,
    float* __restrict__ kvtf)
{
    extern __shared__ char ksm[];
    const int bh = blockIdx.y;
    const int l0 = blockIdx.x * 512;
    const int tid = threadIdx.x;
    const int lane = tid & 31, wid = tid >> 5;
    const int wn = wid * 32;

    uint32_t ah_b[2], al_b[2], bh_b[2], bl_b[2];
#pragma unroll
    for (int s = 0; s < 2; s++) {
        uint32_t base = smem_u32(ksm + s * KV_STAGEF);
        ah_b[s] = base;
        al_b[s] = base + KV_AMS;
        bh_b[s] = base + 2 * KV_AMS;
        bl_b[s] = base + 2 * KV_AMS + KV_BMS;
    }

    const int a_row = (lane & 15);
    const int a_col = (lane >> 4) << 3;
    const int b_row = wn + (lane & 7) + ((lane >> 4) << 3);
    const int b_col = ((lane >> 3) & 1) << 3;

    const size_t abase = (size_t)bh * DHc * Lc + l0;
    const size_t bbase = (size_t)bh * Mc * Lc + l0;

    const int ga_row = tid >> 2, ga_c8 = (tid & 3) << 3;

    auto stage = [&](int kt) {
        const int s  = kt & 1;
        const int kk = kt << 5;
        uint32_t asoff = (uint32_t)(ga_row * LDT + ga_c8) * 2;
        const size_t ga = abase + (size_t)ga_row * Lc + kk + ga_c8;
        cp_async16(ah_b[s] + asoff, vthi + ga);
        cp_async16(al_b[s] + asoff, vtlo + ga);
#pragma unroll
        for (int i = 0; i < 4; i++) {
            int row = ga_row + i * 64;
            uint32_t bsoff = (uint32_t)(row * LDT + ga_c8) * 2;
            const size_t gb = bbase + (size_t)row * Lc + kk + ga_c8;
            cp_async16(bh_b[s] + bsoff, kfthi + gb);
            cp_async16(bl_b[s] + bsoff, kftlo + gb);
        }
        CP_COMMIT();
    };

    float acc[4][4][4];
#pragma unroll
    for (int mi = 0; mi < 4; mi++)
#pragma unroll
        for (int ni = 0; ni < 4; ni++)
#pragma unroll
            for (int e = 0; e < 4; e++) acc[mi][ni][e] = 0.f;

    stage(0); stage(1);

    for (int kt = 0; kt < KVNITF; kt++) {
        const int s = kt & 1;
        if (kt + 1 < KVNITF) CP_WAIT(1); else CP_WAIT(0);
        __syncthreads();

#pragma unroll
        for (int k0 = 0; k0 < 32; k0 += 16) {
            uint32_t bh_[2][4], bl_[2][4];
#pragma unroll
            for (int pr = 0; pr < 2; pr++) {
                uint32_t boff = (uint32_t)((b_row + pr * 16) * LDT + k0 + b_col) * 2;
                ldsm_x4(bh_[pr], bh_b[s] + boff);
                ldsm_x4(bl_[pr], bl_b[s] + boff);
            }
            uint32_t a[4][4];
#pragma unroll
            for (int mi = 0; mi < 4; mi++)
                ldsm_x4(a[mi], ah_b[s] +
                        (uint32_t)((a_row + mi * 16) * LDT + k0 + a_col) * 2);
#pragma unroll
            for (int mi = 0; mi < 4; mi++) {
                mma16816(acc[mi][0], a[mi], bh_[0][0], bh_[0][1]);
                mma16816(acc[mi][1], a[mi], bh_[0][2], bh_[0][3]);
                mma16816(acc[mi][2], a[mi], bh_[1][0], bh_[1][1]);
                mma16816(acc[mi][3], a[mi], bh_[1][2], bh_[1][3]);
            }
#pragma unroll
            for (int mi = 0; mi < 4; mi++) {
                mma16816(acc[mi][0], a[mi], bl_[0][0], bl_[0][1]);
                mma16816(acc[mi][1], a[mi], bl_[0][2], bl_[0][3]);
                mma16816(acc[mi][2], a[mi], bl_[1][0], bl_[1][1]);
                mma16816(acc[mi][3], a[mi], bl_[1][2], bl_[1][3]);
            }
#pragma unroll
            for (int mi = 0; mi < 4; mi++)
                ldsm_x4(a[mi], al_b[s] +
                        (uint32_t)((a_row + mi * 16) * LDT + k0 + a_col) * 2);
#pragma unroll
            for (int mi = 0; mi < 4; mi++) {
                mma16816(acc[mi][0], a[mi], bh_[0][0], bh_[0][1]);
                mma16816(acc[mi][1], a[mi], bh_[0][2], bh_[0][3]);
                mma16816(acc[mi][2], a[mi], bh_[1][0], bh_[1][1]);
                mma16816(acc[mi][3], a[mi], bh_[1][2], bh_[1][3]);
            }
        }
        __syncthreads();
        if (kt + 2 < KVNITF) stage(kt + 2);
    }

    const int lr = lane >> 2;
    const int c0 = wn + ((lane & 3) << 1);
    float* dst = kvtf + (size_t)bh * DHc * Mc;
#pragma unroll
    for (int mi = 0; mi < 4; mi++) {
        const int d0 = mi * 16 + lr;
        const int d1 = d0 + 8;
#pragma unroll
        for (int ni = 0; ni < 4; ni++) {
            int c = c0 + ni * 8;
            atomicAdd(&dst[d0 * Mc + c],     acc[mi][ni][0]);
            atomicAdd(&dst[d0 * Mc + c + 1], acc[mi][ni][1]);
            atomicAdd(&dst[d1 * Mc + c],     acc[mi][ni][2]);
            atomicAdd(&dst[d1 * Mc + c + 1], acc[mi][ni][3]);
        }
    }
}

// ============================================================
// kvtf fp32 -> kvthi/kvtlo
// ============================================================
__global__ __launch_bounds__(256) void kvsplit_kernel(
    const float* __restrict__ kvtf, bf16* __restrict__ Thi, bf16* __restrict__ Tlo)
{
    int i = blockIdx.x * 256 + threadIdx.x;
    float v = kvtf[i];
    bf16 h, l; split2(v, h, l);
    Thi[i] = h; Tlo[i] = l;
}

// ============================================================
// z[bh,l] = 1 / (dot(qf_hi+qf_lo, ksum) + 1e-6)
// ============================================================
__global__ __launch_bounds__(256) void z_kernel(
    const bf16* __restrict__ qfhi, const bf16* __restrict__ qflo,
    const float* __restrict__ ksum, float* __restrict__ z)
{
    __shared__ float ks[256];
    const int bh = blockIdx.y;
    ks[threadIdx.x] = ksum[bh * Mc + threadIdx.x];
    __syncthreads();
    const int w = threadIdx.x >> 5, lane = threadIdx.x & 31;
    const int l = blockIdx.x * 8 + w;
    const size_t base = ((size_t)bh * Lc + l) * Mc;
    float s = 0.f;
#pragma unroll
    for (int q8 = 0; q8 < 8; q8++) {
        int c = lane + q8 * 32;
        s += (__bfloat162float(qfhi[base + c]) + __bfloat162float(qflo[base + c])) * ks[c];
    }
#pragma unroll
    for (int off = 16; off; off >>= 1) s += __shfl_xor_sync(0xffffffffu, s, off);
    if (lane == 0) z[bh * Lc + l] = 1.0f / (s + 1e-6f);
}

// ============================================================
// attn via mma bf16x3 — fused-pass (R11, unchanged)
// ============================================================
#define ANITF 8
#define ATT_AMS (256 * LDT * 2)
#define ATT_BMS (64 * LDT * 2)
#define ATT_STAGEF (2 * ATT_AMS + 2 * ATT_BMS)
#define ATT_SMEMF (2 * ATT_STAGEF)

__global__ __launch_bounds__(256, 2) void attn_mma_kernel(
    const bf16* __restrict__ qfhi, const bf16* __restrict__ qflo,
    const bf16* __restrict__ kvthi, const bf16* __restrict__ kvtlo,
    const float* __restrict__ z,
    bf16* __restrict__ Ohi, bf16* __restrict__ Olo)
{
    extern __shared__ char asm_[];
    const int bh = blockIdx.y;
    const int b = bh >> 4, h = bh & 15;
    const int l0 = blockIdx.x * 256;
    const int tid = threadIdx.x;
    const int lane = tid & 31, wid = tid >> 5;
    const int wm = (wid >> 1) * 64;
    const int wn = (wid & 1) * 32;

    uint32_t ah_b[2], al_b[2], bh_b[2], bl_b[2];
#pragma unroll
    for (int s = 0; s < 2; s++) {
        uint32_t base = smem_u32(asm_ + s * ATT_STAGEF);
        ah_b[s] = base;
        al_b[s] = base + ATT_AMS;
        bh_b[s] = base + 2 * ATT_AMS;
        bl_b[s] = base + 2 * ATT_AMS + ATT_BMS;
    }

    const int a_row = wm + (lane & 15);
    const int a_col = (lane >> 4) << 3;
    const int b_row = wn + (lane & 7) + ((lane >> 4) << 3);
    const int b_col = ((lane >> 3) & 1) << 3;

    const size_t qbase = ((size_t)bh * Lc + l0) * Mc;
    const size_t kbase = (size_t)bh * DHc * Mc;

    const int ga_row = tid >> 2, ga_c8 = (tid & 3) << 3;

    auto stage = [&](int kt) {
        const int s  = kt & 1;
        const int kk = kt << 5;
#pragma unroll
        for (int i = 0; i < 4; i++) {
            int row = ga_row + i * 64;
            uint32_t soff = (uint32_t)(row * LDT + ga_c8) * 2;
            const size_t ga = qbase + (size_t)row * Mc + kk + ga_c8;
            cp_async16(ah_b[s] + soff, qfhi + ga);
            cp_async16(al_b[s] + soff, qflo + ga);
        }
        uint32_t bsoff = (uint32_t)(ga_row * LDT + ga_c8) * 2;
        const size_t gb = kbase + (size_t)ga_row * Mc + kk + ga_c8;
        cp_async16(bh_b[s] + bsoff, kvthi + gb);
        cp_async16(bl_b[s] + bsoff, kvtlo + gb);
        CP_COMMIT();
    };

    float acc[4][4][4];
#pragma unroll
    for (int mi = 0; mi < 4; mi++)
#pragma unroll
        for (int ni = 0; ni < 4; ni++)
#pragma unroll
            for (int e = 0; e < 4; e++) acc[mi][ni][e] = 0.f;

    stage(0); stage(1);

    for (int kt = 0; kt < ANITF; kt++) {
        const int s = kt & 1;
        if (kt + 1 < ANITF) CP_WAIT(1); else CP_WAIT(0);
        __syncthreads();

#pragma unroll
        for (int k0 = 0; k0 < 32; k0 += 16) {
            uint32_t bh_[2][4], bl_[2][4];
#pragma unroll
            for (int pr = 0; pr < 2; pr++) {
                uint32_t boff = (uint32_t)((b_row + pr * 16) * LDT + k0 + b_col) * 2;
                ldsm_x4(bh_[pr], bh_b[s] + boff);
                ldsm_x4(bl_[pr], bl_b[s] + boff);
            }
            uint32_t a[4][4];
#pragma unroll
            for (int mi = 0; mi < 4; mi++)
                ldsm_x4(a[mi], ah_b[s] +
                        (uint32_t)((a_row + mi * 16) * LDT + k0 + a_col) * 2);
#pragma unroll
            for (int mi = 0; mi < 4; mi++) {
                mma16816(acc[mi][0], a[mi], bh_[0][0], bh_[0][1]);
                mma16816(acc[mi][1], a[mi], bh_[0][2], bh_[0][3]);
                mma16816(acc[mi][2], a[mi], bh_[1][0], bh_[1][1]);
                mma16816(acc[mi][3], a[mi], bh_[1][2], bh_[1][3]);
            }
#pragma unroll
            for (int mi = 0; mi < 4; mi++) {
                mma16816(acc[mi][0], a[mi], bl_[0][0], bl_[0][1]);
                mma16816(acc[mi][1], a[mi], bl_[0][2], bl_[0][3]);
                mma16816(acc[mi][2], a[mi], bl_[1][0], bl_[1][1]);
                mma16816(acc[mi][3], a[mi], bl_[1][2], bl_[1][3]);
            }
#pragma unroll
            for (int mi = 0; mi < 4; mi++)
                ldsm_x4(a[mi], al_b[s] +
                        (uint32_t)((a_row + mi * 16) * LDT + k0 + a_col) * 2);
#pragma unroll
            for (int mi = 0; mi < 4; mi++) {
                mma16816(acc[mi][0], a[mi], bh_[0][0], bh_[0][1]);
                mma16816(acc[mi][1], a[mi], bh_[0][2], bh_[0][3]);
                mma16816(acc[mi][2], a[mi], bh_[1][0], bh_[1][1]);
                mma16816(acc[mi][3], a[mi], bh_[1][2], bh_[1][3]);
            }
        }
        __syncthreads();
        if (kt + 2 < ANITF) stage(kt + 2);
    }

    const int lr = lane >> 2;
    const int occ0 = wn + ((lane & 3) << 1);
#pragma unroll
    for (int mi = 0; mi < 4; mi++) {
        const int r0 = wm + mi * 16 + lr;
        const int r1 = r0 + 8;
        const float z0 = z[(size_t)bh * Lc + l0 + r0];
        const float z1 = z[(size_t)bh * Lc + l0 + r1];
        const size_t i0 = (size_t)(b * Lc + l0 + r0) * Dc + h * DHc;
        const size_t i1 = (size_t)(b * Lc + l0 + r1) * Dc + h * DHc;
#pragma unroll
        for (int ni = 0; ni < 4; ni++) {
            int c = occ0 + ni * 8;
            bf16 h0,l0b,h1,l1b,h2,l2b,h3,l3b;
            split2(acc[mi][ni][0] * z0, h0, l0b);
            split2(acc[mi][ni][1] * z0, h1, l1b);
            split2(acc[mi][ni][2] * z1, h2, l2b);
            split2(acc[mi][ni][3] * z1, h3, l3b);
            *(__nv_bfloat162*)&Ohi[i0 + c] = __halves2bfloat162(h0, h1);
            *(__nv_bfloat162*)&Ohi[i1 + c] = __halves2bfloat162(h2, h3);
            *(__nv_bfloat162*)&Olo[i0 + c] = __halves2bfloat162(l0b, l1b);
            *(__nv_bfloat162*)&Olo[i1 + c] = __halves2bfloat162(l2b, l3b);
        }
    }
}

// ============================================================
// LayerNorm + duplicate rows
// ============================================================
__global__ __launch_bounds__(256) void ln_dup_kernel(
    const float* __restrict__ y, const float* __restrict__ g,
    const float* __restrict__ beta, float* __restrict__ out)
{
    __shared__ float red[18];
    const int row = blockIdx.x;
    const int b = row >> 12, l = row & 4095;
    const int tid = threadIdx.x;
    const float* yr = y + (size_t)row * Dc;

    float v[4];
    float s = 0.f, ss = 0.f;
#pragma unroll
    for (int i = 0; i < 4; i++) {
        float t = yr[tid + i * 256];
        v[i] = t; s += t; ss += t * t;
    }
#pragma unroll
    for (int off = 16; off; off >>= 1) {
        s  += __shfl_xor_sync(0xffffffffu, s, off);
        ss += __shfl_xor_sync(0xffffffffu, ss, off);
    }
    const int w = tid >> 5, lane = tid & 31;
    if (lane == 0) { red[w] = s; red[8 + w] = ss; }
    __syncthreads();
    if (tid == 0) {
        float ts = 0.f, tss = 0.f;
#pragma unroll
        for (int i = 0; i < 8; i++) { ts += red[i]; tss += red[8 + i]; }
        float mean = ts * (1.0f / 1024.0f);
        float var = tss * (1.0f / 1024.0f) - mean * mean;
        red[16] = mean;
        red[17] = rsqrtf(var + 1e-5f);
    }
    __syncthreads();
    const float mean = red[16], rstd = red[17];
    float* o0 = out + ((size_t)b * 8192 + 2 * (size_t)l) * Dc;
#pragma unroll
    for (int i = 0; i < 4; i++) {
        int c = tid + i * 256;
        float o = (v[i] - mean) * rstd * g[c] + beta[c];
        o0[c] = o;
        o0[Dc + c] = o;
    }
}

// ============================================================
// host launch
// ============================================================
extern "C" void kernel_launch(void* const* d_in, const int* in_sizes, int n_in,
                              void* d_out, int out_size)
{
    const float* x    = (const float*)d_in[0];
    const float* Wq   = (const float*)d_in[1];
    const float* Wk   = (const float*)d_in[2];
    const float* Wv   = (const float*)d_in[3];
    const float* Wo   = (const float*)d_in[4];
    const float* proj = (const float*)d_in[5];
    const float* ln_g = (const float*)d_in[6];
    const float* ln_b = (const float*)d_in[7];
    float* out = (float*)d_out;

    float *kvtf, *ksum, *z, *y;
    bf16 *qfhi, *qflo, *kfthi, *kftlo, *vthi, *vtlo, *kvthi, *kvtlo;
    bf16 *ahi, *alo, *bthi, *btlo, *qhi, *qlo, *khi, *klo, *phi, *plo;
    cudaGetSymbolAddress((void**)&qfhi,  g_qfhi);
    cudaGetSymbolAddress((void**)&qflo,  g_qflo);
    cudaGetSymbolAddress((void**)&kfthi, g_kfthi);
    cudaGetSymbolAddress((void**)&kftlo, g_kftlo);
    cudaGetSymbolAddress((void**)&vthi,  g_vthi);
    cudaGetSymbolAddress((void**)&vtlo,  g_vtlo);
    cudaGetSymbolAddress((void**)&kvtf,  g_kvtf);
    cudaGetSymbolAddress((void**)&kvthi, g_kvthi);
    cudaGetSymbolAddress((void**)&kvtlo, g_kvtlo);
    cudaGetSymbolAddress((void**)&ksum,  g_ksum);
    cudaGetSymbolAddress((void**)&z,     g_z);
    cudaGetSymbolAddress((void**)&y,     g_y);
    cudaGetSymbolAddress((void**)&ahi,   g_ahi);
    cudaGetSymbolAddress((void**)&alo,   g_alo);
    cudaGetSymbolAddress((void**)&bthi,  g_bthi);
    cudaGetSymbolAddress((void**)&btlo,  g_btlo);
    cudaGetSymbolAddress((void**)&qhi,   g_qhi);
    cudaGetSymbolAddress((void**)&qlo,   g_qlo);
    cudaGetSymbolAddress((void**)&khi,   g_khi);
    cudaGetSymbolAddress((void**)&klo,   g_klo);
    cudaGetSymbolAddress((void**)&phi,   g_phi);
    cudaGetSymbolAddress((void**)&plo,   g_plo);

    const float qscale = 0.35355339059327379f;  // 64^-0.25

    cudaFuncSetAttribute(mma_gemm_kernel<0>,
                         cudaFuncAttributeMaxDynamicSharedMemorySize, GEMM_SMEMF);
    cudaFuncSetAttribute(mma_gemm_kernel<1>,
                         cudaFuncAttributeMaxDynamicSharedMemorySize, GEMM_SMEMF);
    cudaFuncSetAttribute(feature_mma_kernel<1>,
                         cudaFuncAttributeMaxDynamicSharedMemorySize, FEAT2_SMEM);
    cudaFuncSetAttribute(feature_mma_kernel<2>,
                         cudaFuncAttributeMaxDynamicSharedMemorySize, FEAT2_SMEM);
    cudaFuncSetAttribute(kv_mma_kernel,
                         cudaFuncAttributeMaxDynamicSharedMemorySize, KV_SMEMF);
    cudaFuncSetAttribute(attn_mma_kernel,
                         cudaFuncAttributeMaxDynamicSharedMemorySize, ATT_SMEMF);

    const int n4 = ROWS * Dc / 4;

    // splits (weights: single fused launch)
    split_kernel<<<n4 / 256, 256>>>(x, ahi, alo, n4);
    split_kernel<<<(Hc * Mc * DHc / 4) / 256, 256>>>(proj, phi, plo, Hc * Mc * DHc / 4);
    tsplit4_kernel<<<dim3(32, 32, 4), dim3(32, 8)>>>(Wq, Wk, Wv, Wo, bthi, btlo);

    // zero accumulators (consumed by feature<2> and kv_mma)
    cudaMemsetAsync(ksum, 0, (size_t)BHc * Mc * sizeof(float), 0);
    cudaMemsetAsync(kvtf, 0, (size_t)BHc * DHc * Mc * sizeof(float), 0);

    // fused QKV GEMM (V written transposed hi/lo directly)
    mma_gemm_kernel<0><<<dim3(24, 64), 256, GEMM_SMEMF>>>(
        ahi, alo, bthi, btlo, nullptr, qhi, qlo, khi, klo, vthi, vtlo, qscale);

    // features: Q -> qf hi/lo [l][m]; K -> kf_t hi/lo [m][l] + ksum
    feature_mma_kernel<1><<<dim3(Lc / 128, BHc), 256, FEAT2_SMEM>>>(
        qhi, qlo, phi, plo, qfhi, qflo, nullptr);
    feature_mma_kernel<2><<<dim3(Lc / 128, BHc), 256, FEAT2_SMEM>>>(
        khi, klo, phi, plo, kfthi, kftlo, ksum);

    // kv via tensor cores (vt precomputed by GEMM epilogue)
    kv_mma_kernel<<<dim3(8, BHc), 256, KV_SMEMF>>>(vthi, vtlo, kfthi, kftlo, kvtf);
    kvsplit_kernel<<<(BHc * DHc * Mc) / 256, 256>>>(kvtf, kvthi, kvtlo);

    z_kernel<<<dim3(Lc / 8, BHc), 256>>>(qfhi, qflo, ksum, z);

    // attn -> hi/lo directly into O-GEMM A buffers
    attn_mma_kernel<<<dim3(Lc / 256, BHc), 256, ATT_SMEMF>>>(
        qfhi, qflo, kvthi, kvtlo, z, ahi, alo);

    // O projection + exact GELU (weights at offset 3)
    mma_gemm_kernel<1><<<dim3(8, 64), 256, GEMM_SMEMF>>>(
        ahi, alo, bthi + (size_t)3 * Dc * Dc, btlo + (size_t)3 * Dc * Dc,
        y, nullptr, nullptr, nullptr, nullptr, nullptr, nullptr, 1.0f);

    ln_dup_kernel<<<ROWS, 256>>>(y, ln_g, ln_b, out);
}

// round 13
// speedup vs baseline: 1.0137x; 1.0137x over previous
#include <cuda_runtime.h>
#include <cuda_bf16.h>
#include <math.h>
#include <stdint.h>

// Shapes (fixed)
#define Bc   2
#define Lc   4096
#define Dc   1024
#define Hc   16
#define DHc  64
#define Mc   256
#define BHc  32
#define ROWS 8192   // B*L

typedef __nv_bfloat16 bf16;

// -------- scratch (device globals; no allocations allowed) --------
__device__ float g_v    [(size_t)ROWS * Dc];
__device__ bf16  g_qfhi [(size_t)BHc * Lc * Mc];
__device__ bf16  g_qflo [(size_t)BHc * Lc * Mc];
__device__ bf16  g_kfthi[(size_t)BHc * Mc * Lc];
__device__ bf16  g_kftlo[(size_t)BHc * Mc * Lc];
__device__ bf16  g_vthi [(size_t)BHc * DHc * Lc];
__device__ bf16  g_vtlo [(size_t)BHc * DHc * Lc];
__device__ float g_kvtf [(size_t)BHc * DHc * Mc];
__device__ bf16  g_kvthi[(size_t)BHc * DHc * Mc];
__device__ bf16  g_kvtlo[(size_t)BHc * DHc * Mc];
__device__ float g_ksum [(size_t)BHc * Mc];
__device__ float g_z    [(size_t)BHc * Lc];
__device__ float g_y    [(size_t)ROWS * Dc];
__device__ bf16  g_ahi  [(size_t)ROWS * Dc];
__device__ bf16  g_alo  [(size_t)ROWS * Dc];
__device__ bf16  g_bthi [(size_t)4 * Dc * Dc];
__device__ bf16  g_btlo [(size_t)4 * Dc * Dc];
__device__ bf16  g_qhi  [(size_t)ROWS * Dc];
__device__ bf16  g_qlo  [(size_t)ROWS * Dc];
__device__ bf16  g_khi  [(size_t)ROWS * Dc];
__device__ bf16  g_klo  [(size_t)ROWS * Dc];
__device__ bf16  g_phi  [(size_t)Hc * Mc * DHc];
__device__ bf16  g_plo  [(size_t)Hc * Mc * DHc];

// ================= baseline-PTX tensor-core helpers (sm_80+) ==========
__device__ __forceinline__ uint32_t smem_u32(const void* p) {
    uint32_t a;
    asm("{ .reg .u64 t; cvta.to.shared.u64 t, %1; cvt.u32.u64 %0, t; }"
        : "=r"(a) : "l"(p));
    return a;
}
__device__ __forceinline__ void cp_async16(uint32_t saddr, const void* g) {
    asm volatile("cp.async.cg.shared.global [%0], [%1], 16;"
                 :: "r"(saddr), "l"(g) : "memory");
}
#define CP_COMMIT() asm volatile("cp.async.commit_group;" ::: "memory")
#define CP_WAIT(n)  asm volatile("cp.async.wait_group %0;" :: "n"(n) : "memory")

__device__ __forceinline__ void ldsm_x4(uint32_t r[4], uint32_t addr) {
    asm volatile("ldmatrix.sync.aligned.m8n8.x4.shared.b16 {%0,%1,%2,%3}, [%4];"
                 : "=r"(r[0]), "=r"(r[1]), "=r"(r[2]), "=r"(r[3]) : "r"(addr));
}
__device__ __forceinline__ void mma16816(float c[4], const uint32_t a[4],
                                         uint32_t b0, uint32_t b1) {
    asm volatile(
        "mma.sync.aligned.m16n8k16.row.col.f32.bf16.bf16.f32 "
        "{%0,%1,%2,%3}, {%4,%5,%6,%7}, {%8,%9}, {%0,%1,%2,%3};"
        : "+f"(c[0]), "+f"(c[1]), "+f"(c[2]), "+f"(c[3])
        : "r"(a[0]), "r"(a[1]), "r"(a[2]), "r"(a[3]), "r"(b0), "r"(b1));
}
__device__ __forceinline__ void split2(float v, bf16& h, bf16& l) {
    h = __float2bfloat16_rn(v);
    l = __float2bfloat16_rn(v - __bfloat162float(h));
}

// ============================================================
// fp32 -> (hi, lo) bf16 split
// ============================================================
__global__ __launch_bounds__(256) void split_kernel(
    const float* __restrict__ in, bf16* __restrict__ hi,
    bf16* __restrict__ lo, int n4)
{
    int i = blockIdx.x * 256 + threadIdx.x;
    if (i >= n4) return;
    float4 v = ((const float4*)in)[i];
    bf16 h0, h1, h2, h3, l0, l1, l2, l3;
    split2(v.x, h0, l0); split2(v.y, h1, l1);
    split2(v.z, h2, l2); split2(v.w, h3, l3);
    ((__nv_bfloat162*)hi)[2*i]   = __halves2bfloat162(h0, h1);
    ((__nv_bfloat162*)hi)[2*i+1] = __halves2bfloat162(h2, h3);
    ((__nv_bfloat162*)lo)[2*i]   = __halves2bfloat162(l0, l1);
    ((__nv_bfloat162*)lo)[2*i+1] = __halves2bfloat162(l2, l3);
}

// ============================================================
// 4 weights [K,N] -> W^T [N,K] bf16 hi/lo, single launch (z = which W)
// ============================================================
__global__ void tsplit4_kernel(
    const float* __restrict__ W0, const float* __restrict__ W1,
    const float* __restrict__ W2, const float* __restrict__ W3,
    bf16* __restrict__ Thi, bf16* __restrict__ Tlo)
{
    __shared__ float t[32][33];
    const float* W = (blockIdx.z == 0) ? W0 : (blockIdx.z == 1) ? W1
                    : (blockIdx.z == 2) ? W2 : W3;
    bf16* th = Thi + (size_t)blockIdx.z * Dc * Dc;
    bf16* tl = Tlo + (size_t)blockIdx.z * Dc * Dc;
    int bx = blockIdx.x * 32, by = blockIdx.y * 32;
    int tx = threadIdx.x, ty = threadIdx.y;   // 32 x 8
#pragma unroll
    for (int i = 0; i < 32; i += 8)
        t[ty + i][tx] = W[(size_t)(by + ty + i) * Dc + bx + tx];
    __syncthreads();
#pragma unroll
    for (int i = 0; i < 32; i += 8) {
        float v = t[tx][ty + i];
        int orow = bx + ty + i, ocol = by + tx;
        bf16 h, l; split2(v, h, l);
        th[(size_t)orow * Dc + ocol] = h;
        tl[(size_t)orow * Dc + ocol] = l;
    }
}

// ============================================================
// v [b*L][D] fp32 -> v_t [bh][d][l] bf16 hi/lo (standalone, R11 form)
// ============================================================
__global__ __launch_bounds__(256) void vt_kernel(
    const float* __restrict__ v, bf16* __restrict__ Thi, bf16* __restrict__ Tlo)
{
    __shared__ float t[64][33];
    const int bh = blockIdx.y;
    const int b = bh >> 4, h = bh & 15;
    const int l0 = blockIdx.x * 32;
    const int tid = threadIdx.x;
#pragma unroll
    for (int i = 0; i < 8; i++) {
        int s = tid + i * 256;
        int r = s >> 6, c = s & 63;
        t[c][r & 31] = v[(size_t)(b * Lc + l0 + r) * Dc + h * DHc + c];
    }
    __syncthreads();
#pragma unroll
    for (int i = 0; i < 8; i++) {
        int s = tid + i * 256;
        int d = s >> 5, c = s & 31;
        float val = t[d][c];
        bf16 hh, ll; split2(val, hh, ll);
        size_t o = ((size_t)bh * DHc + d) * Lc + l0 + c;
        Thi[o] = hh; Tlo[o] = ll;
    }
}

// ============================================================
// bf16x3 FUSED-PASS tensor-core GEMM (R10/R11 core).
// MODE 0 (fused QKV): which=bn>>10: 0->Qhi/Qlo, 1->Khi/Klo (x qalpha),
//                     2 -> V fp32 (Cv)
// MODE 1: fp32 C with exact GELU. 2 CTAs/SM.
// ============================================================
#define LDT 40
#define GNITF 32                           // 1024 / 32 k-tiles
#define GEMM_MSTG (128 * LDT * 2)          // 10240 B per matrix
#define GEMM_STAGE (4 * GEMM_MSTG)         // 40960 B per stage
#define GEMM_SMEMF (2 * GEMM_STAGE)        // 81920 B

template<int MODE>
__global__ __launch_bounds__(256, 2) void mma_gemm_kernel(
    const bf16* __restrict__ Ahi, const bf16* __restrict__ Alo,
    const bf16* __restrict__ Bhi, const bf16* __restrict__ Blo,
    float* __restrict__ Cv,
    bf16* __restrict__ Qhi, bf16* __restrict__ Qlo,
    bf16* __restrict__ Khi, bf16* __restrict__ Klo,
    float qalpha)
{
    extern __shared__ char gsm[];
    const int tid  = threadIdx.x;
    const int lane = tid & 31, wid = tid >> 5;
    const int bm = blockIdx.y * 128;
    const int bn = blockIdx.x * 128;
    const int wm = (wid >> 2) * 64;
    const int wn = (wid & 3) * 32;

    uint32_t ah_b[2], al_b[2], bh_b[2], bl_b[2];
#pragma unroll
    for (int s = 0; s < 2; s++) {
        uint32_t base = smem_u32(gsm + s * GEMM_STAGE);
        ah_b[s] = base;
        al_b[s] = base + GEMM_MSTG;
        bh_b[s] = base + 2 * GEMM_MSTG;
        bl_b[s] = base + 3 * GEMM_MSTG;
    }

    const int a_row = wm + (lane & 15);
    const int a_col = (lane >> 4) << 3;
    const int b_row = wn + (lane & 7) + ((lane >> 4) << 3);
    const int b_col = ((lane >> 3) & 1) << 3;

    const int g_row0 = tid >> 2;
    const int g_c8   = (tid & 3) << 3;

    auto stage = [&](int kt) {
        const int s  = kt & 1;
        const int kk = kt << 5;
#pragma unroll
        for (int i = 0; i < 2; i++) {
            int row = g_row0 + i * 64;
            uint32_t soff = (uint32_t)(row * LDT + g_c8) * 2;
            const size_t ga = (size_t)(bm + row) * Dc + kk + g_c8;
            const size_t gb = (size_t)(bn + row) * Dc + kk + g_c8;
            cp_async16(ah_b[s] + soff, Ahi + ga);
            cp_async16(al_b[s] + soff, Alo + ga);
            cp_async16(bh_b[s] + soff, Bhi + gb);
            cp_async16(bl_b[s] + soff, Blo + gb);
        }
        CP_COMMIT();
    };

    float acc[4][4][4];
#pragma unroll
    for (int mi = 0; mi < 4; mi++)
#pragma unroll
        for (int ni = 0; ni < 4; ni++)
#pragma unroll
            for (int e = 0; e < 4; e++) acc[mi][ni][e] = 0.f;

    stage(0); stage(1);

    for (int kt = 0; kt < GNITF; kt++) {
        const int s = kt & 1;
        if (kt + 1 < GNITF) CP_WAIT(1); else CP_WAIT(0);
        __syncthreads();

#pragma unroll
        for (int k0 = 0; k0 < 32; k0 += 16) {
            uint32_t bh_[2][4], bl_[2][4];
#pragma unroll
            for (int pr = 0; pr < 2; pr++) {
                uint32_t boff = (uint32_t)((b_row + pr * 16) * LDT + k0 + b_col) * 2;
                ldsm_x4(bh_[pr], bh_b[s] + boff);
                ldsm_x4(bl_[pr], bl_b[s] + boff);
            }
            uint32_t a[4][4];
#pragma unroll
            for (int mi = 0; mi < 4; mi++)
                ldsm_x4(a[mi], ah_b[s] +
                        (uint32_t)((a_row + mi * 16) * LDT + k0 + a_col) * 2);
#pragma unroll
            for (int mi = 0; mi < 4; mi++) {
                mma16816(acc[mi][0], a[mi], bh_[0][0], bh_[0][1]);
                mma16816(acc[mi][1], a[mi], bh_[0][2], bh_[0][3]);
                mma16816(acc[mi][2], a[mi], bh_[1][0], bh_[1][1]);
                mma16816(acc[mi][3], a[mi], bh_[1][2], bh_[1][3]);
            }
#pragma unroll
            for (int mi = 0; mi < 4; mi++) {
                mma16816(acc[mi][0], a[mi], bl_[0][0], bl_[0][1]);
                mma16816(acc[mi][1], a[mi], bl_[0][2], bl_[0][3]);
                mma16816(acc[mi][2], a[mi], bl_[1][0], bl_[1][1]);
                mma16816(acc[mi][3], a[mi], bl_[1][2], bl_[1][3]);
            }
#pragma unroll
            for (int mi = 0; mi < 4; mi++)
                ldsm_x4(a[mi], al_b[s] +
                        (uint32_t)((a_row + mi * 16) * LDT + k0 + a_col) * 2);
#pragma unroll
            for (int mi = 0; mi < 4; mi++) {
                mma16816(acc[mi][0], a[mi], bh_[0][0], bh_[0][1]);
                mma16816(acc[mi][1], a[mi], bh_[0][2], bh_[0][3]);
                mma16816(acc[mi][2], a[mi], bh_[1][0], bh_[1][1]);
                mma16816(acc[mi][3], a[mi], bh_[1][2], bh_[1][3]);
            }
        }
        __syncthreads();
        if (kt + 2 < GNITF) stage(kt + 2);
    }

    const int orow = bm + wm + (lane >> 2);
    const int occ0 = wn + ((lane & 3) << 1);

    if (MODE == 0) {
        const int which = bn >> 10;        // 0 q, 1 k, 2 v
        const int bnl = bn & 1023;
        if (which < 2) {
            bf16* Oh = which ? Khi : Qhi;
            bf16* Ol = which ? Klo : Qlo;
#pragma unroll
            for (int mi = 0; mi < 4; mi++)
#pragma unroll
                for (int ni = 0; ni < 4; ni++) {
                    const size_t i0 = (size_t)(orow + mi * 16) * Dc + bnl + occ0 + ni * 8;
                    const size_t i1 = (size_t)(orow + mi * 16 + 8) * Dc + bnl + occ0 + ni * 8;
                    bf16 h0,l0,h1,l1,h2,l2,h3,l3;
                    split2(acc[mi][ni][0] * qalpha, h0, l0);
                    split2(acc[mi][ni][1] * qalpha, h1, l1);
                    split2(acc[mi][ni][2] * qalpha, h2, l2);
                    split2(acc[mi][ni][3] * qalpha, h3, l3);
                    *(__nv_bfloat162*)&Oh[i0] = __halves2bfloat162(h0, h1);
                    *(__nv_bfloat162*)&Oh[i1] = __halves2bfloat162(h2, h3);
                    *(__nv_bfloat162*)&Ol[i0] = __halves2bfloat162(l0, l1);
                    *(__nv_bfloat162*)&Ol[i1] = __halves2bfloat162(l2, l3);
                }
        } else {
#pragma unroll
            for (int mi = 0; mi < 4; mi++)
#pragma unroll
                for (int ni = 0; ni < 4; ni++) {
                    const size_t i0 = (size_t)(orow + mi * 16) * Dc + bnl + occ0 + ni * 8;
                    const size_t i1 = (size_t)(orow + mi * 16 + 8) * Dc + bnl + occ0 + ni * 8;
                    *(float2*)&Cv[i0] = make_float2(acc[mi][ni][0], acc[mi][ni][1]);
                    *(float2*)&Cv[i1] = make_float2(acc[mi][ni][2], acc[mi][ni][3]);
                }
        }
    } else {
#pragma unroll
        for (int mi = 0; mi < 4; mi++)
#pragma unroll
            for (int ni = 0; ni < 4; ni++) {
                float v0 = acc[mi][ni][0], v1 = acc[mi][ni][1];
                float v2 = acc[mi][ni][2], v3 = acc[mi][ni][3];
                v0 = 0.5f * v0 * (1.f + erff(v0 * 0.70710678118654752f));
                v1 = 0.5f * v1 * (1.f + erff(v1 * 0.70710678118654752f));
                v2 = 0.5f * v2 * (1.f + erff(v2 * 0.70710678118654752f));
                v3 = 0.5f * v3 * (1.f + erff(v3 * 0.70710678118654752f));
                const size_t i0 = (size_t)(orow + mi * 16) * Dc + bn + occ0 + ni * 8;
                const size_t i1 = (size_t)(orow + mi * 16 + 8) * Dc + bn + occ0 + ni * 8;
                *(float2*)&Cv[i0] = make_float2(v0, v1);
                *(float2*)&Cv[i1] = make_float2(v2, v3);
            }
    }
}

// ============================================================
// FAVOR+ feature via mma.sync bf16x3 — fused passes (R11, unchanged)
// ============================================================
#define FLDK 72
#define FEAT2_SMEM ((128 + 128 + 256 + 256) * FLDK * 2 + 128 * 4 + 4 * 128 * 4 + 256 * 4)

template<int OMODE>
__global__ __launch_bounds__(256) void feature_mma_kernel(
    const bf16* __restrict__ Uhi, const bf16* __restrict__ Ulo,
    const bf16* __restrict__ Phi, const bf16* __restrict__ Plo,
    bf16* __restrict__ Fhi, bf16* __restrict__ Flo,
    float* __restrict__ ksum)
{
    extern __shared__ char fsm[];
    bf16* us_h = (bf16*)fsm;
    bf16* us_l = us_h + 128 * FLDK;
    bf16* ps_h = us_l + 128 * FLDK;
    bf16* ps_l = ps_h + 256 * FLDK;
    float* diag   = (float*)(ps_l + 256 * FLDK);
    float* rmaxp  = diag + 128;
    float* colsum = rmaxp + 4 * 128;

    const int bh = blockIdx.y;
    const int b = bh >> 4, h = bh & 15;
    const int l0 = blockIdx.x * 128;
    const int tid = threadIdx.x;
    const int lane = tid & 31, wid = tid >> 5;

#pragma unroll
    for (int i = 0; i < 4; i++) {
        int s = tid + i * 256;
        int r = s >> 3, c8 = (s & 7) << 3;
        size_t gi = (size_t)(b * Lc + l0 + r) * Dc + h * DHc + c8;
        *(uint4*)&us_h[r * FLDK + c8] = *(const uint4*)&Uhi[gi];
        *(uint4*)&us_l[r * FLDK + c8] = *(const uint4*)&Ulo[gi];
    }
#pragma unroll
    for (int i = 0; i < 8; i++) {
        int s = tid + i * 256;
        int r = s >> 3, c8 = (s & 7) << 3;
        size_t gi = (size_t)(h * Mc + r) * DHc + c8;
        *(uint4*)&ps_h[r * FLDK + c8] = *(const uint4*)&Phi[gi];
        *(uint4*)&ps_l[r * FLDK + c8] = *(const uint4*)&Plo[gi];
    }
    __syncthreads();

    if (tid < 128) {
        float s = 0.f;
#pragma unroll
        for (int d2 = 0; d2 < 32; d2++) {
            __nv_bfloat162 hh = *(__nv_bfloat162*)&us_h[tid * FLDK + d2 * 2];
            __nv_bfloat162 ll = *(__nv_bfloat162*)&us_l[tid * FLDK + d2 * 2];
            float u0 = __bfloat162float(hh.x) + __bfloat162float(ll.x);
            float u1 = __bfloat162float(hh.y) + __bfloat162float(ll.y);
            s += u0 * u0 + u1 * u1;
        }
        diag[tid] = 0.5f * s;
    }

    const int wm = (wid >> 2) * 64;
    const int wn = (wid & 3) * 64;
    const int a_row = wm + (lane & 15);
    const int a_col = (lane >> 4) << 3;
    const int b_row = wn + (lane & 7) + ((lane >> 4) << 3);
    const int b_col = ((lane >> 3) & 1) << 3;

    float acc[4][8][4];
#pragma unroll
    for (int mi = 0; mi < 4; mi++)
#pragma unroll
        for (int ni = 0; ni < 8; ni++)
#pragma unroll
            for (int e = 0; e < 4; e++) acc[mi][ni][e] = 0.f;

    const uint32_t ush = smem_u32(us_h), usl = smem_u32(us_l);
    const uint32_t psh = smem_u32(ps_h), psl = smem_u32(ps_l);
    __syncthreads();

#pragma unroll
    for (int k0 = 0; k0 < 64; k0 += 16) {
        uint32_t ah[4][4], al[4][4], bfr[4][4];
#pragma unroll
        for (int mi = 0; mi < 4; mi++) {
            uint32_t aoff = (uint32_t)((a_row + mi * 16) * FLDK + k0 + a_col) * 2;
            ldsm_x4(ah[mi], ush + aoff);
            ldsm_x4(al[mi], usl + aoff);
        }
#pragma unroll
        for (int pr = 0; pr < 4; pr++)
            ldsm_x4(bfr[pr], psh + (uint32_t)((b_row + pr * 16) * FLDK + k0 + b_col) * 2);
#pragma unroll
        for (int mi = 0; mi < 4; mi++)
#pragma unroll
            for (int pr = 0; pr < 4; pr++) {
                mma16816(acc[mi][2 * pr],     ah[mi], bfr[pr][0], bfr[pr][1]);
                mma16816(acc[mi][2 * pr + 1], ah[mi], bfr[pr][2], bfr[pr][3]);
            }
#pragma unroll
        for (int mi = 0; mi < 4; mi++)
#pragma unroll
            for (int pr = 0; pr < 4; pr++) {
                mma16816(acc[mi][2 * pr],     al[mi], bfr[pr][0], bfr[pr][1]);
                mma16816(acc[mi][2 * pr + 1], al[mi], bfr[pr][2], bfr[pr][3]);
            }
#pragma unroll
        for (int pr = 0; pr < 4; pr++)
            ldsm_x4(bfr[pr], psl + (uint32_t)((b_row + pr * 16) * FLDK + k0 + b_col) * 2);
#pragma unroll
        for (int mi = 0; mi < 4; mi++)
#pragma unroll
            for (int pr = 0; pr < 4; pr++) {
                mma16816(acc[mi][2 * pr],     ah[mi], bfr[pr][0], bfr[pr][1]);
                mma16816(acc[mi][2 * pr + 1], ah[mi], bfr[pr][2], bfr[pr][3]);
            }
    }

    float tmax[4][2];
#pragma unroll
    for (int mi = 0; mi < 4; mi++) {
        float m0 = -1e30f, m1 = -1e30f;
#pragma unroll
        for (int ni = 0; ni < 8; ni++) {
            m0 = fmaxf(m0, fmaxf(acc[mi][ni][0], acc[mi][ni][1]));
            m1 = fmaxf(m1, fmaxf(acc[mi][ni][2], acc[mi][ni][3]));
        }
#pragma unroll
        for (int off = 1; off <= 2; off <<= 1) {
            m0 = fmaxf(m0, __shfl_xor_sync(0xffffffffu, m0, off));
            m1 = fmaxf(m1, __shfl_xor_sync(0xffffffffu, m1, off));
        }
        tmax[mi][0] = m0; tmax[mi][1] = m1;
    }
    if ((lane & 3) == 0) {
        const int slab = wid & 3;
#pragma unroll
        for (int mi = 0; mi < 4; mi++) {
            int r = wm + mi * 16 + (lane >> 2);
            rmaxp[slab * 128 + r]     = tmax[mi][0];
            rmaxp[slab * 128 + r + 8] = tmax[mi][1];
        }
    }
    if (OMODE == 2 && tid < 256) colsum[tid] = 0.f;
    __syncthreads();

    float base[4][2];
#pragma unroll
    for (int mi = 0; mi < 4; mi++) {
        const int r0 = wm + mi * 16 + (lane >> 2);
        const int r1 = r0 + 8;
        float rm0 = fmaxf(fmaxf(rmaxp[r0], rmaxp[128 + r0]),
                          fmaxf(rmaxp[256 + r0], rmaxp[384 + r0]));
        float rm1 = fmaxf(fmaxf(rmaxp[r1], rmaxp[128 + r1]),
                          fmaxf(rmaxp[256 + r1], rmaxp[384 + r1]));
        base[mi][0] = -diag[r0] - rm0;
        base[mi][1] = -diag[r1] - rm1;
    }

    if (OMODE == 1) {
#pragma unroll
        for (int mi = 0; mi < 4; mi++) {
            const int r0 = wm + mi * 16 + (lane >> 2);
            const size_t o0 = ((size_t)bh * Lc + l0 + r0) * Mc;
            const size_t o1 = ((size_t)bh * Lc + l0 + r0 + 8) * Mc;
            const int c0 = wn + ((lane & 3) << 1);
#pragma unroll
            for (int ni = 0; ni < 8; ni++) {
                int c = c0 + ni * 8;
                float f0 = __expf(acc[mi][ni][0] + base[mi][0]) * 0.0625f;
                float f1 = __expf(acc[mi][ni][1] + base[mi][0]) * 0.0625f;
                float f2 = __expf(acc[mi][ni][2] + base[mi][1]) * 0.0625f;
                float f3 = __expf(acc[mi][ni][3] + base[mi][1]) * 0.0625f;
                bf16 h0,l0b,h1,l1b,h2,l2b,h3,l3b;
                split2(f0, h0, l0b); split2(f1, h1, l1b);
                split2(f2, h2, l2b); split2(f3, h3, l3b);
                *(__nv_bfloat162*)&Fhi[o0 + c] = __halves2bfloat162(h0, h1);
                *(__nv_bfloat162*)&Fhi[o1 + c] = __halves2bfloat162(h2, h3);
                *(__nv_bfloat162*)&Flo[o0 + c] = __halves2bfloat162(l0b, l1b);
                *(__nv_bfloat162*)&Flo[o1 + c] = __halves2bfloat162(l2b, l3b);
            }
        }
    } else {
        const int lr = lane >> 2;
#pragma unroll
        for (int ni = 0; ni < 8; ni++) {
            const int c = wn + ((lane & 3) << 1) + ni * 8;
            float s0 = 0.f, s1 = 0.f;
#pragma unroll
            for (int mi = 0; mi < 4; mi++) {
                const int r0 = wm + mi * 16 + lr;
                float f0 = __expf(acc[mi][ni][0] + base[mi][0]) * 0.0625f;
                float f1 = __expf(acc[mi][ni][1] + base[mi][0]) * 0.0625f;
                float f2 = __expf(acc[mi][ni][2] + base[mi][1]) * 0.0625f;
                float f3 = __expf(acc[mi][ni][3] + base[mi][1]) * 0.0625f;
                s0 += f0 + f2; s1 += f1 + f3;
                const size_t t0 = ((size_t)bh * Mc + c) * Lc + l0;
                const size_t t1 = t0 + Lc;
                bf16 hh, ll;
                split2(f0, hh, ll); Fhi[t0 + r0] = hh;     Flo[t0 + r0] = ll;
                split2(f2, hh, ll); Fhi[t0 + r0 + 8] = hh; Flo[t0 + r0 + 8] = ll;
                split2(f1, hh, ll); Fhi[t1 + r0] = hh;     Flo[t1 + r0] = ll;
                split2(f3, hh, ll); Fhi[t1 + r0 + 8] = hh; Flo[t1 + r0 + 8] = ll;
            }
            atomicAdd(&colsum[c], s0);
            atomicAdd(&colsum[c + 1], s1);
        }
        __syncthreads();
        if (tid < 256) atomicAdd(&ksum[bh * Mc + tid], colsum[tid]);
    }
}

// ============================================================
// kv via mma bf16x3 — fused-pass (R11, unchanged)
// ============================================================
#define KVNITF 16
#define KV_AMS (64 * LDT * 2)
#define KV_BMS (256 * LDT * 2)
#define KV_STAGEF (2 * KV_AMS + 2 * KV_BMS)
#define KV_SMEMF (2 * KV_STAGEF)

__global__ __launch_bounds__(256, 2) void kv_mma_kernel(
    const bf16* __restrict__ vthi, const bf16* __restrict__ vtlo,
    const bf16* __restrict__ kfthi, const bf16* __restrict__ kftlo,
    float* __restrict__ kvtf)
{
    extern __shared__ char ksm[];
    const int bh = blockIdx.y;
    const int l0 = blockIdx.x * 512;
    const int tid = threadIdx.x;
    const int lane = tid & 31, wid = tid >> 5;
    const int wn = wid * 32;

    uint32_t ah_b[2], al_b[2], bh_b[2], bl_b[2];
#pragma unroll
    for (int s = 0; s < 2; s++) {
        uint32_t base = smem_u32(ksm + s * KV_STAGEF);
        ah_b[s] = base;
        al_b[s] = base + KV_AMS;
        bh_b[s] = base + 2 * KV_AMS;
        bl_b[s] = base + 2 * KV_AMS + KV_BMS;
    }

    const int a_row = (lane & 15);
    const int a_col = (lane >> 4) << 3;
    const int b_row = wn + (lane & 7) + ((lane >> 4) << 3);
    const int b_col = ((lane >> 3) & 1) << 3;

    const size_t abase = (size_t)bh * DHc * Lc + l0;
    const size_t bbase = (size_t)bh * Mc * Lc + l0;

    const int ga_row = tid >> 2, ga_c8 = (tid & 3) << 3;

    auto stage = [&](int kt) {
        const int s  = kt & 1;
        const int kk = kt << 5;
        uint32_t asoff = (uint32_t)(ga_row * LDT + ga_c8) * 2;
        const size_t ga = abase + (size_t)ga_row * Lc + kk + ga_c8;
        cp_async16(ah_b[s] + asoff, vthi + ga);
        cp_async16(al_b[s] + asoff, vtlo + ga);
#pragma unroll
        for (int i = 0; i < 4; i++) {
            int row = ga_row + i * 64;
            uint32_t bsoff = (uint32_t)(row * LDT + ga_c8) * 2;
            const size_t gb = bbase + (size_t)row * Lc + kk + ga_c8;
            cp_async16(bh_b[s] + bsoff, kfthi + gb);
            cp_async16(bl_b[s] + bsoff, kftlo + gb);
        }
        CP_COMMIT();
    };

    float acc[4][4][4];
#pragma unroll
    for (int mi = 0; mi < 4; mi++)
#pragma unroll
        for (int ni = 0; ni < 4; ni++)
#pragma unroll
            for (int e = 0; e < 4; e++) acc[mi][ni][e] = 0.f;

    stage(0); stage(1);

    for (int kt = 0; kt < KVNITF; kt++) {
        const int s = kt & 1;
        if (kt + 1 < KVNITF) CP_WAIT(1); else CP_WAIT(0);
        __syncthreads();

#pragma unroll
        for (int k0 = 0; k0 < 32; k0 += 16) {
            uint32_t bh_[2][4], bl_[2][4];
#pragma unroll
            for (int pr = 0; pr < 2; pr++) {
                uint32_t boff = (uint32_t)((b_row + pr * 16) * LDT + k0 + b_col) * 2;
                ldsm_x4(bh_[pr], bh_b[s] + boff);
                ldsm_x4(bl_[pr], bl_b[s] + boff);
            }
            uint32_t a[4][4];
#pragma unroll
            for (int mi = 0; mi < 4; mi++)
                ldsm_x4(a[mi], ah_b[s] +
                        (uint32_t)((a_row + mi * 16) * LDT + k0 + a_col) * 2);
#pragma unroll
            for (int mi = 0; mi < 4; mi++) {
                mma16816(acc[mi][0], a[mi], bh_[0][0], bh_[0][1]);
                mma16816(acc[mi][1], a[mi], bh_[0][2], bh_[0][3]);
                mma16816(acc[mi][2], a[mi], bh_[1][0], bh_[1][1]);
                mma16816(acc[mi][3], a[mi], bh_[1][2], bh_[1][3]);
            }
#pragma unroll
            for (int mi = 0; mi < 4; mi++) {
                mma16816(acc[mi][0], a[mi], bl_[0][0], bl_[0][1]);
                mma16816(acc[mi][1], a[mi], bl_[0][2], bl_[0][3]);
                mma16816(acc[mi][2], a[mi], bl_[1][0], bl_[1][1]);
                mma16816(acc[mi][3], a[mi], bl_[1][2], bl_[1][3]);
            }
#pragma unroll
            for (int mi = 0; mi < 4; mi++)
                ldsm_x4(a[mi], al_b[s] +
                        (uint32_t)((a_row + mi * 16) * LDT + k0 + a_col) * 2);
#pragma unroll
            for (int mi = 0; mi < 4; mi++) {
                mma16816(acc[mi][0], a[mi], bh_[0][0], bh_[0][1]);
                mma16816(acc[mi][1], a[mi], bh_[0][2], bh_[0][3]);
                mma16816(acc[mi][2], a[mi], bh_[1][0], bh_[1][1]);
                mma16816(acc[mi][3], a[mi], bh_[1][2], bh_[1][3]);
            }
        }
        __syncthreads();
        if (kt + 2 < KVNITF) stage(kt + 2);
    }

    const int lr = lane >> 2;
    const int c0 = wn + ((lane & 3) << 1);
    float* dst = kvtf + (size_t)bh * DHc * Mc;
#pragma unroll
    for (int mi = 0; mi < 4; mi++) {
        const int d0 = mi * 16 + lr;
        const int d1 = d0 + 8;
#pragma unroll
        for (int ni = 0; ni < 4; ni++) {
            int c = c0 + ni * 8;
            atomicAdd(&dst[d0 * Mc + c],     acc[mi][ni][0]);
            atomicAdd(&dst[d0 * Mc + c + 1], acc[mi][ni][1]);
            atomicAdd(&dst[d1 * Mc + c],     acc[mi][ni][2]);
            atomicAdd(&dst[d1 * Mc + c + 1], acc[mi][ni][3]);
        }
    }
}

// ============================================================
// kvtf fp32 -> kvthi/kvtlo
// ============================================================
__global__ __launch_bounds__(256) void kvsplit_kernel(
    const float* __restrict__ kvtf, bf16* __restrict__ Thi, bf16* __restrict__ Tlo)
{
    int i = blockIdx.x * 256 + threadIdx.x;
    float v = kvtf[i];
    bf16 h, l; split2(v, h, l);
    Thi[i] = h; Tlo[i] = l;
}

// ============================================================
// z[bh,l] = 1 / (dot(qf_hi+qf_lo, ksum) + 1e-6)
// ============================================================
__global__ __launch_bounds__(256) void z_kernel(
    const bf16* __restrict__ qfhi, const bf16* __restrict__ qflo,
    const float* __restrict__ ksum, float* __restrict__ z)
{
    __shared__ float ks[256];
    const int bh = blockIdx.y;
    ks[threadIdx.x] = ksum[bh * Mc + threadIdx.x];
    __syncthreads();
    const int w = threadIdx.x >> 5, lane = threadIdx.x & 31;
    const int l = blockIdx.x * 8 + w;
    const size_t base = ((size_t)bh * Lc + l) * Mc;
    float s = 0.f;
#pragma unroll
    for (int q8 = 0; q8 < 8; q8++) {
        int c = lane + q8 * 32;
        s += (__bfloat162float(qfhi[base + c]) + __bfloat162float(qflo[base + c])) * ks[c];
    }
#pragma unroll
    for (int off = 16; off; off >>= 1) s += __shfl_xor_sync(0xffffffffu, s, off);
    if (lane == 0) z[bh * Lc + l] = 1.0f / (s + 1e-6f);
}

// ============================================================
// attn via mma bf16x3 — fused-pass (R11, unchanged)
// ============================================================
#define ANITF 8
#define ATT_AMS (256 * LDT * 2)
#define ATT_BMS (64 * LDT * 2)
#define ATT_STAGEF (2 * ATT_AMS + 2 * ATT_BMS)
#define ATT_SMEMF (2 * ATT_STAGEF)

__global__ __launch_bounds__(256, 2) void attn_mma_kernel(
    const bf16* __restrict__ qfhi, const bf16* __restrict__ qflo,
    const bf16* __restrict__ kvthi, const bf16* __restrict__ kvtlo,
    const float* __restrict__ z,
    bf16* __restrict__ Ohi, bf16* __restrict__ Olo)
{
    extern __shared__ char asm_[];
    const int bh = blockIdx.y;
    const int b = bh >> 4, h = bh & 15;
    const int l0 = blockIdx.x * 256;
    const int tid = threadIdx.x;
    const int lane = tid & 31, wid = tid >> 5;
    const int wm = (wid >> 1) * 64;
    const int wn = (wid & 1) * 32;

    uint32_t ah_b[2], al_b[2], bh_b[2], bl_b[2];
#pragma unroll
    for (int s = 0; s < 2; s++) {
        uint32_t base = smem_u32(asm_ + s * ATT_STAGEF);
        ah_b[s] = base;
        al_b[s] = base + ATT_AMS;
        bh_b[s] = base + 2 * ATT_AMS;
        bl_b[s] = base + 2 * ATT_AMS + ATT_BMS;
    }

    const int a_row = wm + (lane & 15);
    const int a_col = (lane >> 4) << 3;
    const int b_row = wn + (lane & 7) + ((lane >> 4) << 3);
    const int b_col = ((lane >> 3) & 1) << 3;

    const size_t qbase = ((size_t)bh * Lc + l0) * Mc;
    const size_t kbase = (size_t)bh * DHc * Mc;

    const int ga_row = tid >> 2, ga_c8 = (tid & 3) << 3;

    auto stage = [&](int kt) {
        const int s  = kt & 1;
        const int kk = kt << 5;
#pragma unroll
        for (int i = 0; i < 4; i++) {
            int row = ga_row + i * 64;
            uint32_t soff = (uint32_t)(row * LDT + ga_c8) * 2;
            const size_t ga = qbase + (size_t)row * Mc + kk + ga_c8;
            cp_async16(ah_b[s] + soff, qfhi + ga);
            cp_async16(al_b[s] + soff, qflo + ga);
        }
        uint32_t bsoff = (uint32_t)(ga_row * LDT + ga_c8) * 2;
        const size_t gb = kbase + (size_t)ga_row * Mc + kk + ga_c8;
        cp_async16(bh_b[s] + bsoff, kvthi + gb);
        cp_async16(bl_b[s] + bsoff, kvtlo + gb);
        CP_COMMIT();
    };

    float acc[4][4][4];
#pragma unroll
    for (int mi = 0; mi < 4; mi++)
#pragma unroll
        for (int ni = 0; ni < 4; ni++)
#pragma unroll
            for (int e = 0; e < 4; e++) acc[mi][ni][e] = 0.f;

    stage(0); stage(1);

    for (int kt = 0; kt < ANITF; kt++) {
        const int s = kt & 1;
        if (kt + 1 < ANITF) CP_WAIT(1); else CP_WAIT(0);
        __syncthreads();

#pragma unroll
        for (int k0 = 0; k0 < 32; k0 += 16) {
            uint32_t bh_[2][4], bl_[2][4];
#pragma unroll
            for (int pr = 0; pr < 2; pr++) {
                uint32_t boff = (uint32_t)((b_row + pr * 16) * LDT + k0 + b_col) * 2;
                ldsm_x4(bh_[pr], bh_b[s] + boff);
                ldsm_x4(bl_[pr], bl_b[s] + boff);
            }
            uint32_t a[4][4];
#pragma unroll
            for (int mi = 0; mi < 4; mi++)
                ldsm_x4(a[mi], ah_b[s] +
                        (uint32_t)((a_row + mi * 16) * LDT + k0 + a_col) * 2);
#pragma unroll
            for (int mi = 0; mi < 4; mi++) {
                mma16816(acc[mi][0], a[mi], bh_[0][0], bh_[0][1]);
                mma16816(acc[mi][1], a[mi], bh_[0][2], bh_[0][3]);
                mma16816(acc[mi][2], a[mi], bh_[1][0], bh_[1][1]);
                mma16816(acc[mi][3], a[mi], bh_[1][2], bh_[1][3]);
            }
#pragma unroll
            for (int mi = 0; mi < 4; mi++) {
                mma16816(acc[mi][0], a[mi], bl_[0][0], bl_[0][1]);
                mma16816(acc[mi][1], a[mi], bl_[0][2], bl_[0][3]);
                mma16816(acc[mi][2], a[mi], bl_[1][0], bl_[1][1]);
                mma16816(acc[mi][3], a[mi], bl_[1][2], bl_[1][3]);
            }
#pragma unroll
            for (int mi = 0; mi < 4; mi++)
                ldsm_x4(a[mi], al_b[s] +
                        (uint32_t)((a_row + mi * 16) * LDT + k0 + a_col) * 2);
#pragma unroll
            for (int mi = 0; mi < 4; mi++) {
                mma16816(acc[mi][0], a[mi], bh_[0][0], bh_[0][1]);
                mma16816(acc[mi][1], a[mi], bh_[0][2], bh_[0][3]);
                mma16816(acc[mi][2], a[mi], bh_[1][0], bh_[1][1]);
                mma16816(acc[mi][3], a[mi], bh_[1][2], bh_[1][3]);
            }
        }
        __syncthreads();
        if (kt + 2 < ANITF) stage(kt + 2);
    }

    const int lr = lane >> 2;
    const int occ0 = wn + ((lane & 3) << 1);
#pragma unroll
    for (int mi = 0; mi < 4; mi++) {
        const int r0 = wm + mi * 16 + lr;
        const int r1 = r0 + 8;
        const float z0 = z[(size_t)bh * Lc + l0 + r0];
        const float z1 = z[(size_t)bh * Lc + l0 + r1];
        const size_t i0 = (size_t)(b * Lc + l0 + r0) * Dc + h * DHc;
        const size_t i1 = (size_t)(b * Lc + l0 + r1) * Dc + h * DHc;
#pragma unroll
        for (int ni = 0; ni < 4; ni++) {
            int c = occ0 + ni * 8;
            bf16 h0,l0b,h1,l1b,h2,l2b,h3,l3b;
            split2(acc[mi][ni][0] * z0, h0, l0b);
            split2(acc[mi][ni][1] * z0, h1, l1b);
            split2(acc[mi][ni][2] * z1, h2, l2b);
            split2(acc[mi][ni][3] * z1, h3, l3b);
            *(__nv_bfloat162*)&Ohi[i0 + c] = __halves2bfloat162(h0, h1);
            *(__nv_bfloat162*)&Ohi[i1 + c] = __halves2bfloat162(h2, h3);
            *(__nv_bfloat162*)&Olo[i0 + c] = __halves2bfloat162(l0b, l1b);
            *(__nv_bfloat162*)&Olo[i1 + c] = __halves2bfloat162(l2b, l3b);
        }
    }
}

// ============================================================
// LayerNorm + duplicate rows
// ============================================================
__global__ __launch_bounds__(256) void ln_dup_kernel(
    const float* __restrict__ y, const float* __restrict__ g,
    const float* __restrict__ beta, float* __restrict__ out)
{
    __shared__ float red[18];
    const int row = blockIdx.x;
    const int b = row >> 12, l = row & 4095;
    const int tid = threadIdx.x;
    const float* yr = y + (size_t)row * Dc;

    float v[4];
    float s = 0.f, ss = 0.f;
#pragma unroll
    for (int i = 0; i < 4; i++) {
        float t = yr[tid + i * 256];
        v[i] = t; s += t; ss += t * t;
    }
#pragma unroll
    for (int off = 16; off; off >>= 1) {
        s  += __shfl_xor_sync(0xffffffffu, s, off);
        ss += __shfl_xor_sync(0xffffffffu, ss, off);
    }
    const int w = tid >> 5, lane = tid & 31;
    if (lane == 0) { red[w] = s; red[8 + w] = ss; }
    __syncthreads();
    if (tid == 0) {
        float ts = 0.f, tss = 0.f;
#pragma unroll
        for (int i = 0; i < 8; i++) { ts += red[i]; tss += red[8 + i]; }
        float mean = ts * (1.0f / 1024.0f);
        float var = tss * (1.0f / 1024.0f) - mean * mean;
        red[16] = mean;
        red[17] = rsqrtf(var + 1e-5f);
    }
    __syncthreads();
    const float mean = red[16], rstd = red[17];
    float* o0 = out + ((size_t)b * 8192 + 2 * (size_t)l) * Dc;
#pragma unroll
    for (int i = 0; i < 4; i++) {
        int c = tid + i * 256;
        float o = (v[i] - mean) * rstd * g[c] + beta[c];
        o0[c] = o;
        o0[Dc + c] = o;
    }
}

// ============================================================
// host launch
// ============================================================
extern "C" void kernel_launch(void* const* d_in, const int* in_sizes, int n_in,
                              void* d_out, int out_size)
{
    const float* x    = (const float*)d_in[0];
    const float* Wq   = (const float*)d_in[1];
    const float* Wk   = (const float*)d_in[2];
    const float* Wv   = (const float*)d_in[3];
    const float* Wo   = (const float*)d_in[4];
    const float* proj = (const float*)d_in[5];
    const float* ln_g = (const float*)d_in[6];
    const float* ln_b = (const float*)d_in[7];
    float* out = (float*)d_out;

    float *v, *kvtf, *ksum, *z, *y;
    bf16 *qfhi, *qflo, *kfthi, *kftlo, *vthi, *vtlo, *kvthi, *kvtlo;
    bf16 *ahi, *alo, *bthi, *btlo, *qhi, *qlo, *khi, *klo, *phi, *plo;
    cudaGetSymbolAddress((void**)&v,     g_v);
    cudaGetSymbolAddress((void**)&qfhi,  g_qfhi);
    cudaGetSymbolAddress((void**)&qflo,  g_qflo);
    cudaGetSymbolAddress((void**)&kfthi, g_kfthi);
    cudaGetSymbolAddress((void**)&kftlo, g_kftlo);
    cudaGetSymbolAddress((void**)&vthi,  g_vthi);
    cudaGetSymbolAddress((void**)&vtlo,  g_vtlo);
    cudaGetSymbolAddress((void**)&kvtf,  g_kvtf);
    cudaGetSymbolAddress((void**)&kvthi, g_kvthi);
    cudaGetSymbolAddress((void**)&kvtlo, g_kvtlo);
    cudaGetSymbolAddress((void**)&ksum,  g_ksum);
    cudaGetSymbolAddress((void**)&z,     g_z);
    cudaGetSymbolAddress((void**)&y,     g_y);
    cudaGetSymbolAddress((void**)&ahi,   g_ahi);
    cudaGetSymbolAddress((void**)&alo,   g_alo);
    cudaGetSymbolAddress((void**)&bthi,  g_bthi);
    cudaGetSymbolAddress((void**)&btlo,  g_btlo);
    cudaGetSymbolAddress((void**)&qhi,   g_qhi);
    cudaGetSymbolAddress((void**)&qlo,   g_qlo);
    cudaGetSymbolAddress((void**)&khi,   g_khi);
    cudaGetSymbolAddress((void**)&klo,   g_klo);
    cudaGetSymbolAddress((void**)&phi,   g_phi);
    cudaGetSymbolAddress((void**)&plo,   g_plo);

    const float qscale = 0.35355339059327379f;  // 64^-0.25

    cudaFuncSetAttribute(mma_gemm_kernel<0>,
                         cudaFuncAttributeMaxDynamicSharedMemorySize, GEMM_SMEMF);
    cudaFuncSetAttribute(mma_gemm_kernel<1>,
                         cudaFuncAttributeMaxDynamicSharedMemorySize, GEMM_SMEMF);
    cudaFuncSetAttribute(feature_mma_kernel<1>,
                         cudaFuncAttributeMaxDynamicSharedMemorySize, FEAT2_SMEM);
    cudaFuncSetAttribute(feature_mma_kernel<2>,
                         cudaFuncAttributeMaxDynamicSharedMemorySize, FEAT2_SMEM);
    cudaFuncSetAttribute(kv_mma_kernel,
                         cudaFuncAttributeMaxDynamicSharedMemorySize, KV_SMEMF);
    cudaFuncSetAttribute(attn_mma_kernel,
                         cudaFuncAttributeMaxDynamicSharedMemorySize, ATT_SMEMF);

    const int n4 = ROWS * Dc / 4;

    // splits (weights: single fused launch)
    split_kernel<<<n4 / 256, 256>>>(x, ahi, alo, n4);
    split_kernel<<<(Hc * Mc * DHc / 4) / 256, 256>>>(proj, phi, plo, Hc * Mc * DHc / 4);
    tsplit4_kernel<<<dim3(32, 32, 4), dim3(32, 8)>>>(Wq, Wk, Wv, Wo, bthi, btlo);

    // zero accumulators (consumed by feature<2> and kv_mma)
    cudaMemsetAsync(ksum, 0, (size_t)BHc * Mc * sizeof(float), 0);
    cudaMemsetAsync(kvtf, 0, (size_t)BHc * DHc * Mc * sizeof(float), 0);

    // fused QKV GEMM (V -> fp32)
    mma_gemm_kernel<0><<<dim3(24, 64), 256, GEMM_SMEMF>>>(
        ahi, alo, bthi, btlo, v, qhi, qlo, khi, klo, qscale);

    // features: Q -> qf hi/lo [l][m]; K -> kf_t hi/lo [m][l] + ksum
    feature_mma_kernel<1><<<dim3(Lc / 128, BHc), 256, FEAT2_SMEM>>>(
        qhi, qlo, phi, plo, qfhi, qflo, nullptr);
    feature_mma_kernel<2><<<dim3(Lc / 128, BHc), 256, FEAT2_SMEM>>>(
        khi, klo, phi, plo, kfthi, kftlo, ksum);

    // v transpose+split, then kv via tensor cores
    vt_kernel<<<dim3(Lc / 32, BHc), 256>>>(v, vthi, vtlo);
    kv_mma_kernel<<<dim3(8, BHc), 256, KV_SMEMF>>>(vthi, vtlo, kfthi, kftlo, kvtf);
    kvsplit_kernel<<<(BHc * DHc * Mc) / 256, 256>>>(kvtf, kvthi, kvtlo);

    z_kernel<<<dim3(Lc / 8, BHc), 256>>>(qfhi, qflo, ksum, z);

    // attn -> hi/lo directly into O-GEMM A buffers
    attn_mma_kernel<<<dim3(Lc / 256, BHc), 256, ATT_SMEMF>>>(
        qfhi, qflo, kvthi, kvtlo, z, ahi, alo);

    // O projection + exact GELU (weights at offset 3)
    mma_gemm_kernel<1><<<dim3(8, 64), 256, GEMM_SMEMF>>>(
        ahi, alo, bthi + (size_t)3 * Dc * Dc, btlo + (size_t)3 * Dc * Dc,
        y, nullptr, nullptr, nullptr, nullptr, 1.0f);

    ln_dup_kernel<<<ROWS, 256>>>(y, ln_g, ln_b, out);
}

// round 14
// speedup vs baseline: 1.0336x; 1.0196x over previous
#include <cuda_runtime.h>
#include <cuda_bf16.h>
#include <math.h>
#include <stdint.h>

// Shapes (fixed)
#define Bc   2
#define Lc   4096
#define Dc   1024
#define Hc   16
#define DHc  64
#define Mc   256
#define BHc  32
#define ROWS 8192   // B*L

typedef __nv_bfloat16 bf16;

// -------- scratch (device globals; no allocations allowed) --------
__device__ float g_v    [(size_t)ROWS * Dc];
__device__ bf16  g_qfhi [(size_t)BHc * Lc * Mc];
__device__ bf16  g_qflo [(size_t)BHc * Lc * Mc];
__device__ bf16  g_kfthi[(size_t)BHc * Mc * Lc];
__device__ bf16  g_kftlo[(size_t)BHc * Mc * Lc];
__device__ bf16  g_vthi [(size_t)BHc * DHc * Lc];
__device__ bf16  g_vtlo [(size_t)BHc * DHc * Lc];
__device__ float g_kvtf [(size_t)BHc * DHc * Mc];
__device__ bf16  g_kvthi[(size_t)BHc * DHc * Mc];
__device__ bf16  g_kvtlo[(size_t)BHc * DHc * Mc];
__device__ float g_ksum [(size_t)BHc * Mc];
__device__ float g_y    [(size_t)ROWS * Dc];
__device__ bf16  g_ahi  [(size_t)ROWS * Dc];
__device__ bf16  g_alo  [(size_t)ROWS * Dc];
__device__ bf16  g_bthi [(size_t)4 * Dc * Dc];
__device__ bf16  g_btlo [(size_t)4 * Dc * Dc];
__device__ bf16  g_qhi  [(size_t)ROWS * Dc];
__device__ bf16  g_qlo  [(size_t)ROWS * Dc];
__device__ bf16  g_khi  [(size_t)ROWS * Dc];
__device__ bf16  g_klo  [(size_t)ROWS * Dc];
__device__ bf16  g_phi  [(size_t)Hc * Mc * DHc];
__device__ bf16  g_plo  [(size_t)Hc * Mc * DHc];

// ================= baseline-PTX tensor-core helpers (sm_80+) ==========
__device__ __forceinline__ uint32_t smem_u32(const void* p) {
    uint32_t a;
    asm("{ .reg .u64 t; cvta.to.shared.u64 t, %1; cvt.u32.u64 %0, t; }"
        : "=r"(a) : "l"(p));
    return a;
}
__device__ __forceinline__ void cp_async16(uint32_t saddr, const void* g) {
    asm volatile("cp.async.cg.shared.global [%0], [%1], 16;"
                 :: "r"(saddr), "l"(g) : "memory");
}
#define CP_COMMIT() asm volatile("cp.async.commit_group;" ::: "memory")
#define CP_WAIT(n)  asm volatile("cp.async.wait_group %0;" :: "n"(n) : "memory")

__device__ __forceinline__ void ldsm_x4(uint32_t r[4], uint32_t addr) {
    asm volatile("ldmatrix.sync.aligned.m8n8.x4.shared.b16 {%0,%1,%2,%3}, [%4];"
                 : "=r"(r[0]), "=r"(r[1]), "=r"(r[2]), "=r"(r[3]) : "r"(addr));
}
__device__ __forceinline__ void mma16816(float c[4], const uint32_t a[4],
                                         uint32_t b0, uint32_t b1) {
    asm volatile(
        "mma.sync.aligned.m16n8k16.row.col.f32.bf16.bf16.f32 "
        "{%0,%1,%2,%3}, {%4,%5,%6,%7}, {%8,%9}, {%0,%1,%2,%3};"
        : "+f"(c[0]), "+f"(c[1]), "+f"(c[2]), "+f"(c[3])
        : "r"(a[0]), "r"(a[1]), "r"(a[2]), "r"(a[3]), "r"(b0), "r"(b1));
}
__device__ __forceinline__ void split2(float v, bf16& h, bf16& l) {
    h = __float2bfloat16_rn(v);
    l = __float2bfloat16_rn(v - __bfloat162float(h));
}

// ============================================================
// fp32 -> (hi, lo) bf16 split
// ============================================================
__global__ __launch_bounds__(256) void split_kernel(
    const float* __restrict__ in, bf16* __restrict__ hi,
    bf16* __restrict__ lo, int n4)
{
    int i = blockIdx.x * 256 + threadIdx.x;
    if (i >= n4) return;
    float4 v = ((const float4*)in)[i];
    bf16 h0, h1, h2, h3, l0, l1, l2, l3;
    split2(v.x, h0, l0); split2(v.y, h1, l1);
    split2(v.z, h2, l2); split2(v.w, h3, l3);
    ((__nv_bfloat162*)hi)[2*i]   = __halves2bfloat162(h0, h1);
    ((__nv_bfloat162*)hi)[2*i+1] = __halves2bfloat162(h2, h3);
    ((__nv_bfloat162*)lo)[2*i]   = __halves2bfloat162(l0, l1);
    ((__nv_bfloat162*)lo)[2*i+1] = __halves2bfloat162(l2, l3);
}

// ============================================================
// 4 weights [K,N] -> W^T [N,K] bf16 hi/lo, single launch
// ============================================================
__global__ void tsplit4_kernel(
    const float* __restrict__ W0, const float* __restrict__ W1,
    const float* __restrict__ W2, const float* __restrict__ W3,
    bf16* __restrict__ Thi, bf16* __restrict__ Tlo)
{
    __shared__ float t[32][33];
    const float* W = (blockIdx.z == 0) ? W0 : (blockIdx.z == 1) ? W1
                    : (blockIdx.z == 2) ? W2 : W3;
    bf16* th = Thi + (size_t)blockIdx.z * Dc * Dc;
    bf16* tl = Tlo + (size_t)blockIdx.z * Dc * Dc;
    int bx = blockIdx.x * 32, by = blockIdx.y * 32;
    int tx = threadIdx.x, ty = threadIdx.y;   // 32 x 8
#pragma unroll
    for (int i = 0; i < 32; i += 8)
        t[ty + i][tx] = W[(size_t)(by + ty + i) * Dc + bx + tx];
    __syncthreads();
#pragma unroll
    for (int i = 0; i < 32; i += 8) {
        float v = t[tx][ty + i];
        int orow = bx + ty + i, ocol = by + tx;
        bf16 h, l; split2(v, h, l);
        th[(size_t)orow * Dc + ocol] = h;
        tl[(size_t)orow * Dc + ocol] = l;
    }
}

// ============================================================
// v [b*L][D] fp32 -> v_t [bh][d][l] bf16 hi/lo
// ============================================================
__global__ __launch_bounds__(256) void vt_kernel(
    const float* __restrict__ v, bf16* __restrict__ Thi, bf16* __restrict__ Tlo)
{
    __shared__ float t[64][33];
    const int bh = blockIdx.y;
    const int b = bh >> 4, h = bh & 15;
    const int l0 = blockIdx.x * 32;
    const int tid = threadIdx.x;
#pragma unroll
    for (int i = 0; i < 8; i++) {
        int s = tid + i * 256;
        int r = s >> 6, c = s & 63;
        t[c][r & 31] = v[(size_t)(b * Lc + l0 + r) * Dc + h * DHc + c];
    }
    __syncthreads();
#pragma unroll
    for (int i = 0; i < 8; i++) {
        int s = tid + i * 256;
        int d = s >> 5, c = s & 31;
        float val = t[d][c];
        bf16 hh, ll; split2(val, hh, ll);
        size_t o = ((size_t)bh * DHc + d) * Lc + l0 + c;
        Thi[o] = hh; Tlo[o] = ll;
    }
}

// ============================================================
// bf16x3 FUSED-PASS tensor-core GEMM (R13, unchanged)
// ============================================================
#define LDT 40
#define GNITF 32
#define GEMM_MSTG (128 * LDT * 2)
#define GEMM_STAGE (4 * GEMM_MSTG)
#define GEMM_SMEMF (2 * GEMM_STAGE)

template<int MODE>
__global__ __launch_bounds__(256, 2) void mma_gemm_kernel(
    const bf16* __restrict__ Ahi, const bf16* __restrict__ Alo,
    const bf16* __restrict__ Bhi, const bf16* __restrict__ Blo,
    float* __restrict__ Cv,
    bf16* __restrict__ Qhi, bf16* __restrict__ Qlo,
    bf16* __restrict__ Khi, bf16* __restrict__ Klo,
    float qalpha)
{
    extern __shared__ char gsm[];
    const int tid  = threadIdx.x;
    const int lane = tid & 31, wid = tid >> 5;
    const int bm = blockIdx.y * 128;
    const int bn = blockIdx.x * 128;
    const int wm = (wid >> 2) * 64;
    const int wn = (wid & 3) * 32;

    uint32_t ah_b[2], al_b[2], bh_b[2], bl_b[2];
#pragma unroll
    for (int s = 0; s < 2; s++) {
        uint32_t base = smem_u32(gsm + s * GEMM_STAGE);
        ah_b[s] = base;
        al_b[s] = base + GEMM_MSTG;
        bh_b[s] = base + 2 * GEMM_MSTG;
        bl_b[s] = base + 3 * GEMM_MSTG;
    }

    const int a_row = wm + (lane & 15);
    const int a_col = (lane >> 4) << 3;
    const int b_row = wn + (lane & 7) + ((lane >> 4) << 3);
    const int b_col = ((lane >> 3) & 1) << 3;

    const int g_row0 = tid >> 2;
    const int g_c8   = (tid & 3) << 3;

    auto stage = [&](int kt) {
        const int s  = kt & 1;
        const int kk = kt << 5;
#pragma unroll
        for (int i = 0; i < 2; i++) {
            int row = g_row0 + i * 64;
            uint32_t soff = (uint32_t)(row * LDT + g_c8) * 2;
            const size_t ga = (size_t)(bm + row) * Dc + kk + g_c8;
            const size_t gb = (size_t)(bn + row) * Dc + kk + g_c8;
            cp_async16(ah_b[s] + soff, Ahi + ga);
            cp_async16(al_b[s] + soff, Alo + ga);
            cp_async16(bh_b[s] + soff, Bhi + gb);
            cp_async16(bl_b[s] + soff, Blo + gb);
        }
        CP_COMMIT();
    };

    float acc[4][4][4];
#pragma unroll
    for (int mi = 0; mi < 4; mi++)
#pragma unroll
        for (int ni = 0; ni < 4; ni++)
#pragma unroll
            for (int e = 0; e < 4; e++) acc[mi][ni][e] = 0.f;

    stage(0); stage(1);

    for (int kt = 0; kt < GNITF; kt++) {
        const int s = kt & 1;
        if (kt + 1 < GNITF) CP_WAIT(1); else CP_WAIT(0);
        __syncthreads();

#pragma unroll
        for (int k0 = 0; k0 < 32; k0 += 16) {
            uint32_t bh_[2][4], bl_[2][4];
#pragma unroll
            for (int pr = 0; pr < 2; pr++) {
                uint32_t boff = (uint32_t)((b_row + pr * 16) * LDT + k0 + b_col) * 2;
                ldsm_x4(bh_[pr], bh_b[s] + boff);
                ldsm_x4(bl_[pr], bl_b[s] + boff);
            }
            uint32_t a[4][4];
#pragma unroll
            for (int mi = 0; mi < 4; mi++)
                ldsm_x4(a[mi], ah_b[s] +
                        (uint32_t)((a_row + mi * 16) * LDT + k0 + a_col) * 2);
#pragma unroll
            for (int mi = 0; mi < 4; mi++) {
                mma16816(acc[mi][0], a[mi], bh_[0][0], bh_[0][1]);
                mma16816(acc[mi][1], a[mi], bh_[0][2], bh_[0][3]);
                mma16816(acc[mi][2], a[mi], bh_[1][0], bh_[1][1]);
                mma16816(acc[mi][3], a[mi], bh_[1][2], bh_[1][3]);
            }
#pragma unroll
            for (int mi = 0; mi < 4; mi++) {
                mma16816(acc[mi][0], a[mi], bl_[0][0], bl_[0][1]);
                mma16816(acc[mi][1], a[mi], bl_[0][2], bl_[0][3]);
                mma16816(acc[mi][2], a[mi], bl_[1][0], bl_[1][1]);
                mma16816(acc[mi][3], a[mi], bl_[1][2], bl_[1][3]);
            }
#pragma unroll
            for (int mi = 0; mi < 4; mi++)
                ldsm_x4(a[mi], al_b[s] +
                        (uint32_t)((a_row + mi * 16) * LDT + k0 + a_col) * 2);
#pragma unroll
            for (int mi = 0; mi < 4; mi++) {
                mma16816(acc[mi][0], a[mi], bh_[0][0], bh_[0][1]);
                mma16816(acc[mi][1], a[mi], bh_[0][2], bh_[0][3]);
                mma16816(acc[mi][2], a[mi], bh_[1][0], bh_[1][1]);
                mma16816(acc[mi][3], a[mi], bh_[1][2], bh_[1][3]);
            }
        }
        __syncthreads();
        if (kt + 2 < GNITF) stage(kt + 2);
    }

    const int orow = bm + wm + (lane >> 2);
    const int occ0 = wn + ((lane & 3) << 1);

    if (MODE == 0) {
        const int which = bn >> 10;        // 0 q, 1 k, 2 v
        const int bnl = bn & 1023;
        if (which < 2) {
            bf16* Oh = which ? Khi : Qhi;
            bf16* Ol = which ? Klo : Qlo;
#pragma unroll
            for (int mi = 0; mi < 4; mi++)
#pragma unroll
                for (int ni = 0; ni < 4; ni++) {
                    const size_t i0 = (size_t)(orow + mi * 16) * Dc + bnl + occ0 + ni * 8;
                    const size_t i1 = (size_t)(orow + mi * 16 + 8) * Dc + bnl + occ0 + ni * 8;
                    bf16 h0,l0,h1,l1,h2,l2,h3,l3;
                    split2(acc[mi][ni][0] * qalpha, h0, l0);
                    split2(acc[mi][ni][1] * qalpha, h1, l1);
                    split2(acc[mi][ni][2] * qalpha, h2, l2);
                    split2(acc[mi][ni][3] * qalpha, h3, l3);
                    *(__nv_bfloat162*)&Oh[i0] = __halves2bfloat162(h0, h1);
                    *(__nv_bfloat162*)&Oh[i1] = __halves2bfloat162(h2, h3);
                    *(__nv_bfloat162*)&Ol[i0] = __halves2bfloat162(l0, l1);
                    *(__nv_bfloat162*)&Ol[i1] = __halves2bfloat162(l2, l3);
                }
        } else {
#pragma unroll
            for (int mi = 0; mi < 4; mi++)
#pragma unroll
                for (int ni = 0; ni < 4; ni++) {
                    const size_t i0 = (size_t)(orow + mi * 16) * Dc + bnl + occ0 + ni * 8;
                    const size_t i1 = (size_t)(orow + mi * 16 + 8) * Dc + bnl + occ0 + ni * 8;
                    *(float2*)&Cv[i0] = make_float2(acc[mi][ni][0], acc[mi][ni][1]);
                    *(float2*)&Cv[i1] = make_float2(acc[mi][ni][2], acc[mi][ni][3]);
                }
        }
    } else {
#pragma unroll
        for (int mi = 0; mi < 4; mi++)
#pragma unroll
            for (int ni = 0; ni < 4; ni++) {
                float v0 = acc[mi][ni][0], v1 = acc[mi][ni][1];
                float v2 = acc[mi][ni][2], v3 = acc[mi][ni][3];
                v0 = 0.5f * v0 * (1.f + erff(v0 * 0.70710678118654752f));
                v1 = 0.5f * v1 * (1.f + erff(v1 * 0.70710678118654752f));
                v2 = 0.5f * v2 * (1.f + erff(v2 * 0.70710678118654752f));
                v3 = 0.5f * v3 * (1.f + erff(v3 * 0.70710678118654752f));
                const size_t i0 = (size_t)(orow + mi * 16) * Dc + bn + occ0 + ni * 8;
                const size_t i1 = (size_t)(orow + mi * 16 + 8) * Dc + bn + occ0 + ni * 8;
                *(float2*)&Cv[i0] = make_float2(v0, v1);
                *(float2*)&Cv[i1] = make_float2(v2, v3);
            }
    }
}

// ============================================================
// FAVOR+ feature via mma.sync bf16x3 — fused passes (R13, unchanged)
// ============================================================
#define FLDK 72
#define FEAT2_SMEM ((128 + 128 + 256 + 256) * FLDK * 2 + 128 * 4 + 4 * 128 * 4 + 256 * 4)

template<int OMODE>
__global__ __launch_bounds__(256) void feature_mma_kernel(
    const bf16* __restrict__ Uhi, const bf16* __restrict__ Ulo,
    const bf16* __restrict__ Phi, const bf16* __restrict__ Plo,
    bf16* __restrict__ Fhi, bf16* __restrict__ Flo,
    float* __restrict__ ksum)
{
    extern __shared__ char fsm[];
    bf16* us_h = (bf16*)fsm;
    bf16* us_l = us_h + 128 * FLDK;
    bf16* ps_h = us_l + 128 * FLDK;
    bf16* ps_l = ps_h + 256 * FLDK;
    float* diag   = (float*)(ps_l + 256 * FLDK);
    float* rmaxp  = diag + 128;
    float* colsum = rmaxp + 4 * 128;

    const int bh = blockIdx.y;
    const int b = bh >> 4, h = bh & 15;
    const int l0 = blockIdx.x * 128;
    const int tid = threadIdx.x;
    const int lane = tid & 31, wid = tid >> 5;

#pragma unroll
    for (int i = 0; i < 4; i++) {
        int s = tid + i * 256;
        int r = s >> 3, c8 = (s & 7) << 3;
        size_t gi = (size_t)(b * Lc + l0 + r) * Dc + h * DHc + c8;
        *(uint4*)&us_h[r * FLDK + c8] = *(const uint4*)&Uhi[gi];
        *(uint4*)&us_l[r * FLDK + c8] = *(const uint4*)&Ulo[gi];
    }
#pragma unroll
    for (int i = 0; i < 8; i++) {
        int s = tid + i * 256;
        int r = s >> 3, c8 = (s & 7) << 3;
        size_t gi = (size_t)(h * Mc + r) * DHc + c8;
        *(uint4*)&ps_h[r * FLDK + c8] = *(const uint4*)&Phi[gi];
        *(uint4*)&ps_l[r * FLDK + c8] = *(const uint4*)&Plo[gi];
    }
    __syncthreads();

    if (tid < 128) {
        float s = 0.f;
#pragma unroll
        for (int d2 = 0; d2 < 32; d2++) {
            __nv_bfloat162 hh = *(__nv_bfloat162*)&us_h[tid * FLDK + d2 * 2];
            __nv_bfloat162 ll = *(__nv_bfloat162*)&us_l[tid * FLDK + d2 * 2];
            float u0 = __bfloat162float(hh.x) + __bfloat162float(ll.x);
            float u1 = __bfloat162float(hh.y) + __bfloat162float(ll.y);
            s += u0 * u0 + u1 * u1;
        }
        diag[tid] = 0.5f * s;
    }

    const int wm = (wid >> 2) * 64;
    const int wn = (wid & 3) * 64;
    const int a_row = wm + (lane & 15);
    const int a_col = (lane >> 4) << 3;
    const int b_row = wn + (lane & 7) + ((lane >> 4) << 3);
    const int b_col = ((lane >> 3) & 1) << 3;

    float acc[4][8][4];
#pragma unroll
    for (int mi = 0; mi < 4; mi++)
#pragma unroll
        for (int ni = 0; ni < 8; ni++)
#pragma unroll
            for (int e = 0; e < 4; e++) acc[mi][ni][e] = 0.f;

    const uint32_t ush = smem_u32(us_h), usl = smem_u32(us_l);
    const uint32_t psh = smem_u32(ps_h), psl = smem_u32(ps_l);
    __syncthreads();

#pragma unroll
    for (int k0 = 0; k0 < 64; k0 += 16) {
        uint32_t ah[4][4], al[4][4], bfr[4][4];
#pragma unroll
        for (int mi = 0; mi < 4; mi++) {
            uint32_t aoff = (uint32_t)((a_row + mi * 16) * FLDK + k0 + a_col) * 2;
            ldsm_x4(ah[mi], ush + aoff);
            ldsm_x4(al[mi], usl + aoff);
        }
#pragma unroll
        for (int pr = 0; pr < 4; pr++)
            ldsm_x4(bfr[pr], psh + (uint32_t)((b_row + pr * 16) * FLDK + k0 + b_col) * 2);
#pragma unroll
        for (int mi = 0; mi < 4; mi++)
#pragma unroll
            for (int pr = 0; pr < 4; pr++) {
                mma16816(acc[mi][2 * pr],     ah[mi], bfr[pr][0], bfr[pr][1]);
                mma16816(acc[mi][2 * pr + 1], ah[mi], bfr[pr][2], bfr[pr][3]);
            }
#pragma unroll
        for (int mi = 0; mi < 4; mi++)
#pragma unroll
            for (int pr = 0; pr < 4; pr++) {
                mma16816(acc[mi][2 * pr],     al[mi], bfr[pr][0], bfr[pr][1]);
                mma16816(acc[mi][2 * pr + 1], al[mi], bfr[pr][2], bfr[pr][3]);
            }
#pragma unroll
        for (int pr = 0; pr < 4; pr++)
            ldsm_x4(bfr[pr], psl + (uint32_t)((b_row + pr * 16) * FLDK + k0 + b_col) * 2);
#pragma unroll
        for (int mi = 0; mi < 4; mi++)
#pragma unroll
            for (int pr = 0; pr < 4; pr++) {
                mma16816(acc[mi][2 * pr],     ah[mi], bfr[pr][0], bfr[pr][1]);
                mma16816(acc[mi][2 * pr + 1], ah[mi], bfr[pr][2], bfr[pr][3]);
            }
    }

    float tmax[4][2];
#pragma unroll
    for (int mi = 0; mi < 4; mi++) {
        float m0 = -1e30f, m1 = -1e30f;
#pragma unroll
        for (int ni = 0; ni < 8; ni++) {
            m0 = fmaxf(m0, fmaxf(acc[mi][ni][0], acc[mi][ni][1]));
            m1 = fmaxf(m1, fmaxf(acc[mi][ni][2], acc[mi][ni][3]));
        }
#pragma unroll
        for (int off = 1; off <= 2; off <<= 1) {
            m0 = fmaxf(m0, __shfl_xor_sync(0xffffffffu, m0, off));
            m1 = fmaxf(m1, __shfl_xor_sync(0xffffffffu, m1, off));
        }
        tmax[mi][0] = m0; tmax[mi][1] = m1;
    }
    if ((lane & 3) == 0) {
        const int slab = wid & 3;
#pragma unroll
        for (int mi = 0; mi < 4; mi++) {
            int r = wm + mi * 16 + (lane >> 2);
            rmaxp[slab * 128 + r]     = tmax[mi][0];
            rmaxp[slab * 128 + r + 8] = tmax[mi][1];
        }
    }
    if (OMODE == 2 && tid < 256) colsum[tid] = 0.f;
    __syncthreads();

    float base[4][2];
#pragma unroll
    for (int mi = 0; mi < 4; mi++) {
        const int r0 = wm + mi * 16 + (lane >> 2);
        const int r1 = r0 + 8;
        float rm0 = fmaxf(fmaxf(rmaxp[r0], rmaxp[128 + r0]),
                          fmaxf(rmaxp[256 + r0], rmaxp[384 + r0]));
        float rm1 = fmaxf(fmaxf(rmaxp[r1], rmaxp[128 + r1]),
                          fmaxf(rmaxp[256 + r1], rmaxp[384 + r1]));
        base[mi][0] = -diag[r0] - rm0;
        base[mi][1] = -diag[r1] - rm1;
    }

    if (OMODE == 1) {
#pragma unroll
        for (int mi = 0; mi < 4; mi++) {
            const int r0 = wm + mi * 16 + (lane >> 2);
            const size_t o0 = ((size_t)bh * Lc + l0 + r0) * Mc;
            const size_t o1 = ((size_t)bh * Lc + l0 + r0 + 8) * Mc;
            const int c0 = wn + ((lane & 3) << 1);
#pragma unroll
            for (int ni = 0; ni < 8; ni++) {
                int c = c0 + ni * 8;
                float f0 = __expf(acc[mi][ni][0] + base[mi][0]) * 0.0625f;
                float f1 = __expf(acc[mi][ni][1] + base[mi][0]) * 0.0625f;
                float f2 = __expf(acc[mi][ni][2] + base[mi][1]) * 0.0625f;
                float f3 = __expf(acc[mi][ni][3] + base[mi][1]) * 0.0625f;
                bf16 h0,l0b,h1,l1b,h2,l2b,h3,l3b;
                split2(f0, h0, l0b); split2(f1, h1, l1b);
                split2(f2, h2, l2b); split2(f3, h3, l3b);
                *(__nv_bfloat162*)&Fhi[o0 + c] = __halves2bfloat162(h0, h1);
                *(__nv_bfloat162*)&Fhi[o1 + c] = __halves2bfloat162(h2, h3);
                *(__nv_bfloat162*)&Flo[o0 + c] = __halves2bfloat162(l0b, l1b);
                *(__nv_bfloat162*)&Flo[o1 + c] = __halves2bfloat162(l2b, l3b);
            }
        }
    } else {
        const int lr = lane >> 2;
#pragma unroll
        for (int ni = 0; ni < 8; ni++) {
            const int c = wn + ((lane & 3) << 1) + ni * 8;
            float s0 = 0.f, s1 = 0.f;
#pragma unroll
            for (int mi = 0; mi < 4; mi++) {
                const int r0 = wm + mi * 16 + lr;
                float f0 = __expf(acc[mi][ni][0] + base[mi][0]) * 0.0625f;
                float f1 = __expf(acc[mi][ni][1] + base[mi][0]) * 0.0625f;
                float f2 = __expf(acc[mi][ni][2] + base[mi][1]) * 0.0625f;
                float f3 = __expf(acc[mi][ni][3] + base[mi][1]) * 0.0625f;
                s0 += f0 + f2; s1 += f1 + f3;
                const size_t t0 = ((size_t)bh * Mc + c) * Lc + l0;
                const size_t t1 = t0 + Lc;
                bf16 hh, ll;
                split2(f0, hh, ll); Fhi[t0 + r0] = hh;     Flo[t0 + r0] = ll;
                split2(f2, hh, ll); Fhi[t0 + r0 + 8] = hh; Flo[t0 + r0 + 8] = ll;
                split2(f1, hh, ll); Fhi[t1 + r0] = hh;     Flo[t1 + r0] = ll;
                split2(f3, hh, ll); Fhi[t1 + r0 + 8] = hh; Flo[t1 + r0 + 8] = ll;
            }
            atomicAdd(&colsum[c], s0);
            atomicAdd(&colsum[c + 1], s1);
        }
        __syncthreads();
        if (tid < 256) atomicAdd(&ksum[bh * Mc + tid], colsum[tid]);
    }
}

// ============================================================
// kv via mma bf16x3 — fused-pass (R13, unchanged)
// ============================================================
#define KVNITF 16
#define KV_AMS (64 * LDT * 2)
#define KV_BMS (256 * LDT * 2)
#define KV_STAGEF (2 * KV_AMS + 2 * KV_BMS)
#define KV_SMEMF (2 * KV_STAGEF)

__global__ __launch_bounds__(256, 2) void kv_mma_kernel(
    const bf16* __restrict__ vthi, const bf16* __restrict__ vtlo,
    const bf16* __restrict__ kfthi, const bf16* __restrict__ kftlo,
    float* __restrict__ kvtf)
{
    extern __shared__ char ksm[];
    const int bh = blockIdx.y;
    const int l0 = blockIdx.x * 512;
    const int tid = threadIdx.x;
    const int lane = tid & 31, wid = tid >> 5;
    const int wn = wid * 32;

    uint32_t ah_b[2], al_b[2], bh_b[2], bl_b[2];
#pragma unroll
    for (int s = 0; s < 2; s++) {
        uint32_t base = smem_u32(ksm + s * KV_STAGEF);
        ah_b[s] = base;
        al_b[s] = base + KV_AMS;
        bh_b[s] = base + 2 * KV_AMS;
        bl_b[s] = base + 2 * KV_AMS + KV_BMS;
    }

    const int a_row = (lane & 15);
    const int a_col = (lane >> 4) << 3;
    const int b_row = wn + (lane & 7) + ((lane >> 4) << 3);
    const int b_col = ((lane >> 3) & 1) << 3;

    const size_t abase = (size_t)bh * DHc * Lc + l0;
    const size_t bbase = (size_t)bh * Mc * Lc + l0;

    const int ga_row = tid >> 2, ga_c8 = (tid & 3) << 3;

    auto stage = [&](int kt) {
        const int s  = kt & 1;
        const int kk = kt << 5;
        uint32_t asoff = (uint32_t)(ga_row * LDT + ga_c8) * 2;
        const size_t ga = abase + (size_t)ga_row * Lc + kk + ga_c8;
        cp_async16(ah_b[s] + asoff, vthi + ga);
        cp_async16(al_b[s] + asoff, vtlo + ga);
#pragma unroll
        for (int i = 0; i < 4; i++) {
            int row = ga_row + i * 64;
            uint32_t bsoff = (uint32_t)(row * LDT + ga_c8) * 2;
            const size_t gb = bbase + (size_t)row * Lc + kk + ga_c8;
            cp_async16(bh_b[s] + bsoff, kfthi + gb);
            cp_async16(bl_b[s] + bsoff, kftlo + gb);
        }
        CP_COMMIT();
    };

    float acc[4][4][4];
#pragma unroll
    for (int mi = 0; mi < 4; mi++)
#pragma unroll
        for (int ni = 0; ni < 4; ni++)
#pragma unroll
            for (int e = 0; e < 4; e++) acc[mi][ni][e] = 0.f;

    stage(0); stage(1);

    for (int kt = 0; kt < KVNITF; kt++) {
        const int s = kt & 1;
        if (kt + 1 < KVNITF) CP_WAIT(1); else CP_WAIT(0);
        __syncthreads();

#pragma unroll
        for (int k0 = 0; k0 < 32; k0 += 16) {
            uint32_t bh_[2][4], bl_[2][4];
#pragma unroll
            for (int pr = 0; pr < 2; pr++) {
                uint32_t boff = (uint32_t)((b_row + pr * 16) * LDT + k0 + b_col) * 2;
                ldsm_x4(bh_[pr], bh_b[s] + boff);
                ldsm_x4(bl_[pr], bl_b[s] + boff);
            }
            uint32_t a[4][4];
#pragma unroll
            for (int mi = 0; mi < 4; mi++)
                ldsm_x4(a[mi], ah_b[s] +
                        (uint32_t)((a_row + mi * 16) * LDT + k0 + a_col) * 2);
#pragma unroll
            for (int mi = 0; mi < 4; mi++) {
                mma16816(acc[mi][0], a[mi], bh_[0][0], bh_[0][1]);
                mma16816(acc[mi][1], a[mi], bh_[0][2], bh_[0][3]);
                mma16816(acc[mi][2], a[mi], bh_[1][0], bh_[1][1]);
                mma16816(acc[mi][3], a[mi], bh_[1][2], bh_[1][3]);
            }
#pragma unroll
            for (int mi = 0; mi < 4; mi++) {
                mma16816(acc[mi][0], a[mi], bl_[0][0], bl_[0][1]);
                mma16816(acc[mi][1], a[mi], bl_[0][2], bl_[0][3]);
                mma16816(acc[mi][2], a[mi], bl_[1][0], bl_[1][1]);
                mma16816(acc[mi][3], a[mi], bl_[1][2], bl_[1][3]);
            }
#pragma unroll
            for (int mi = 0; mi < 4; mi++)
                ldsm_x4(a[mi], al_b[s] +
                        (uint32_t)((a_row + mi * 16) * LDT + k0 + a_col) * 2);
#pragma unroll
            for (int mi = 0; mi < 4; mi++) {
                mma16816(acc[mi][0], a[mi], bh_[0][0], bh_[0][1]);
                mma16816(acc[mi][1], a[mi], bh_[0][2], bh_[0][3]);
                mma16816(acc[mi][2], a[mi], bh_[1][0], bh_[1][1]);
                mma16816(acc[mi][3], a[mi], bh_[1][2], bh_[1][3]);
            }
        }
        __syncthreads();
        if (kt + 2 < KVNITF) stage(kt + 2);
    }

    const int lr = lane >> 2;
    const int c0 = wn + ((lane & 3) << 1);
    float* dst = kvtf + (size_t)bh * DHc * Mc;
#pragma unroll
    for (int mi = 0; mi < 4; mi++) {
        const int d0 = mi * 16 + lr;
        const int d1 = d0 + 8;
#pragma unroll
        for (int ni = 0; ni < 4; ni++) {
            int c = c0 + ni * 8;
            atomicAdd(&dst[d0 * Mc + c],     acc[mi][ni][0]);
            atomicAdd(&dst[d0 * Mc + c + 1], acc[mi][ni][1]);
            atomicAdd(&dst[d1 * Mc + c],     acc[mi][ni][2]);
            atomicAdd(&dst[d1 * Mc + c + 1], acc[mi][ni][3]);
        }
    }
}

// ============================================================
// kvtf fp32 -> kvthi/kvtlo
// ============================================================
__global__ __launch_bounds__(256) void kvsplit_kernel(
    const float* __restrict__ kvtf, bf16* __restrict__ Thi, bf16* __restrict__ Tlo)
{
    int i = blockIdx.x * 256 + threadIdx.x;
    float v = kvtf[i];
    bf16 h, l; split2(v, h, l);
    Thi[i] = h; Tlo[i] = l;
}

// ============================================================
// attn via mma bf16x3 — fused-pass + FUSED z (denominator in-kernel).
// den[r] = sum_m qf[r,m]*ksum[m] computed on FMA pipe from staged tiles.
// ============================================================
#define ANITF 8
#define ATT_AMS (256 * LDT * 2)
#define ATT_BMS (64 * LDT * 2)
#define ATT_STAGEF (2 * ATT_AMS + 2 * ATT_BMS)
#define ATT_SMEMF (2 * ATT_STAGEF + 512 * 4)   // + ksum_s[256] + zden[256]

__global__ __launch_bounds__(256, 2) void attn_mma_kernel(
    const bf16* __restrict__ qfhi, const bf16* __restrict__ qflo,
    const bf16* __restrict__ kvthi, const bf16* __restrict__ kvtlo,
    const float* __restrict__ ksum,
    bf16* __restrict__ Ohi, bf16* __restrict__ Olo)
{
    extern __shared__ char asm_[];
    const int bh = blockIdx.y;
    const int b = bh >> 4, h = bh & 15;
    const int l0 = blockIdx.x * 256;
    const int tid = threadIdx.x;
    const int lane = tid & 31, wid = tid >> 5;
    const int wm = (wid >> 1) * 64;
    const int wn = (wid & 1) * 32;

    uint32_t ah_b[2], al_b[2], bh_b[2], bl_b[2];
#pragma unroll
    for (int s = 0; s < 2; s++) {
        uint32_t base = smem_u32(asm_ + s * ATT_STAGEF);
        ah_b[s] = base;
        al_b[s] = base + ATT_AMS;
        bh_b[s] = base + 2 * ATT_AMS;
        bl_b[s] = base + 2 * ATT_AMS + ATT_BMS;
    }
    float* ksum_s = (float*)(asm_ + 2 * ATT_STAGEF);   // [256]
    float* zden   = ksum_s + 256;                      // [256]

    const int a_row = wm + (lane & 15);
    const int a_col = (lane >> 4) << 3;
    const int b_row = wn + (lane & 7) + ((lane >> 4) << 3);
    const int b_col = ((lane >> 3) & 1) << 3;

    const size_t qbase = ((size_t)bh * Lc + l0) * Mc;
    const size_t kbase = (size_t)bh * DHc * Mc;

    const int ga_row = tid >> 2, ga_c8 = (tid & 3) << 3;

    // load ksum for this bh (all 256 threads)
    ksum_s[tid] = ksum[bh * Mc + tid];

    auto stage = [&](int kt) {
        const int s  = kt & 1;
        const int kk = kt << 5;
#pragma unroll
        for (int i = 0; i < 4; i++) {
            int row = ga_row + i * 64;
            uint32_t soff = (uint32_t)(row * LDT + ga_c8) * 2;
            const size_t ga = qbase + (size_t)row * Mc + kk + ga_c8;
            cp_async16(ah_b[s] + soff, qfhi + ga);
            cp_async16(al_b[s] + soff, qflo + ga);
        }
        uint32_t bsoff = (uint32_t)(ga_row * LDT + ga_c8) * 2;
        const size_t gb = kbase + (size_t)ga_row * Mc + kk + ga_c8;
        cp_async16(bh_b[s] + bsoff, kvthi + gb);
        cp_async16(bl_b[s] + bsoff, kvtlo + gb);
        CP_COMMIT();
    };

    float acc[4][4][4];
#pragma unroll
    for (int mi = 0; mi < 4; mi++)
#pragma unroll
        for (int ni = 0; ni < 4; ni++)
#pragma unroll
            for (int e = 0; e < 4; e++) acc[mi][ni][e] = 0.f;
    float den = 0.f;

    stage(0); stage(1);

    for (int kt = 0; kt < ANITF; kt++) {
        const int s = kt & 1;
        if (kt + 1 < ANITF) CP_WAIT(1); else CP_WAIT(0);
        __syncthreads();

        // denominator partial for row tid over this k-tile's 32 m-cols
        {
            const bf16* ah_row = (const bf16*)(asm_ + s * ATT_STAGEF) + tid * LDT;
            const bf16* al_row = (const bf16*)(asm_ + s * ATT_STAGEF + ATT_AMS) + tid * LDT;
            const float* ks = ksum_s + (kt << 5);
#pragma unroll
            for (int c2 = 0; c2 < 16; c2++) {
                __nv_bfloat162 hh = *(const __nv_bfloat162*)&ah_row[c2 * 2];
                __nv_bfloat162 ll = *(const __nv_bfloat162*)&al_row[c2 * 2];
                den += (__bfloat162float(hh.x) + __bfloat162float(ll.x)) * ks[c2 * 2];
                den += (__bfloat162float(hh.y) + __bfloat162float(ll.y)) * ks[c2 * 2 + 1];
            }
        }

#pragma unroll
        for (int k0 = 0; k0 < 32; k0 += 16) {
            uint32_t bh_[2][4], bl_[2][4];
#pragma unroll
            for (int pr = 0; pr < 2; pr++) {
                uint32_t boff = (uint32_t)((b_row + pr * 16) * LDT + k0 + b_col) * 2;
                ldsm_x4(bh_[pr], bh_b[s] + boff);
                ldsm_x4(bl_[pr], bl_b[s] + boff);
            }
            uint32_t a[4][4];
#pragma unroll
            for (int mi = 0; mi < 4; mi++)
                ldsm_x4(a[mi], ah_b[s] +
                        (uint32_t)((a_row + mi * 16) * LDT + k0 + a_col) * 2);
#pragma unroll
            for (int mi = 0; mi < 4; mi++) {
                mma16816(acc[mi][0], a[mi], bh_[0][0], bh_[0][1]);
                mma16816(acc[mi][1], a[mi], bh_[0][2], bh_[0][3]);
                mma16816(acc[mi][2], a[mi], bh_[1][0], bh_[1][1]);
                mma16816(acc[mi][3], a[mi], bh_[1][2], bh_[1][3]);
            }
#pragma unroll
            for (int mi = 0; mi < 4; mi++) {
                mma16816(acc[mi][0], a[mi], bl_[0][0], bl_[0][1]);
                mma16816(acc[mi][1], a[mi], bl_[0][2], bl_[0][3]);
                mma16816(acc[mi][2], a[mi], bl_[1][0], bl_[1][1]);
                mma16816(acc[mi][3], a[mi], bl_[1][2], bl_[1][3]);
            }
#pragma unroll
            for (int mi = 0; mi < 4; mi++)
                ldsm_x4(a[mi], al_b[s] +
                        (uint32_t)((a_row + mi * 16) * LDT + k0 + a_col) * 2);
#pragma unroll
            for (int mi = 0; mi < 4; mi++) {
                mma16816(acc[mi][0], a[mi], bh_[0][0], bh_[0][1]);
                mma16816(acc[mi][1], a[mi], bh_[0][2], bh_[0][3]);
                mma16816(acc[mi][2], a[mi], bh_[1][0], bh_[1][1]);
                mma16816(acc[mi][3], a[mi], bh_[1][2], bh_[1][3]);
            }
        }
        __syncthreads();
        if (kt + 2 < ANITF) stage(kt + 2);
    }

    // publish z = 1/(den+eps) per local row
    zden[tid] = 1.0f / (den + 1e-6f);
    __syncthreads();

    const int lr = lane >> 2;
    const int occ0 = wn + ((lane & 3) << 1);
#pragma unroll
    for (int mi = 0; mi < 4; mi++) {
        const int r0 = wm + mi * 16 + lr;
        const int r1 = r0 + 8;
        const float z0 = zden[r0];
        const float z1 = zden[r1];
        const size_t i0 = (size_t)(b * Lc + l0 + r0) * Dc + h * DHc;
        const size_t i1 = (size_t)(b * Lc + l0 + r1) * Dc + h * DHc;
#pragma unroll
        for (int ni = 0; ni < 4; ni++) {
            int c = occ0 + ni * 8;
            bf16 h0,l0b,h1,l1b,h2,l2b,h3,l3b;
            split2(acc[mi][ni][0] * z0, h0, l0b);
            split2(acc[mi][ni][1] * z0, h1, l1b);
            split2(acc[mi][ni][2] * z1, h2, l2b);
            split2(acc[mi][ni][3] * z1, h3, l3b);
            *(__nv_bfloat162*)&Ohi[i0 + c] = __halves2bfloat162(h0, h1);
            *(__nv_bfloat162*)&Ohi[i1 + c] = __halves2bfloat162(h2, h3);
            *(__nv_bfloat162*)&Olo[i0 + c] = __halves2bfloat162(l0b, l1b);
            *(__nv_bfloat162*)&Olo[i1 + c] = __halves2bfloat162(l2b, l3b);
        }
    }
}

// ============================================================
// LayerNorm + duplicate rows
// ============================================================
__global__ __launch_bounds__(256) void ln_dup_kernel(
    const float* __restrict__ y, const float* __restrict__ g,
    const float* __restrict__ beta, float* __restrict__ out)
{
    __shared__ float red[18];
    const int row = blockIdx.x;
    const int b = row >> 12, l = row & 4095;
    const int tid = threadIdx.x;
    const float* yr = y + (size_t)row * Dc;

    float v[4];
    float s = 0.f, ss = 0.f;
#pragma unroll
    for (int i = 0; i < 4; i++) {
        float t = yr[tid + i * 256];
        v[i] = t; s += t; ss += t * t;
    }
#pragma unroll
    for (int off = 16; off; off >>= 1) {
        s  += __shfl_xor_sync(0xffffffffu, s, off);
        ss += __shfl_xor_sync(0xffffffffu, ss, off);
    }
    const int w = tid >> 5, lane = tid & 31;
    if (lane == 0) { red[w] = s; red[8 + w] = ss; }
    __syncthreads();
    if (tid == 0) {
        float ts = 0.f, tss = 0.f;
#pragma unroll
        for (int i = 0; i < 8; i++) { ts += red[i]; tss += red[8 + i]; }
        float mean = ts * (1.0f / 1024.0f);
        float var = tss * (1.0f / 1024.0f) - mean * mean;
        red[16] = mean;
        red[17] = rsqrtf(var + 1e-5f);
    }
    __syncthreads();
    const float mean = red[16], rstd = red[17];
    float* o0 = out + ((size_t)b * 8192 + 2 * (size_t)l) * Dc;
#pragma unroll
    for (int i = 0; i < 4; i++) {
        int c = tid + i * 256;
        float o = (v[i] - mean) * rstd * g[c] + beta[c];
        o0[c] = o;
        o0[Dc + c] = o;
    }
}

// ============================================================
// host launch
// ============================================================
extern "C" void kernel_launch(void* const* d_in, const int* in_sizes, int n_in,
                              void* d_out, int out_size)
{
    const float* x    = (const float*)d_in[0];
    const float* Wq   = (const float*)d_in[1];
    const float* Wk   = (const float*)d_in[2];
    const float* Wv   = (const float*)d_in[3];
    const float* Wo   = (const float*)d_in[4];
    const float* proj = (const float*)d_in[5];
    const float* ln_g = (const float*)d_in[6];
    const float* ln_b = (const float*)d_in[7];
    float* out = (float*)d_out;

    float *v, *kvtf, *ksum, *y;
    bf16 *qfhi, *qflo, *kfthi, *kftlo, *vthi, *vtlo, *kvthi, *kvtlo;
    bf16 *ahi, *alo, *bthi, *btlo, *qhi, *qlo, *khi, *klo, *phi, *plo;
    cudaGetSymbolAddress((void**)&v,     g_v);
    cudaGetSymbolAddress((void**)&qfhi,  g_qfhi);
    cudaGetSymbolAddress((void**)&qflo,  g_qflo);
    cudaGetSymbolAddress((void**)&kfthi, g_kfthi);
    cudaGetSymbolAddress((void**)&kftlo, g_kftlo);
    cudaGetSymbolAddress((void**)&vthi,  g_vthi);
    cudaGetSymbolAddress((void**)&vtlo,  g_vtlo);
    cudaGetSymbolAddress((void**)&kvtf,  g_kvtf);
    cudaGetSymbolAddress((void**)&kvthi, g_kvthi);
    cudaGetSymbolAddress((void**)&kvtlo, g_kvtlo);
    cudaGetSymbolAddress((void**)&ksum,  g_ksum);
    cudaGetSymbolAddress((void**)&y,     g_y);
    cudaGetSymbolAddress((void**)&ahi,   g_ahi);
    cudaGetSymbolAddress((void**)&alo,   g_alo);
    cudaGetSymbolAddress((void**)&bthi,  g_bthi);
    cudaGetSymbolAddress((void**)&btlo,  g_btlo);
    cudaGetSymbolAddress((void**)&qhi,   g_qhi);
    cudaGetSymbolAddress((void**)&qlo,   g_qlo);
    cudaGetSymbolAddress((void**)&khi,   g_khi);
    cudaGetSymbolAddress((void**)&klo,   g_klo);
    cudaGetSymbolAddress((void**)&phi,   g_phi);
    cudaGetSymbolAddress((void**)&plo,   g_plo);

    const float qscale = 0.35355339059327379f;  // 64^-0.25

    cudaFuncSetAttribute(mma_gemm_kernel<0>,
                         cudaFuncAttributeMaxDynamicSharedMemorySize, GEMM_SMEMF);
    cudaFuncSetAttribute(mma_gemm_kernel<1>,
                         cudaFuncAttributeMaxDynamicSharedMemorySize, GEMM_SMEMF);
    cudaFuncSetAttribute(feature_mma_kernel<1>,
                         cudaFuncAttributeMaxDynamicSharedMemorySize, FEAT2_SMEM);
    cudaFuncSetAttribute(feature_mma_kernel<2>,
                         cudaFuncAttributeMaxDynamicSharedMemorySize, FEAT2_SMEM);
    cudaFuncSetAttribute(kv_mma_kernel,
                         cudaFuncAttributeMaxDynamicSharedMemorySize, KV_SMEMF);
    cudaFuncSetAttribute(attn_mma_kernel,
                         cudaFuncAttributeMaxDynamicSharedMemorySize, ATT_SMEMF);

    const int n4 = ROWS * Dc / 4;

    // splits (weights: single fused launch)
    split_kernel<<<n4 / 256, 256>>>(x, ahi, alo, n4);
    split_kernel<<<(Hc * Mc * DHc / 4) / 256, 256>>>(proj, phi, plo, Hc * Mc * DHc / 4);
    tsplit4_kernel<<<dim3(32, 32, 4), dim3(32, 8)>>>(Wq, Wk, Wv, Wo, bthi, btlo);

    // zero accumulators (consumed by feature<2> and kv_mma)
    cudaMemsetAsync(ksum, 0, (size_t)BHc * Mc * sizeof(float), 0);
    cudaMemsetAsync(kvtf, 0, (size_t)BHc * DHc * Mc * sizeof(float), 0);

    // fused QKV GEMM (V -> fp32)
    mma_gemm_kernel<0><<<dim3(24, 64), 256, GEMM_SMEMF>>>(
        ahi, alo, bthi, btlo, v, qhi, qlo, khi, klo, qscale);

    // features: Q -> qf hi/lo [l][m]; K -> kf_t hi/lo [m][l] + ksum
    feature_mma_kernel<1><<<dim3(Lc / 128, BHc), 256, FEAT2_SMEM>>>(
        qhi, qlo, phi, plo, qfhi, qflo, nullptr);
    feature_mma_kernel<2><<<dim3(Lc / 128, BHc), 256, FEAT2_SMEM>>>(
        khi, klo, phi, plo, kfthi, kftlo, ksum);

    // v transpose+split, then kv via tensor cores
    vt_kernel<<<dim3(Lc / 32, BHc), 256>>>(v, vthi, vtlo);
    kv_mma_kernel<<<dim3(8, BHc), 256, KV_SMEMF>>>(vthi, vtlo, kfthi, kftlo, kvtf);
    kvsplit_kernel<<<(BHc * DHc * Mc) / 256, 256>>>(kvtf, kvthi, kvtlo);

    // attn (z fused in-kernel) -> hi/lo directly into O-GEMM A buffers
    attn_mma_kernel<<<dim3(Lc / 256, BHc), 256, ATT_SMEMF>>>(
        qfhi, qflo, kvthi, kvtlo, ksum, ahi, alo);

    // O projection + exact GELU (weights at offset 3)
    mma_gemm_kernel<1><<<dim3(8, 64), 256, GEMM_SMEMF>>>(
        ahi, alo, bthi + (size_t)3 * Dc * Dc, btlo + (size_t)3 * Dc * Dc,
        y, nullptr, nullptr, nullptr, nullptr, 1.0f);

    ln_dup_kernel<<<ROWS, 256>>>(y, ln_g, ln_b, out);
}

// round 15
// speedup vs baseline: 1.0396x; 1.0058x over previous
#include <cuda_runtime.h>
#include <cuda_bf16.h>
#include <math.h>
#include <stdint.h>

// Shapes (fixed)
#define Bc   2
#define Lc   4096
#define Dc   1024
#define Hc   16
#define DHc  64
#define Mc   256
#define BHc  32
#define ROWS 8192   // B*L

typedef __nv_bfloat16 bf16;

// -------- scratch (device globals; no allocations allowed) --------
__device__ float g_v    [(size_t)ROWS * Dc];
__device__ bf16  g_qfhi [(size_t)BHc * Lc * Mc];
__device__ bf16  g_qflo [(size_t)BHc * Lc * Mc];
__device__ bf16  g_kfthi[(size_t)BHc * Mc * Lc];
__device__ bf16  g_kftlo[(size_t)BHc * Mc * Lc];
__device__ bf16  g_vthi [(size_t)BHc * DHc * Lc];
__device__ bf16  g_vtlo [(size_t)BHc * DHc * Lc];
__device__ float g_kvtf [(size_t)BHc * DHc * Mc];
__device__ bf16  g_kvthi[(size_t)BHc * DHc * Mc];
__device__ bf16  g_kvtlo[(size_t)BHc * DHc * Mc];
__device__ float g_ksum [(size_t)BHc * Mc];
__device__ float g_y    [(size_t)ROWS * Dc];
__device__ bf16  g_ahi  [(size_t)ROWS * Dc];
__device__ bf16  g_alo  [(size_t)ROWS * Dc];
__device__ bf16  g_bthi [(size_t)4 * Dc * Dc];
__device__ bf16  g_btlo [(size_t)4 * Dc * Dc];
__device__ bf16  g_qhi  [(size_t)ROWS * Dc];
__device__ bf16  g_qlo  [(size_t)ROWS * Dc];
__device__ bf16  g_khi  [(size_t)ROWS * Dc];
__device__ bf16  g_klo  [(size_t)ROWS * Dc];
__device__ bf16  g_phi  [(size_t)Hc * Mc * DHc];
__device__ bf16  g_plo  [(size_t)Hc * Mc * DHc];

// ================= baseline-PTX tensor-core helpers (sm_80+) ==========
__device__ __forceinline__ uint32_t smem_u32(const void* p) {
    uint32_t a;
    asm("{ .reg .u64 t; cvta.to.shared.u64 t, %1; cvt.u32.u64 %0, t; }"
        : "=r"(a) : "l"(p));
    return a;
}
__device__ __forceinline__ void cp_async16(uint32_t saddr, const void* g) {
    asm volatile("cp.async.cg.shared.global [%0], [%1], 16;"
                 :: "r"(saddr), "l"(g) : "memory");
}
#define CP_COMMIT() asm volatile("cp.async.commit_group;" ::: "memory")
#define CP_WAIT(n)  asm volatile("cp.async.wait_group %0;" :: "n"(n) : "memory")

__device__ __forceinline__ void ldsm_x4(uint32_t r[4], uint32_t addr) {
    asm volatile("ldmatrix.sync.aligned.m8n8.x4.shared.b16 {%0,%1,%2,%3}, [%4];"
                 : "=r"(r[0]), "=r"(r[1]), "=r"(r[2]), "=r"(r[3]) : "r"(addr));
}
__device__ __forceinline__ void mma16816(float c[4], const uint32_t a[4],
                                         uint32_t b0, uint32_t b1) {
    asm volatile(
        "mma.sync.aligned.m16n8k16.row.col.f32.bf16.bf16.f32 "
        "{%0,%1,%2,%3}, {%4,%5,%6,%7}, {%8,%9}, {%0,%1,%2,%3};"
        : "+f"(c[0]), "+f"(c[1]), "+f"(c[2]), "+f"(c[3])
        : "r"(a[0]), "r"(a[1]), "r"(a[2]), "r"(a[3]), "r"(b0), "r"(b1));
}
__device__ __forceinline__ void split2(float v, bf16& h, bf16& l) {
    h = __float2bfloat16_rn(v);
    l = __float2bfloat16_rn(v - __bfloat162float(h));
}

// ============================================================
// PREP: x-split + proj-split + zero(ksum) + zero(kvtf) in ONE launch
// blocks: [0,8192) x | [8192,8448) proj | [8448,8456) ksum | [8456,8968) kvtf
// ============================================================
#define XN4   (ROWS * Dc / 4)              // 2,097,152 -> 8192 blocks
#define PN4   (Hc * Mc * DHc / 4)          // 65,536    -> 256 blocks
#define KSN4  (BHc * Mc / 4)               // 2,048     -> 8 blocks
#define KVN4  (BHc * DHc * Mc / 4)         // 131,072   -> 512 blocks
#define PREP_BLOCKS (8192 + 256 + 8 + 512)

__global__ __launch_bounds__(256) void prep_kernel(
    const float* __restrict__ x, bf16* __restrict__ ahi, bf16* __restrict__ alo,
    const float* __restrict__ proj, bf16* __restrict__ phi, bf16* __restrict__ plo,
    float* __restrict__ ksum, float* __restrict__ kvtf)
{
    int bid = blockIdx.x;
    if (bid < 8192 + 256) {
        const float* in = (bid < 8192) ? x : proj;
        bf16* hi = (bid < 8192) ? ahi : phi;
        bf16* lo = (bid < 8192) ? alo : plo;
        int base = (bid < 8192) ? bid : (bid - 8192);
        int i = base * 256 + threadIdx.x;
        float4 v = ((const float4*)in)[i];
        bf16 h0, h1, h2, h3, l0, l1, l2, l3;
        split2(v.x, h0, l0); split2(v.y, h1, l1);
        split2(v.z, h2, l2); split2(v.w, h3, l3);
        ((__nv_bfloat162*)hi)[2*i]   = __halves2bfloat162(h0, h1);
        ((__nv_bfloat162*)hi)[2*i+1] = __halves2bfloat162(h2, h3);
        ((__nv_bfloat162*)lo)[2*i]   = __halves2bfloat162(l0, l1);
        ((__nv_bfloat162*)lo)[2*i+1] = __halves2bfloat162(l2, l3);
    } else if (bid < 8192 + 256 + 8) {
        int i = (bid - 8448) * 256 + threadIdx.x;
        ((float4*)ksum)[i] = make_float4(0.f, 0.f, 0.f, 0.f);
    } else {
        int i = (bid - 8456) * 256 + threadIdx.x;
        ((float4*)kvtf)[i] = make_float4(0.f, 0.f, 0.f, 0.f);
    }
}

// ============================================================
// 4 weights [K,N] -> W^T [N,K] bf16 hi/lo, single launch
// ============================================================
__global__ void tsplit4_kernel(
    const float* __restrict__ W0, const float* __restrict__ W1,
    const float* __restrict__ W2, const float* __restrict__ W3,
    bf16* __restrict__ Thi, bf16* __restrict__ Tlo)
{
    __shared__ float t[32][33];
    const float* W = (blockIdx.z == 0) ? W0 : (blockIdx.z == 1) ? W1
                    : (blockIdx.z == 2) ? W2 : W3;
    bf16* th = Thi + (size_t)blockIdx.z * Dc * Dc;
    bf16* tl = Tlo + (size_t)blockIdx.z * Dc * Dc;
    int bx = blockIdx.x * 32, by = blockIdx.y * 32;
    int tx = threadIdx.x, ty = threadIdx.y;   // 32 x 8
#pragma unroll
    for (int i = 0; i < 32; i += 8)
        t[ty + i][tx] = W[(size_t)(by + ty + i) * Dc + bx + tx];
    __syncthreads();
#pragma unroll
    for (int i = 0; i < 32; i += 8) {
        float v = t[tx][ty + i];
        int orow = bx + ty + i, ocol = by + tx;
        bf16 h, l; split2(v, h, l);
        th[(size_t)orow * Dc + ocol] = h;
        tl[(size_t)orow * Dc + ocol] = l;
    }
}

// ============================================================
// v [b*L][D] fp32 -> v_t [bh][d][l] bf16 hi/lo
// ============================================================
__global__ __launch_bounds__(256) void vt_kernel(
    const float* __restrict__ v, bf16* __restrict__ Thi, bf16* __restrict__ Tlo)
{
    __shared__ float t[64][33];
    const int bh = blockIdx.y;
    const int b = bh >> 4, h = bh & 15;
    const int l0 = blockIdx.x * 32;
    const int tid = threadIdx.x;
#pragma unroll
    for (int i = 0; i < 8; i++) {
        int s = tid + i * 256;
        int r = s >> 6, c = s & 63;
        t[c][r & 31] = v[(size_t)(b * Lc + l0 + r) * Dc + h * DHc + c];
    }
    __syncthreads();
#pragma unroll
    for (int i = 0; i < 8; i++) {
        int s = tid + i * 256;
        int d = s >> 5, c = s & 31;
        float val = t[d][c];
        bf16 hh, ll; split2(val, hh, ll);
        size_t o = ((size_t)bh * DHc + d) * Lc + l0 + c;
        Thi[o] = hh; Tlo[o] = ll;
    }
}

// ============================================================
// bf16x3 FUSED-PASS tensor-core GEMM — interleaved ldsm/mma schedule.
// MODE 0 (fused QKV), MODE 1 (single + exact GELU). 2 CTAs/SM.
// ============================================================
#define LDT 40
#define GNITF 32
#define GEMM_MSTG (128 * LDT * 2)
#define GEMM_STAGE (4 * GEMM_MSTG)
#define GEMM_SMEMF (2 * GEMM_STAGE)

template<int MODE>
__global__ __launch_bounds__(256, 2) void mma_gemm_kernel(
    const bf16* __restrict__ Ahi, const bf16* __restrict__ Alo,
    const bf16* __restrict__ Bhi, const bf16* __restrict__ Blo,
    float* __restrict__ Cv,
    bf16* __restrict__ Qhi, bf16* __restrict__ Qlo,
    bf16* __restrict__ Khi, bf16* __restrict__ Klo,
    float qalpha)
{
    extern __shared__ char gsm[];
    const int tid  = threadIdx.x;
    const int lane = tid & 31, wid = tid >> 5;
    const int bm = blockIdx.y * 128;
    const int bn = blockIdx.x * 128;
    const int wm = (wid >> 2) * 64;
    const int wn = (wid & 3) * 32;

    uint32_t ah_b[2], al_b[2], bh_b[2], bl_b[2];
#pragma unroll
    for (int s = 0; s < 2; s++) {
        uint32_t base = smem_u32(gsm + s * GEMM_STAGE);
        ah_b[s] = base;
        al_b[s] = base + GEMM_MSTG;
        bh_b[s] = base + 2 * GEMM_MSTG;
        bl_b[s] = base + 3 * GEMM_MSTG;
    }

    const int a_row = wm + (lane & 15);
    const int a_col = (lane >> 4) << 3;
    const int b_row = wn + (lane & 7) + ((lane >> 4) << 3);
    const int b_col = ((lane >> 3) & 1) << 3;

    const int g_row0 = tid >> 2;
    const int g_c8   = (tid & 3) << 3;

    auto stage = [&](int kt) {
        const int s  = kt & 1;
        const int kk = kt << 5;
#pragma unroll
        for (int i = 0; i < 2; i++) {
            int row = g_row0 + i * 64;
            uint32_t soff = (uint32_t)(row * LDT + g_c8) * 2;
            const size_t ga = (size_t)(bm + row) * Dc + kk + g_c8;
            const size_t gb = (size_t)(bn + row) * Dc + kk + g_c8;
            cp_async16(ah_b[s] + soff, Ahi + ga);
            cp_async16(al_b[s] + soff, Alo + ga);
            cp_async16(bh_b[s] + soff, Bhi + gb);
            cp_async16(bl_b[s] + soff, Blo + gb);
        }
        CP_COMMIT();
    };

    float acc[4][4][4];
#pragma unroll
    for (int mi = 0; mi < 4; mi++)
#pragma unroll
        for (int ni = 0; ni < 4; ni++)
#pragma unroll
            for (int e = 0; e < 4; e++) acc[mi][ni][e] = 0.f;

    stage(0); stage(1);

    for (int kt = 0; kt < GNITF; kt++) {
        const int s = kt & 1;
        if (kt + 1 < GNITF) CP_WAIT(1); else CP_WAIT(0);
        __syncthreads();

#pragma unroll
        for (int k0 = 0; k0 < 32; k0 += 16) {
            uint32_t bfr[2][4];   // shared b-frag buffer (bh then bl)
            uint32_t a[4][4];
            // ldsm bh + ah, then group1 (ah*bh)
#pragma unroll
            for (int pr = 0; pr < 2; pr++)
                ldsm_x4(bfr[pr], bh_b[s] +
                        (uint32_t)((b_row + pr * 16) * LDT + k0 + b_col) * 2);
#pragma unroll
            for (int mi = 0; mi < 4; mi++)
                ldsm_x4(a[mi], ah_b[s] +
                        (uint32_t)((a_row + mi * 16) * LDT + k0 + a_col) * 2);
#pragma unroll
            for (int mi = 0; mi < 4; mi++) {
                mma16816(acc[mi][0], a[mi], bfr[0][0], bfr[0][1]);
                mma16816(acc[mi][1], a[mi], bfr[0][2], bfr[0][3]);
                mma16816(acc[mi][2], a[mi], bfr[1][0], bfr[1][1]);
                mma16816(acc[mi][3], a[mi], bfr[1][2], bfr[1][3]);
            }
            // ldsm bl (reuse separate regs) interleaved, then group2 (ah*bl)
            uint32_t blr[2][4];
#pragma unroll
            for (int pr = 0; pr < 2; pr++)
                ldsm_x4(blr[pr], bl_b[s] +
                        (uint32_t)((b_row + pr * 16) * LDT + k0 + b_col) * 2);
#pragma unroll
            for (int mi = 0; mi < 4; mi++) {
                mma16816(acc[mi][0], a[mi], blr[0][0], blr[0][1]);
                mma16816(acc[mi][1], a[mi], blr[0][2], blr[0][3]);
                mma16816(acc[mi][2], a[mi], blr[1][0], blr[1][1]);
                mma16816(acc[mi][3], a[mi], blr[1][2], blr[1][3]);
            }
            // ldsm al over a, then group3 (al*bh)
#pragma unroll
            for (int mi = 0; mi < 4; mi++)
                ldsm_x4(a[mi], al_b[s] +
                        (uint32_t)((a_row + mi * 16) * LDT + k0 + a_col) * 2);
#pragma unroll
            for (int mi = 0; mi < 4; mi++) {
                mma16816(acc[mi][0], a[mi], bfr[0][0], bfr[0][1]);
                mma16816(acc[mi][1], a[mi], bfr[0][2], bfr[0][3]);
                mma16816(acc[mi][2], a[mi], bfr[1][0], bfr[1][1]);
                mma16816(acc[mi][3], a[mi], bfr[1][2], bfr[1][3]);
            }
        }
        __syncthreads();
        if (kt + 2 < GNITF) stage(kt + 2);
    }

    const int orow = bm + wm + (lane >> 2);
    const int occ0 = wn + ((lane & 3) << 1);

    if (MODE == 0) {
        const int which = bn >> 10;        // 0 q, 1 k, 2 v
        const int bnl = bn & 1023;
        if (which < 2) {
            bf16* Oh = which ? Khi : Qhi;
            bf16* Ol = which ? Klo : Qlo;
#pragma unroll
            for (int mi = 0; mi < 4; mi++)
#pragma unroll
                for (int ni = 0; ni < 4; ni++) {
                    const size_t i0 = (size_t)(orow + mi * 16) * Dc + bnl + occ0 + ni * 8;
                    const size_t i1 = (size_t)(orow + mi * 16 + 8) * Dc + bnl + occ0 + ni * 8;
                    bf16 h0,l0,h1,l1,h2,l2,h3,l3;
                    split2(acc[mi][ni][0] * qalpha, h0, l0);
                    split2(acc[mi][ni][1] * qalpha, h1, l1);
                    split2(acc[mi][ni][2] * qalpha, h2, l2);
                    split2(acc[mi][ni][3] * qalpha, h3, l3);
                    *(__nv_bfloat162*)&Oh[i0] = __halves2bfloat162(h0, h1);
                    *(__nv_bfloat162*)&Oh[i1] = __halves2bfloat162(h2, h3);
                    *(__nv_bfloat162*)&Ol[i0] = __halves2bfloat162(l0, l1);
                    *(__nv_bfloat162*)&Ol[i1] = __halves2bfloat162(l2, l3);
                }
        } else {
#pragma unroll
            for (int mi = 0; mi < 4; mi++)
#pragma unroll
                for (int ni = 0; ni < 4; ni++) {
                    const size_t i0 = (size_t)(orow + mi * 16) * Dc + bnl + occ0 + ni * 8;
                    const size_t i1 = (size_t)(orow + mi * 16 + 8) * Dc + bnl + occ0 + ni * 8;
                    *(float2*)&Cv[i0] = make_float2(acc[mi][ni][0], acc[mi][ni][1]);
                    *(float2*)&Cv[i1] = make_float2(acc[mi][ni][2], acc[mi][ni][3]);
                }
        }
    } else {
#pragma unroll
        for (int mi = 0; mi < 4; mi++)
#pragma unroll
            for (int ni = 0; ni < 4; ni++) {
                float v0 = acc[mi][ni][0], v1 = acc[mi][ni][1];
                float v2 = acc[mi][ni][2], v3 = acc[mi][ni][3];
                v0 = 0.5f * v0 * (1.f + erff(v0 * 0.70710678118654752f));
                v1 = 0.5f * v1 * (1.f + erff(v1 * 0.70710678118654752f));
                v2 = 0.5f * v2 * (1.f + erff(v2 * 0.70710678118654752f));
                v3 = 0.5f * v3 * (1.f + erff(v3 * 0.70710678118654752f));
                const size_t i0 = (size_t)(orow + mi * 16) * Dc + bn + occ0 + ni * 8;
                const size_t i1 = (size_t)(orow + mi * 16 + 8) * Dc + bn + occ0 + ni * 8;
                *(float2*)&Cv[i0] = make_float2(v0, v1);
                *(float2*)&Cv[i1] = make_float2(v2, v3);
            }
    }
}

// ============================================================
// FAVOR+ feature via mma.sync bf16x3 — fused passes (unchanged)
// ============================================================
#define FLDK 72
#define FEAT2_SMEM ((128 + 128 + 256 + 256) * FLDK * 2 + 128 * 4 + 4 * 128 * 4 + 256 * 4)

template<int OMODE>
__global__ __launch_bounds__(256) void feature_mma_kernel(
    const bf16* __restrict__ Uhi, const bf16* __restrict__ Ulo,
    const bf16* __restrict__ Phi, const bf16* __restrict__ Plo,
    bf16* __restrict__ Fhi, bf16* __restrict__ Flo,
    float* __restrict__ ksum)
{
    extern __shared__ char fsm[];
    bf16* us_h = (bf16*)fsm;
    bf16* us_l = us_h + 128 * FLDK;
    bf16* ps_h = us_l + 128 * FLDK;
    bf16* ps_l = ps_h + 256 * FLDK;
    float* diag   = (float*)(ps_l + 256 * FLDK);
    float* rmaxp  = diag + 128;
    float* colsum = rmaxp + 4 * 128;

    const int bh = blockIdx.y;
    const int b = bh >> 4, h = bh & 15;
    const int l0 = blockIdx.x * 128;
    const int tid = threadIdx.x;
    const int lane = tid & 31, wid = tid >> 5;

#pragma unroll
    for (int i = 0; i < 4; i++) {
        int s = tid + i * 256;
        int r = s >> 3, c8 = (s & 7) << 3;
        size_t gi = (size_t)(b * Lc + l0 + r) * Dc + h * DHc + c8;
        *(uint4*)&us_h[r * FLDK + c8] = *(const uint4*)&Uhi[gi];
        *(uint4*)&us_l[r * FLDK + c8] = *(const uint4*)&Ulo[gi];
    }
#pragma unroll
    for (int i = 0; i < 8; i++) {
        int s = tid + i * 256;
        int r = s >> 3, c8 = (s & 7) << 3;
        size_t gi = (size_t)(h * Mc + r) * DHc + c8;
        *(uint4*)&ps_h[r * FLDK + c8] = *(const uint4*)&Phi[gi];
        *(uint4*)&ps_l[r * FLDK + c8] = *(const uint4*)&Plo[gi];
    }
    __syncthreads();

    if (tid < 128) {
        float s = 0.f;
#pragma unroll
        for (int d2 = 0; d2 < 32; d2++) {
            __nv_bfloat162 hh = *(__nv_bfloat162*)&us_h[tid * FLDK + d2 * 2];
            __nv_bfloat162 ll = *(__nv_bfloat162*)&us_l[tid * FLDK + d2 * 2];
            float u0 = __bfloat162float(hh.x) + __bfloat162float(ll.x);
            float u1 = __bfloat162float(hh.y) + __bfloat162float(ll.y);
            s += u0 * u0 + u1 * u1;
        }
        diag[tid] = 0.5f * s;
    }

    const int wm = (wid >> 2) * 64;
    const int wn = (wid & 3) * 64;
    const int a_row = wm + (lane & 15);
    const int a_col = (lane >> 4) << 3;
    const int b_row = wn + (lane & 7) + ((lane >> 4) << 3);
    const int b_col = ((lane >> 3) & 1) << 3;

    float acc[4][8][4];
#pragma unroll
    for (int mi = 0; mi < 4; mi++)
#pragma unroll
        for (int ni = 0; ni < 8; ni++)
#pragma unroll
            for (int e = 0; e < 4; e++) acc[mi][ni][e] = 0.f;

    const uint32_t ush = smem_u32(us_h), usl = smem_u32(us_l);
    const uint32_t psh = smem_u32(ps_h), psl = smem_u32(ps_l);
    __syncthreads();

#pragma unroll
    for (int k0 = 0; k0 < 64; k0 += 16) {
        uint32_t ah[4][4], al[4][4], bfr[4][4];
#pragma unroll
        for (int mi = 0; mi < 4; mi++) {
            uint32_t aoff = (uint32_t)((a_row + mi * 16) * FLDK + k0 + a_col) * 2;
            ldsm_x4(ah[mi], ush + aoff);
            ldsm_x4(al[mi], usl + aoff);
        }
#pragma unroll
        for (int pr = 0; pr < 4; pr++)
            ldsm_x4(bfr[pr], psh + (uint32_t)((b_row + pr * 16) * FLDK + k0 + b_col) * 2);
#pragma unroll
        for (int mi = 0; mi < 4; mi++)
#pragma unroll
            for (int pr = 0; pr < 4; pr++) {
                mma16816(acc[mi][2 * pr],     ah[mi], bfr[pr][0], bfr[pr][1]);
                mma16816(acc[mi][2 * pr + 1], ah[mi], bfr[pr][2], bfr[pr][3]);
            }
#pragma unroll
        for (int mi = 0; mi < 4; mi++)
#pragma unroll
            for (int pr = 0; pr < 4; pr++) {
                mma16816(acc[mi][2 * pr],     al[mi], bfr[pr][0], bfr[pr][1]);
                mma16816(acc[mi][2 * pr + 1], al[mi], bfr[pr][2], bfr[pr][3]);
            }
#pragma unroll
        for (int pr = 0; pr < 4; pr++)
            ldsm_x4(bfr[pr], psl + (uint32_t)((b_row + pr * 16) * FLDK + k0 + b_col) * 2);
#pragma unroll
        for (int mi = 0; mi < 4; mi++)
#pragma unroll
            for (int pr = 0; pr < 4; pr++) {
                mma16816(acc[mi][2 * pr],     ah[mi], bfr[pr][0], bfr[pr][1]);
                mma16816(acc[mi][2 * pr + 1], ah[mi], bfr[pr][2], bfr[pr][3]);
            }
    }

    float tmax[4][2];
#pragma unroll
    for (int mi = 0; mi < 4; mi++) {
        float m0 = -1e30f, m1 = -1e30f;
#pragma unroll
        for (int ni = 0; ni < 8; ni++) {
            m0 = fmaxf(m0, fmaxf(acc[mi][ni][0], acc[mi][ni][1]));
            m1 = fmaxf(m1, fmaxf(acc[mi][ni][2], acc[mi][ni][3]));
        }
#pragma unroll
        for (int off = 1; off <= 2; off <<= 1) {
            m0 = fmaxf(m0, __shfl_xor_sync(0xffffffffu, m0, off));
            m1 = fmaxf(m1, __shfl_xor_sync(0xffffffffu, m1, off));
        }
        tmax[mi][0] = m0; tmax[mi][1] = m1;
    }
    if ((lane & 3) == 0) {
        const int slab = wid & 3;
#pragma unroll
        for (int mi = 0; mi < 4; mi++) {
            int r = wm + mi * 16 + (lane >> 2);
            rmaxp[slab * 128 + r]     = tmax[mi][0];
            rmaxp[slab * 128 + r + 8] = tmax[mi][1];
        }
    }
    if (OMODE == 2 && tid < 256) colsum[tid] = 0.f;
    __syncthreads();

    float base[4][2];
#pragma unroll
    for (int mi = 0; mi < 4; mi++) {
        const int r0 = wm + mi * 16 + (lane >> 2);
        const int r1 = r0 + 8;
        float rm0 = fmaxf(fmaxf(rmaxp[r0], rmaxp[128 + r0]),
                          fmaxf(rmaxp[256 + r0], rmaxp[384 + r0]));
        float rm1 = fmaxf(fmaxf(rmaxp[r1], rmaxp[128 + r1]),
                          fmaxf(rmaxp[256 + r1], rmaxp[384 + r1]));
        base[mi][0] = -diag[r0] - rm0;
        base[mi][1] = -diag[r1] - rm1;
    }

    if (OMODE == 1) {
#pragma unroll
        for (int mi = 0; mi < 4; mi++) {
            const int r0 = wm + mi * 16 + (lane >> 2);
            const size_t o0 = ((size_t)bh * Lc + l0 + r0) * Mc;
            const size_t o1 = ((size_t)bh * Lc + l0 + r0 + 8) * Mc;
            const int c0 = wn + ((lane & 3) << 1);
#pragma unroll
            for (int ni = 0; ni < 8; ni++) {
                int c = c0 + ni * 8;
                float f0 = __expf(acc[mi][ni][0] + base[mi][0]) * 0.0625f;
                float f1 = __expf(acc[mi][ni][1] + base[mi][0]) * 0.0625f;
                float f2 = __expf(acc[mi][ni][2] + base[mi][1]) * 0.0625f;
                float f3 = __expf(acc[mi][ni][3] + base[mi][1]) * 0.0625f;
                bf16 h0,l0b,h1,l1b,h2,l2b,h3,l3b;
                split2(f0, h0, l0b); split2(f1, h1, l1b);
                split2(f2, h2, l2b); split2(f3, h3, l3b);
                *(__nv_bfloat162*)&Fhi[o0 + c] = __halves2bfloat162(h0, h1);
                *(__nv_bfloat162*)&Fhi[o1 + c] = __halves2bfloat162(h2, h3);
                *(__nv_bfloat162*)&Flo[o0 + c] = __halves2bfloat162(l0b, l1b);
                *(__nv_bfloat162*)&Flo[o1 + c] = __halves2bfloat162(l2b, l3b);
            }
        }
    } else {
        const int lr = lane >> 2;
#pragma unroll
        for (int ni = 0; ni < 8; ni++) {
            const int c = wn + ((lane & 3) << 1) + ni * 8;
            float s0 = 0.f, s1 = 0.f;
#pragma unroll
            for (int mi = 0; mi < 4; mi++) {
                const int r0 = wm + mi * 16 + lr;
                float f0 = __expf(acc[mi][ni][0] + base[mi][0]) * 0.0625f;
                float f1 = __expf(acc[mi][ni][1] + base[mi][0]) * 0.0625f;
                float f2 = __expf(acc[mi][ni][2] + base[mi][1]) * 0.0625f;
                float f3 = __expf(acc[mi][ni][3] + base[mi][1]) * 0.0625f;
                s0 += f0 + f2; s1 += f1 + f3;
                const size_t t0 = ((size_t)bh * Mc + c) * Lc + l0;
                const size_t t1 = t0 + Lc;
                bf16 hh, ll;
                split2(f0, hh, ll); Fhi[t0 + r0] = hh;     Flo[t0 + r0] = ll;
                split2(f2, hh, ll); Fhi[t0 + r0 + 8] = hh; Flo[t0 + r0 + 8] = ll;
                split2(f1, hh, ll); Fhi[t1 + r0] = hh;     Flo[t1 + r0] = ll;
                split2(f3, hh, ll); Fhi[t1 + r0 + 8] = hh; Flo[t1 + r0 + 8] = ll;
            }
            atomicAdd(&colsum[c], s0);
            atomicAdd(&colsum[c + 1], s1);
        }
        __syncthreads();
        if (tid < 256) atomicAdd(&ksum[bh * Mc + tid], colsum[tid]);
    }
}

// ============================================================
// kv via mma bf16x3 — fused-pass (unchanged)
// ============================================================
#define KVNITF 16
#define KV_AMS (64 * LDT * 2)
#define KV_BMS (256 * LDT * 2)
#define KV_STAGEF (2 * KV_AMS + 2 * KV_BMS)
#define KV_SMEMF (2 * KV_STAGEF)

__global__ __launch_bounds__(256, 2) void kv_mma_kernel(
    const bf16* __restrict__ vthi, const bf16* __restrict__ vtlo,
    const bf16* __restrict__ kfthi, const bf16* __restrict__ kftlo,
    float* __restrict__ kvtf)
{
    extern __shared__ char ksm[];
    const int bh = blockIdx.y;
    const int l0 = blockIdx.x * 512;
    const int tid = threadIdx.x;
    const int lane = tid & 31, wid = tid >> 5;
    const int wn = wid * 32;

    uint32_t ah_b[2], al_b[2], bh_b[2], bl_b[2];
#pragma unroll
    for (int s = 0; s < 2; s++) {
        uint32_t base = smem_u32(ksm + s * KV_STAGEF);
        ah_b[s] = base;
        al_b[s] = base + KV_AMS;
        bh_b[s] = base + 2 * KV_AMS;
        bl_b[s] = base + 2 * KV_AMS + KV_BMS;
    }

    const int a_row = (lane & 15);
    const int a_col = (lane >> 4) << 3;
    const int b_row = wn + (lane & 7) + ((lane >> 4) << 3);
    const int b_col = ((lane >> 3) & 1) << 3;

    const size_t abase = (size_t)bh * DHc * Lc + l0;
    const size_t bbase = (size_t)bh * Mc * Lc + l0;

    const int ga_row = tid >> 2, ga_c8 = (tid & 3) << 3;

    auto stage = [&](int kt) {
        const int s  = kt & 1;
        const int kk = kt << 5;
        uint32_t asoff = (uint32_t)(ga_row * LDT + ga_c8) * 2;
        const size_t ga = abase + (size_t)ga_row * Lc + kk + ga_c8;
        cp_async16(ah_b[s] + asoff, vthi + ga);
        cp_async16(al_b[s] + asoff, vtlo + ga);
#pragma unroll
        for (int i = 0; i < 4; i++) {
            int row = ga_row + i * 64;
            uint32_t bsoff = (uint32_t)(row * LDT + ga_c8) * 2;
            const size_t gb = bbase + (size_t)row * Lc + kk + ga_c8;
            cp_async16(bh_b[s] + bsoff, kfthi + gb);
            cp_async16(bl_b[s] + bsoff, kftlo + gb);
        }
        CP_COMMIT();
    };

    float acc[4][4][4];
#pragma unroll
    for (int mi = 0; mi < 4; mi++)
#pragma unroll
        for (int ni = 0; ni < 4; ni++)
#pragma unroll
            for (int e = 0; e < 4; e++) acc[mi][ni][e] = 0.f;

    stage(0); stage(1);

    for (int kt = 0; kt < KVNITF; kt++) {
        const int s = kt & 1;
        if (kt + 1 < KVNITF) CP_WAIT(1); else CP_WAIT(0);
        __syncthreads();

#pragma unroll
        for (int k0 = 0; k0 < 32; k0 += 16) {
            uint32_t bh_[2][4], bl_[2][4];
#pragma unroll
            for (int pr = 0; pr < 2; pr++) {
                uint32_t boff = (uint32_t)((b_row + pr * 16) * LDT + k0 + b_col) * 2;
                ldsm_x4(bh_[pr], bh_b[s] + boff);
                ldsm_x4(bl_[pr], bl_b[s] + boff);
            }
            uint32_t a[4][4];
#pragma unroll
            for (int mi = 0; mi < 4; mi++)
                ldsm_x4(a[mi], ah_b[s] +
                        (uint32_t)((a_row + mi * 16) * LDT + k0 + a_col) * 2);
#pragma unroll
            for (int mi = 0; mi < 4; mi++) {
                mma16816(acc[mi][0], a[mi], bh_[0][0], bh_[0][1]);
                mma16816(acc[mi][1], a[mi], bh_[0][2], bh_[0][3]);
                mma16816(acc[mi][2], a[mi], bh_[1][0], bh_[1][1]);
                mma16816(acc[mi][3], a[mi], bh_[1][2], bh_[1][3]);
            }
#pragma unroll
            for (int mi = 0; mi < 4; mi++) {
                mma16816(acc[mi][0], a[mi], bl_[0][0], bl_[0][1]);
                mma16816(acc[mi][1], a[mi], bl_[0][2], bl_[0][3]);
                mma16816(acc[mi][2], a[mi], bl_[1][0], bl_[1][1]);
                mma16816(acc[mi][3], a[mi], bl_[1][2], bl_[1][3]);
            }
#pragma unroll
            for (int mi = 0; mi < 4; mi++)
                ldsm_x4(a[mi], al_b[s] +
                        (uint32_t)((a_row + mi * 16) * LDT + k0 + a_col) * 2);
#pragma unroll
            for (int mi = 0; mi < 4; mi++) {
                mma16816(acc[mi][0], a[mi], bh_[0][0], bh_[0][1]);
                mma16816(acc[mi][1], a[mi], bh_[0][2], bh_[0][3]);
                mma16816(acc[mi][2], a[mi], bh_[1][0], bh_[1][1]);
                mma16816(acc[mi][3], a[mi], bh_[1][2], bh_[1][3]);
            }
        }
        __syncthreads();
        if (kt + 2 < KVNITF) stage(kt + 2);
    }

    const int lr = lane >> 2;
    const int c0 = wn + ((lane & 3) << 1);
    float* dst = kvtf + (size_t)bh * DHc * Mc;
#pragma unroll
    for (int mi = 0; mi < 4; mi++) {
        const int d0 = mi * 16 + lr;
        const int d1 = d0 + 8;
#pragma unroll
        for (int ni = 0; ni < 4; ni++) {
            int c = c0 + ni * 8;
            atomicAdd(&dst[d0 * Mc + c],     acc[mi][ni][0]);
            atomicAdd(&dst[d0 * Mc + c + 1], acc[mi][ni][1]);
            atomicAdd(&dst[d1 * Mc + c],     acc[mi][ni][2]);
            atomicAdd(&dst[d1 * Mc + c + 1], acc[mi][ni][3]);
        }
    }
}

// ============================================================
// kvtf fp32 -> kvthi/kvtlo
// ============================================================
__global__ __launch_bounds__(256) void kvsplit_kernel(
    const float* __restrict__ kvtf, bf16* __restrict__ Thi, bf16* __restrict__ Tlo)
{
    int i = blockIdx.x * 256 + threadIdx.x;
    float v = kvtf[i];
    bf16 h, l; split2(v, h, l);
    Thi[i] = h; Tlo[i] = l;
}

// ============================================================
// attn via mma bf16x3 — fused-pass + fused z (R14, unchanged)
// ============================================================
#define ANITF 8
#define ATT_AMS (256 * LDT * 2)
#define ATT_BMS (64 * LDT * 2)
#define ATT_STAGEF (2 * ATT_AMS + 2 * ATT_BMS)
#define ATT_SMEMF (2 * ATT_STAGEF + 512 * 4)

__global__ __launch_bounds__(256, 2) void attn_mma_kernel(
    const bf16* __restrict__ qfhi, const bf16* __restrict__ qflo,
    const bf16* __restrict__ kvthi, const bf16* __restrict__ kvtlo,
    const float* __restrict__ ksum,
    bf16* __restrict__ Ohi, bf16* __restrict__ Olo)
{
    extern __shared__ char asm_[];
    const int bh = blockIdx.y;
    const int b = bh >> 4, h = bh & 15;
    const int l0 = blockIdx.x * 256;
    const int tid = threadIdx.x;
    const int lane = tid & 31, wid = tid >> 5;
    const int wm = (wid >> 1) * 64;
    const int wn = (wid & 1) * 32;

    uint32_t ah_b[2], al_b[2], bh_b[2], bl_b[2];
#pragma unroll
    for (int s = 0; s < 2; s++) {
        uint32_t base = smem_u32(asm_ + s * ATT_STAGEF);
        ah_b[s] = base;
        al_b[s] = base + ATT_AMS;
        bh_b[s] = base + 2 * ATT_AMS;
        bl_b[s] = base + 2 * ATT_AMS + ATT_BMS;
    }
    float* ksum_s = (float*)(asm_ + 2 * ATT_STAGEF);
    float* zden   = ksum_s + 256;

    const int a_row = wm + (lane & 15);
    const int a_col = (lane >> 4) << 3;
    const int b_row = wn + (lane & 7) + ((lane >> 4) << 3);
    const int b_col = ((lane >> 3) & 1) << 3;

    const size_t qbase = ((size_t)bh * Lc + l0) * Mc;
    const size_t kbase = (size_t)bh * DHc * Mc;

    const int ga_row = tid >> 2, ga_c8 = (tid & 3) << 3;

    ksum_s[tid] = ksum[bh * Mc + tid];

    auto stage = [&](int kt) {
        const int s  = kt & 1;
        const int kk = kt << 5;
#pragma unroll
        for (int i = 0; i < 4; i++) {
            int row = ga_row + i * 64;
            uint32_t soff = (uint32_t)(row * LDT + ga_c8) * 2;
            const size_t ga = qbase + (size_t)row * Mc + kk + ga_c8;
            cp_async16(ah_b[s] + soff, qfhi + ga);
            cp_async16(al_b[s] + soff, qflo + ga);
        }
        uint32_t bsoff = (uint32_t)(ga_row * LDT + ga_c8) * 2;
        const size_t gb = kbase + (size_t)ga_row * Mc + kk + ga_c8;
        cp_async16(bh_b[s] + bsoff, kvthi + gb);
        cp_async16(bl_b[s] + bsoff, kvtlo + gb);
        CP_COMMIT();
    };

    float acc[4][4][4];
#pragma unroll
    for (int mi = 0; mi < 4; mi++)
#pragma unroll
        for (int ni = 0; ni < 4; ni++)
#pragma unroll
            for (int e = 0; e < 4; e++) acc[mi][ni][e] = 0.f;
    float den = 0.f;

    stage(0); stage(1);

    for (int kt = 0; kt < ANITF; kt++) {
        const int s = kt & 1;
        if (kt + 1 < ANITF) CP_WAIT(1); else CP_WAIT(0);
        __syncthreads();

        {
            const bf16* ah_row = (const bf16*)(asm_ + s * ATT_STAGEF) + tid * LDT;
            const bf16* al_row = (const bf16*)(asm_ + s * ATT_STAGEF + ATT_AMS) + tid * LDT;
            const float* ks = ksum_s + (kt << 5);
#pragma unroll
            for (int c2 = 0; c2 < 16; c2++) {
                __nv_bfloat162 hh = *(const __nv_bfloat162*)&ah_row[c2 * 2];
                __nv_bfloat162 ll = *(const __nv_bfloat162*)&al_row[c2 * 2];
                den += (__bfloat162float(hh.x) + __bfloat162float(ll.x)) * ks[c2 * 2];
                den += (__bfloat162float(hh.y) + __bfloat162float(ll.y)) * ks[c2 * 2 + 1];
            }
        }

#pragma unroll
        for (int k0 = 0; k0 < 32; k0 += 16) {
            uint32_t bh_[2][4], bl_[2][4];
#pragma unroll
            for (int pr = 0; pr < 2; pr++) {
                uint32_t boff = (uint32_t)((b_row + pr * 16) * LDT + k0 + b_col) * 2;
                ldsm_x4(bh_[pr], bh_b[s] + boff);
                ldsm_x4(bl_[pr], bl_b[s] + boff);
            }
            uint32_t a[4][4];
#pragma unroll
            for (int mi = 0; mi < 4; mi++)
                ldsm_x4(a[mi], ah_b[s] +
                        (uint32_t)((a_row + mi * 16) * LDT + k0 + a_col) * 2);
#pragma unroll
            for (int mi = 0; mi < 4; mi++) {
                mma16816(acc[mi][0], a[mi], bh_[0][0], bh_[0][1]);
                mma16816(acc[mi][1], a[mi], bh_[0][2], bh_[0][3]);
                mma16816(acc[mi][2], a[mi], bh_[1][0], bh_[1][1]);
                mma16816(acc[mi][3], a[mi], bh_[1][2], bh_[1][3]);
            }
#pragma unroll
            for (int mi = 0; mi < 4; mi++) {
                mma16816(acc[mi][0], a[mi], bl_[0][0], bl_[0][1]);
                mma16816(acc[mi][1], a[mi], bl_[0][2], bl_[0][3]);
                mma16816(acc[mi][2], a[mi], bl_[1][0], bl_[1][1]);
                mma16816(acc[mi][3], a[mi], bl_[1][2], bl_[1][3]);
            }
#pragma unroll
            for (int mi = 0; mi < 4; mi++)
                ldsm_x4(a[mi], al_b[s] +
                        (uint32_t)((a_row + mi * 16) * LDT + k0 + a_col) * 2);
#pragma unroll
            for (int mi = 0; mi < 4; mi++) {
                mma16816(acc[mi][0], a[mi], bh_[0][0], bh_[0][1]);
                mma16816(acc[mi][1], a[mi], bh_[0][2], bh_[0][3]);
                mma16816(acc[mi][2], a[mi], bh_[1][0], bh_[1][1]);
                mma16816(acc[mi][3], a[mi], bh_[1][2], bh_[1][3]);
            }
        }
        __syncthreads();
        if (kt + 2 < ANITF) stage(kt + 2);
    }

    zden[tid] = 1.0f / (den + 1e-6f);
    __syncthreads();

    const int lr = lane >> 2;
    const int occ0 = wn + ((lane & 3) << 1);
#pragma unroll
    for (int mi = 0; mi < 4; mi++) {
        const int r0 = wm + mi * 16 + lr;
        const int r1 = r0 + 8;
        const float z0 = zden[r0];
        const float z1 = zden[r1];
        const size_t i0 = (size_t)(b * Lc + l0 + r0) * Dc + h * DHc;
        const size_t i1 = (size_t)(b * Lc + l0 + r1) * Dc + h * DHc;
#pragma unroll
        for (int ni = 0; ni < 4; ni++) {
            int c = occ0 + ni * 8;
            bf16 h0,l0b,h1,l1b,h2,l2b,h3,l3b;
            split2(acc[mi][ni][0] * z0, h0, l0b);
            split2(acc[mi][ni][1] * z0, h1, l1b);
            split2(acc[mi][ni][2] * z1, h2, l2b);
            split2(acc[mi][ni][3] * z1, h3, l3b);
            *(__nv_bfloat162*)&Ohi[i0 + c] = __halves2bfloat162(h0, h1);
            *(__nv_bfloat162*)&Ohi[i1 + c] = __halves2bfloat162(h2, h3);
            *(__nv_bfloat162*)&Olo[i0 + c] = __halves2bfloat162(l0b, l1b);
            *(__nv_bfloat162*)&Olo[i1 + c] = __halves2bfloat162(l2b, l3b);
        }
    }
}

// ============================================================
// LayerNorm + duplicate rows
// ============================================================
__global__ __launch_bounds__(256) void ln_dup_kernel(
    const float* __restrict__ y, const float* __restrict__ g,
    const float* __restrict__ beta, float* __restrict__ out)
{
    __shared__ float red[18];
    const int row = blockIdx.x;
    const int b = row >> 12, l = row & 4095;
    const int tid = threadIdx.x;
    const float* yr = y + (size_t)row * Dc;

    float v[4];
    float s = 0.f, ss = 0.f;
#pragma unroll
    for (int i = 0; i < 4; i++) {
        float t = yr[tid + i * 256];
        v[i] = t; s += t; ss += t * t;
    }
#pragma unroll
    for (int off = 16; off; off >>= 1) {
        s  += __shfl_xor_sync(0xffffffffu, s, off);
        ss += __shfl_xor_sync(0xffffffffu, ss, off);
    }
    const int w = tid >> 5, lane = tid & 31;
    if (lane == 0) { red[w] = s; red[8 + w] = ss; }
    __syncthreads();
    if (tid == 0) {
        float ts = 0.f, tss = 0.f;
#pragma unroll
        for (int i = 0; i < 8; i++) { ts += red[i]; tss += red[8 + i]; }
        float mean = ts * (1.0f / 1024.0f);
        float var = tss * (1.0f / 1024.0f) - mean * mean;
        red[16] = mean;
        red[17] = rsqrtf(var + 1e-5f);
    }
    __syncthreads();
    const float mean = red[16], rstd = red[17];
    float* o0 = out + ((size_t)b * 8192 + 2 * (size_t)l) * Dc;
#pragma unroll
    for (int i = 0; i < 4; i++) {
        int c = tid + i * 256;
        float o = (v[i] - mean) * rstd * g[c] + beta[c];
        o0[c] = o;
        o0[Dc + c] = o;
    }
}

// ============================================================
// host launch
// ============================================================
extern "C" void kernel_launch(void* const* d_in, const int* in_sizes, int n_in,
                              void* d_out, int out_size)
{
    const float* x    = (const float*)d_in[0];
    const float* Wq   = (const float*)d_in[1];
    const float* Wk   = (const float*)d_in[2];
    const float* Wv   = (const float*)d_in[3];
    const float* Wo   = (const float*)d_in[4];
    const float* proj = (const float*)d_in[5];
    const float* ln_g = (const float*)d_in[6];
    const float* ln_b = (const float*)d_in[7];
    float* out = (float*)d_out;

    float *v, *kvtf, *ksum, *y;
    bf16 *qfhi, *qflo, *kfthi, *kftlo, *vthi, *vtlo, *kvthi, *kvtlo;
    bf16 *ahi, *alo, *bthi, *btlo, *qhi, *qlo, *khi, *klo, *phi, *plo;
    cudaGetSymbolAddress((void**)&v,     g_v);
    cudaGetSymbolAddress((void**)&qfhi,  g_qfhi);
    cudaGetSymbolAddress((void**)&qflo,  g_qflo);
    cudaGetSymbolAddress((void**)&kfthi, g_kfthi);
    cudaGetSymbolAddress((void**)&kftlo, g_kftlo);
    cudaGetSymbolAddress((void**)&vthi,  g_vthi);
    cudaGetSymbolAddress((void**)&vtlo,  g_vtlo);
    cudaGetSymbolAddress((void**)&kvtf,  g_kvtf);
    cudaGetSymbolAddress((void**)&kvthi, g_kvthi);
    cudaGetSymbolAddress((void**)&kvtlo, g_kvtlo);
    cudaGetSymbolAddress((void**)&ksum,  g_ksum);
    cudaGetSymbolAddress((void**)&y,     g_y);
    cudaGetSymbolAddress((void**)&ahi,   g_ahi);
    cudaGetSymbolAddress((void**)&alo,   g_alo);
    cudaGetSymbolAddress((void**)&bthi,  g_bthi);
    cudaGetSymbolAddress((void**)&btlo,  g_btlo);
    cudaGetSymbolAddress((void**)&qhi,   g_qhi);
    cudaGetSymbolAddress((void**)&qlo,   g_qlo);
    cudaGetSymbolAddress((void**)&khi,   g_khi);
    cudaGetSymbolAddress((void**)&klo,   g_klo);
    cudaGetSymbolAddress((void**)&phi,   g_phi);
    cudaGetSymbolAddress((void**)&plo,   g_plo);

    const float qscale = 0.35355339059327379f;  // 64^-0.25

    cudaFuncSetAttribute(mma_gemm_kernel<0>,
                         cudaFuncAttributeMaxDynamicSharedMemorySize, GEMM_SMEMF);
    cudaFuncSetAttribute(mma_gemm_kernel<1>,
                         cudaFuncAttributeMaxDynamicSharedMemorySize, GEMM_SMEMF);
    cudaFuncSetAttribute(feature_mma_kernel<1>,
                         cudaFuncAttributeMaxDynamicSharedMemorySize, FEAT2_SMEM);
    cudaFuncSetAttribute(feature_mma_kernel<2>,
                         cudaFuncAttributeMaxDynamicSharedMemorySize, FEAT2_SMEM);
    cudaFuncSetAttribute(kv_mma_kernel,
                         cudaFuncAttributeMaxDynamicSharedMemorySize, KV_SMEMF);
    cudaFuncSetAttribute(attn_mma_kernel,
                         cudaFuncAttributeMaxDynamicSharedMemorySize, ATT_SMEMF);

    // prep: x/proj splits + ksum/kvtf zero in ONE launch
    prep_kernel<<<PREP_BLOCKS, 256>>>(x, ahi, alo, proj, phi, plo, ksum, kvtf);
    tsplit4_kernel<<<dim3(32, 32, 4), dim3(32, 8)>>>(Wq, Wk, Wv, Wo, bthi, btlo);

    // fused QKV GEMM (V -> fp32)
    mma_gemm_kernel<0><<<dim3(24, 64), 256, GEMM_SMEMF>>>(
        ahi, alo, bthi, btlo, v, qhi, qlo, khi, klo, qscale);

    // features: Q -> qf hi/lo [l][m]; K -> kf_t hi/lo [m][l] + ksum
    feature_mma_kernel<1><<<dim3(Lc / 128, BHc), 256, FEAT2_SMEM>>>(
        qhi, qlo, phi, plo, qfhi, qflo, nullptr);
    feature_mma_kernel<2><<<dim3(Lc / 128, BHc), 256, FEAT2_SMEM>>>(
        khi, klo, phi, plo, kfthi, kftlo, ksum);

    // v transpose+split, then kv via tensor cores
    vt_kernel<<<dim3(Lc / 32, BHc), 256>>>(v, vthi, vtlo);
    kv_mma_kernel<<<dim3(8, BHc), 256, KV_SMEMF>>>(vthi, vtlo, kfthi, kftlo, kvtf);
    kvsplit_kernel<<<(BHc * DHc * Mc) / 256, 256>>>(kvtf, kvthi, kvtlo);

    // attn (z fused) -> hi/lo directly into O-GEMM A buffers
    attn_mma_kernel<<<dim3(Lc / 256, BHc), 256, ATT_SMEMF>>>(
        qfhi, qflo, kvthi, kvtlo, ksum, ahi, alo);

    // O projection + exact GELU (weights at offset 3)
    mma_gemm_kernel<1><<<dim3(8, 64), 256, GEMM_SMEMF>>>(
        ahi, alo, bthi + (size_t)3 * Dc * Dc, btlo + (size_t)3 * Dc * Dc,
        y, nullptr, nullptr, nullptr, nullptr, 1.0f);

    ln_dup_kernel<<<ROWS, 256>>>(y, ln_g, ln_b, out);
}

// round 16
// speedup vs baseline: 1.0562x; 1.0160x over previous
#include <cuda_runtime.h>
#include <cuda_bf16.h>
#include <math.h>
#include <stdint.h>

// Shapes (fixed)
#define Bc   2
#define Lc   4096
#define Dc   1024
#define Hc   16
#define DHc  64
#define Mc   256
#define BHc  32
#define ROWS 8192   // B*L

typedef __nv_bfloat16 bf16;

// -------- scratch (device globals; no allocations allowed) --------
__device__ float g_v    [(size_t)ROWS * Dc];
__device__ bf16  g_qfhi [(size_t)BHc * Lc * Mc];
__device__ bf16  g_qflo [(size_t)BHc * Lc * Mc];
__device__ bf16  g_kfthi[(size_t)BHc * Mc * Lc];
__device__ bf16  g_kftlo[(size_t)BHc * Mc * Lc];
__device__ bf16  g_vthi [(size_t)BHc * DHc * Lc];
__device__ bf16  g_vtlo [(size_t)BHc * DHc * Lc];
__device__ float g_kvtf [(size_t)BHc * DHc * Mc];
__device__ bf16  g_kvthi[(size_t)BHc * DHc * Mc];
__device__ bf16  g_kvtlo[(size_t)BHc * DHc * Mc];
__device__ float g_ksum [(size_t)BHc * Mc];
__device__ float g_y    [(size_t)ROWS * Dc];
__device__ bf16  g_ahi  [(size_t)ROWS * Dc];
__device__ bf16  g_alo  [(size_t)ROWS * Dc];
__device__ bf16  g_bthi [(size_t)4 * Dc * Dc];
__device__ bf16  g_btlo [(size_t)4 * Dc * Dc];
__device__ bf16  g_qhi  [(size_t)ROWS * Dc];
__device__ bf16  g_qlo  [(size_t)ROWS * Dc];
__device__ bf16  g_khi  [(size_t)ROWS * Dc];
__device__ bf16  g_klo  [(size_t)ROWS * Dc];
__device__ bf16  g_phi  [(size_t)Hc * Mc * DHc];
__device__ bf16  g_plo  [(size_t)Hc * Mc * DHc];

// ================= baseline-PTX tensor-core helpers (sm_80+) ==========
__device__ __forceinline__ uint32_t smem_u32(const void* p) {
    uint32_t a;
    asm("{ .reg .u64 t; cvta.to.shared.u64 t, %1; cvt.u32.u64 %0, t; }"
        : "=r"(a) : "l"(p));
    return a;
}
__device__ __forceinline__ void cp_async16(uint32_t saddr, const void* g) {
    asm volatile("cp.async.cg.shared.global [%0], [%1], 16;"
                 :: "r"(saddr), "l"(g) : "memory");
}
#define CP_COMMIT() asm volatile("cp.async.commit_group;" ::: "memory")
#define CP_WAIT(n)  asm volatile("cp.async.wait_group %0;" :: "n"(n) : "memory")

__device__ __forceinline__ void ldsm_x4(uint32_t r[4], uint32_t addr) {
    asm volatile("ldmatrix.sync.aligned.m8n8.x4.shared.b16 {%0,%1,%2,%3}, [%4];"
                 : "=r"(r[0]), "=r"(r[1]), "=r"(r[2]), "=r"(r[3]) : "r"(addr));
}
__device__ __forceinline__ void mma16816(float c[4], const uint32_t a[4],
                                         uint32_t b0, uint32_t b1) {
    asm volatile(
        "mma.sync.aligned.m16n8k16.row.col.f32.bf16.bf16.f32 "
        "{%0,%1,%2,%3}, {%4,%5,%6,%7}, {%8,%9}, {%0,%1,%2,%3};"
        : "+f"(c[0]), "+f"(c[1]), "+f"(c[2]), "+f"(c[3])
        : "r"(a[0]), "r"(a[1]), "r"(a[2]), "r"(a[3]), "r"(b0), "r"(b1));
}
__device__ __forceinline__ void split2(float v, bf16& h, bf16& l) {
    h = __float2bfloat16_rn(v);
    l = __float2bfloat16_rn(v - __bfloat162float(h));
}

// ============================================================
// PREP: x-split + proj-split + zero(ksum) + zero(kvtf) in ONE launch
// ============================================================
#define PREP_BLOCKS (8192 + 256 + 8 + 512)

__global__ __launch_bounds__(256) void prep_kernel(
    const float* __restrict__ x, bf16* __restrict__ ahi, bf16* __restrict__ alo,
    const float* __restrict__ proj, bf16* __restrict__ phi, bf16* __restrict__ plo,
    float* __restrict__ ksum, float* __restrict__ kvtf)
{
    int bid = blockIdx.x;
    if (bid < 8192 + 256) {
        const float* in = (bid < 8192) ? x : proj;
        bf16* hi = (bid < 8192) ? ahi : phi;
        bf16* lo = (bid < 8192) ? alo : plo;
        int base = (bid < 8192) ? bid : (bid - 8192);
        int i = base * 256 + threadIdx.x;
        float4 v = ((const float4*)in)[i];
        bf16 h0, h1, h2, h3, l0, l1, l2, l3;
        split2(v.x, h0, l0); split2(v.y, h1, l1);
        split2(v.z, h2, l2); split2(v.w, h3, l3);
        ((__nv_bfloat162*)hi)[2*i]   = __halves2bfloat162(h0, h1);
        ((__nv_bfloat162*)hi)[2*i+1] = __halves2bfloat162(h2, h3);
        ((__nv_bfloat162*)lo)[2*i]   = __halves2bfloat162(l0, l1);
        ((__nv_bfloat162*)lo)[2*i+1] = __halves2bfloat162(l2, l3);
    } else if (bid < 8192 + 256 + 8) {
        int i = (bid - 8448) * 256 + threadIdx.x;
        ((float4*)ksum)[i] = make_float4(0.f, 0.f, 0.f, 0.f);
    } else {
        int i = (bid - 8456) * 256 + threadIdx.x;
        ((float4*)kvtf)[i] = make_float4(0.f, 0.f, 0.f, 0.f);
    }
}

// ============================================================
// 4 weights [K,N] -> W^T [N,K] bf16 hi/lo, single launch
// ============================================================
__global__ void tsplit4_kernel(
    const float* __restrict__ W0, const float* __restrict__ W1,
    const float* __restrict__ W2, const float* __restrict__ W3,
    bf16* __restrict__ Thi, bf16* __restrict__ Tlo)
{
    __shared__ float t[32][33];
    const float* W = (blockIdx.z == 0) ? W0 : (blockIdx.z == 1) ? W1
                    : (blockIdx.z == 2) ? W2 : W3;
    bf16* th = Thi + (size_t)blockIdx.z * Dc * Dc;
    bf16* tl = Tlo + (size_t)blockIdx.z * Dc * Dc;
    int bx = blockIdx.x * 32, by = blockIdx.y * 32;
    int tx = threadIdx.x, ty = threadIdx.y;   // 32 x 8
#pragma unroll
    for (int i = 0; i < 32; i += 8)
        t[ty + i][tx] = W[(size_t)(by + ty + i) * Dc + bx + tx];
    __syncthreads();
#pragma unroll
    for (int i = 0; i < 32; i += 8) {
        float v = t[tx][ty + i];
        int orow = bx + ty + i, ocol = by + tx;
        bf16 h, l; split2(v, h, l);
        th[(size_t)orow * Dc + ocol] = h;
        tl[(size_t)orow * Dc + ocol] = l;
    }
}

// ============================================================
// v [b*L][D] fp32 -> v_t [bh][d][l] bf16 hi/lo
// ============================================================
__global__ __launch_bounds__(256) void vt_kernel(
    const float* __restrict__ v, bf16* __restrict__ Thi, bf16* __restrict__ Tlo)
{
    __shared__ float t[64][33];
    const int bh = blockIdx.y;
    const int b = bh >> 4, h = bh & 15;
    const int l0 = blockIdx.x * 32;
    const int tid = threadIdx.x;
#pragma unroll
    for (int i = 0; i < 8; i++) {
        int s = tid + i * 256;
        int r = s >> 6, c = s & 63;
        t[c][r & 31] = v[(size_t)(b * Lc + l0 + r) * Dc + h * DHc + c];
    }
    __syncthreads();
#pragma unroll
    for (int i = 0; i < 8; i++) {
        int s = tid + i * 256;
        int d = s >> 5, c = s & 31;
        float val = t[d][c];
        bf16 hh, ll; split2(val, hh, ll);
        size_t o = ((size_t)bh * DHc + d) * Lc + l0 + c;
        Thi[o] = hh; Tlo[o] = ll;
    }
}

// ============================================================
// bf16x3 FUSED-PASS tensor-core GEMM — interleaved schedule (R15)
// ============================================================
#define LDT 40
#define GNITF 32
#define GEMM_MSTG (128 * LDT * 2)
#define GEMM_STAGE (4 * GEMM_MSTG)
#define GEMM_SMEMF (2 * GEMM_STAGE)

template<int MODE>
__global__ __launch_bounds__(256, 2) void mma_gemm_kernel(
    const bf16* __restrict__ Ahi, const bf16* __restrict__ Alo,
    const bf16* __restrict__ Bhi, const bf16* __restrict__ Blo,
    float* __restrict__ Cv,
    bf16* __restrict__ Qhi, bf16* __restrict__ Qlo,
    bf16* __restrict__ Khi, bf16* __restrict__ Klo,
    float qalpha)
{
    extern __shared__ char gsm[];
    const int tid  = threadIdx.x;
    const int lane = tid & 31, wid = tid >> 5;
    const int bm = blockIdx.y * 128;
    const int bn = blockIdx.x * 128;
    const int wm = (wid >> 2) * 64;
    const int wn = (wid & 3) * 32;

    uint32_t ah_b[2], al_b[2], bh_b[2], bl_b[2];
#pragma unroll
    for (int s = 0; s < 2; s++) {
        uint32_t base = smem_u32(gsm + s * GEMM_STAGE);
        ah_b[s] = base;
        al_b[s] = base + GEMM_MSTG;
        bh_b[s] = base + 2 * GEMM_MSTG;
        bl_b[s] = base + 3 * GEMM_MSTG;
    }

    const int a_row = wm + (lane & 15);
    const int a_col = (lane >> 4) << 3;
    const int b_row = wn + (lane & 7) + ((lane >> 4) << 3);
    const int b_col = ((lane >> 3) & 1) << 3;

    const int g_row0 = tid >> 2;
    const int g_c8   = (tid & 3) << 3;

    auto stage = [&](int kt) {
        const int s  = kt & 1;
        const int kk = kt << 5;
#pragma unroll
        for (int i = 0; i < 2; i++) {
            int row = g_row0 + i * 64;
            uint32_t soff = (uint32_t)(row * LDT + g_c8) * 2;
            const size_t ga = (size_t)(bm + row) * Dc + kk + g_c8;
            const size_t gb = (size_t)(bn + row) * Dc + kk + g_c8;
            cp_async16(ah_b[s] + soff, Ahi + ga);
            cp_async16(al_b[s] + soff, Alo + ga);
            cp_async16(bh_b[s] + soff, Bhi + gb);
            cp_async16(bl_b[s] + soff, Blo + gb);
        }
        CP_COMMIT();
    };

    float acc[4][4][4];
#pragma unroll
    for (int mi = 0; mi < 4; mi++)
#pragma unroll
        for (int ni = 0; ni < 4; ni++)
#pragma unroll
            for (int e = 0; e < 4; e++) acc[mi][ni][e] = 0.f;

    stage(0); stage(1);

    for (int kt = 0; kt < GNITF; kt++) {
        const int s = kt & 1;
        if (kt + 1 < GNITF) CP_WAIT(1); else CP_WAIT(0);
        __syncthreads();

#pragma unroll
        for (int k0 = 0; k0 < 32; k0 += 16) {
            uint32_t bfr[2][4];
            uint32_t a[4][4];
#pragma unroll
            for (int pr = 0; pr < 2; pr++)
                ldsm_x4(bfr[pr], bh_b[s] +
                        (uint32_t)((b_row + pr * 16) * LDT + k0 + b_col) * 2);
#pragma unroll
            for (int mi = 0; mi < 4; mi++)
                ldsm_x4(a[mi], ah_b[s] +
                        (uint32_t)((a_row + mi * 16) * LDT + k0 + a_col) * 2);
#pragma unroll
            for (int mi = 0; mi < 4; mi++) {
                mma16816(acc[mi][0], a[mi], bfr[0][0], bfr[0][1]);
                mma16816(acc[mi][1], a[mi], bfr[0][2], bfr[0][3]);
                mma16816(acc[mi][2], a[mi], bfr[1][0], bfr[1][1]);
                mma16816(acc[mi][3], a[mi], bfr[1][2], bfr[1][3]);
            }
            uint32_t blr[2][4];
#pragma unroll
            for (int pr = 0; pr < 2; pr++)
                ldsm_x4(blr[pr], bl_b[s] +
                        (uint32_t)((b_row + pr * 16) * LDT + k0 + b_col) * 2);
#pragma unroll
            for (int mi = 0; mi < 4; mi++) {
                mma16816(acc[mi][0], a[mi], blr[0][0], blr[0][1]);
                mma16816(acc[mi][1], a[mi], blr[0][2], blr[0][3]);
                mma16816(acc[mi][2], a[mi], blr[1][0], blr[1][1]);
                mma16816(acc[mi][3], a[mi], blr[1][2], blr[1][3]);
            }
#pragma unroll
            for (int mi = 0; mi < 4; mi++)
                ldsm_x4(a[mi], al_b[s] +
                        (uint32_t)((a_row + mi * 16) * LDT + k0 + a_col) * 2);
#pragma unroll
            for (int mi = 0; mi < 4; mi++) {
                mma16816(acc[mi][0], a[mi], bfr[0][0], bfr[0][1]);
                mma16816(acc[mi][1], a[mi], bfr[0][2], bfr[0][3]);
                mma16816(acc[mi][2], a[mi], bfr[1][0], bfr[1][1]);
                mma16816(acc[mi][3], a[mi], bfr[1][2], bfr[1][3]);
            }
        }
        __syncthreads();
        if (kt + 2 < GNITF) stage(kt + 2);
    }

    const int orow = bm + wm + (lane >> 2);
    const int occ0 = wn + ((lane & 3) << 1);

    if (MODE == 0) {
        const int which = bn >> 10;        // 0 q, 1 k, 2 v
        const int bnl = bn & 1023;
        if (which < 2) {
            bf16* Oh = which ? Khi : Qhi;
            bf16* Ol = which ? Klo : Qlo;
#pragma unroll
            for (int mi = 0; mi < 4; mi++)
#pragma unroll
                for (int ni = 0; ni < 4; ni++) {
                    const size_t i0 = (size_t)(orow + mi * 16) * Dc + bnl + occ0 + ni * 8;
                    const size_t i1 = (size_t)(orow + mi * 16 + 8) * Dc + bnl + occ0 + ni * 8;
                    bf16 h0,l0,h1,l1,h2,l2,h3,l3;
                    split2(acc[mi][ni][0] * qalpha, h0, l0);
                    split2(acc[mi][ni][1] * qalpha, h1, l1);
                    split2(acc[mi][ni][2] * qalpha, h2, l2);
                    split2(acc[mi][ni][3] * qalpha, h3, l3);
                    *(__nv_bfloat162*)&Oh[i0] = __halves2bfloat162(h0, h1);
                    *(__nv_bfloat162*)&Oh[i1] = __halves2bfloat162(h2, h3);
                    *(__nv_bfloat162*)&Ol[i0] = __halves2bfloat162(l0, l1);
                    *(__nv_bfloat162*)&Ol[i1] = __halves2bfloat162(l2, l3);
                }
        } else {
#pragma unroll
            for (int mi = 0; mi < 4; mi++)
#pragma unroll
                for (int ni = 0; ni < 4; ni++) {
                    const size_t i0 = (size_t)(orow + mi * 16) * Dc + bnl + occ0 + ni * 8;
                    const size_t i1 = (size_t)(orow + mi * 16 + 8) * Dc + bnl + occ0 + ni * 8;
                    *(float2*)&Cv[i0] = make_float2(acc[mi][ni][0], acc[mi][ni][1]);
                    *(float2*)&Cv[i1] = make_float2(acc[mi][ni][2], acc[mi][ni][3]);
                }
        }
    } else {
#pragma unroll
        for (int mi = 0; mi < 4; mi++)
#pragma unroll
            for (int ni = 0; ni < 4; ni++) {
                float v0 = acc[mi][ni][0], v1 = acc[mi][ni][1];
                float v2 = acc[mi][ni][2], v3 = acc[mi][ni][3];
                v0 = 0.5f * v0 * (1.f + erff(v0 * 0.70710678118654752f));
                v1 = 0.5f * v1 * (1.f + erff(v1 * 0.70710678118654752f));
                v2 = 0.5f * v2 * (1.f + erff(v2 * 0.70710678118654752f));
                v3 = 0.5f * v3 * (1.f + erff(v3 * 0.70710678118654752f));
                const size_t i0 = (size_t)(orow + mi * 16) * Dc + bn + occ0 + ni * 8;
                const size_t i1 = (size_t)(orow + mi * 16 + 8) * Dc + bn + occ0 + ni * 8;
                *(float2*)&Cv[i0] = make_float2(v0, v1);
                *(float2*)&Cv[i1] = make_float2(v2, v3);
            }
    }
}

// ============================================================
// FAVOR+ feature via mma.sync bf16x3 — 64-row CTA tile, 2 CTAs/SM.
// OMODE 1: [bh][l][m] hi/lo.  OMODE 2: transposed [bh][m][l] + ksum.
// Warp tile 32x64 (2 m-groups x 4 n-warps).
// ============================================================
#define FLDK 72
#define FEAT3_SMEM ((64 + 64 + 256 + 256) * FLDK * 2 + (64 + 256 + 256) * 4)

template<int OMODE>
__global__ __launch_bounds__(256, 2) void feature_mma_kernel(
    const bf16* __restrict__ Uhi, const bf16* __restrict__ Ulo,
    const bf16* __restrict__ Phi, const bf16* __restrict__ Plo,
    bf16* __restrict__ Fhi, bf16* __restrict__ Flo,
    float* __restrict__ ksum)
{
    extern __shared__ char fsm[];
    bf16* us_h = (bf16*)fsm;                    // [64][FLDK]
    bf16* us_l = us_h + 64 * FLDK;
    bf16* ps_h = us_l + 64 * FLDK;              // [256][FLDK]
    bf16* ps_l = ps_h + 256 * FLDK;
    float* diag   = (float*)(ps_l + 256 * FLDK); // [64]
    float* rmaxp  = diag + 64;                   // [4][64]
    float* colsum = rmaxp + 4 * 64;              // [256]

    const int bh = blockIdx.y;
    const int b = bh >> 4, h = bh & 15;
    const int l0 = blockIdx.x * 64;
    const int tid = threadIdx.x;
    const int lane = tid & 31, wid = tid >> 5;

    // load u: 64 x 64, hi & lo (2 x uint4 per thread per matrix)
#pragma unroll
    for (int i = 0; i < 2; i++) {
        int s = tid + i * 256;            // 0..511
        int r = s >> 3, c8 = (s & 7) << 3;
        size_t gi = (size_t)(b * Lc + l0 + r) * Dc + h * DHc + c8;
        *(uint4*)&us_h[r * FLDK + c8] = *(const uint4*)&Uhi[gi];
        *(uint4*)&us_l[r * FLDK + c8] = *(const uint4*)&Ulo[gi];
    }
    // load proj[h]: 256 x 64, hi & lo
#pragma unroll
    for (int i = 0; i < 8; i++) {
        int s = tid + i * 256;
        int r = s >> 3, c8 = (s & 7) << 3;
        size_t gi = (size_t)(h * Mc + r) * DHc + c8;
        *(uint4*)&ps_h[r * FLDK + c8] = *(const uint4*)&Phi[gi];
        *(uint4*)&ps_l[r * FLDK + c8] = *(const uint4*)&Plo[gi];
    }
    __syncthreads();

    if (tid < 64) {
        float s = 0.f;
#pragma unroll
        for (int d2 = 0; d2 < 32; d2++) {
            __nv_bfloat162 hh = *(__nv_bfloat162*)&us_h[tid * FLDK + d2 * 2];
            __nv_bfloat162 ll = *(__nv_bfloat162*)&us_l[tid * FLDK + d2 * 2];
            float u0 = __bfloat162float(hh.x) + __bfloat162float(ll.x);
            float u1 = __bfloat162float(hh.y) + __bfloat162float(ll.y);
            s += u0 * u0 + u1 * u1;
        }
        diag[tid] = 0.5f * s;
    }

    const int wm = (wid >> 2) * 32;      // 2 m-groups of 32 rows
    const int wn = (wid & 3) * 64;       // 4 n-warps of 64 cols
    const int a_row = wm + (lane & 15);
    const int a_col = (lane >> 4) << 3;
    const int b_row = wn + (lane & 7) + ((lane >> 4) << 3);
    const int b_col = ((lane >> 3) & 1) << 3;

    float acc[2][8][4];
#pragma unroll
    for (int mi = 0; mi < 2; mi++)
#pragma unroll
        for (int ni = 0; ni < 8; ni++)
#pragma unroll
            for (int e = 0; e < 4; e++) acc[mi][ni][e] = 0.f;

    const uint32_t ush = smem_u32(us_h), usl = smem_u32(us_l);
    const uint32_t psh = smem_u32(ps_h), psl = smem_u32(ps_l);
    __syncthreads();

#pragma unroll
    for (int k0 = 0; k0 < 64; k0 += 16) {
        uint32_t ah[2][4], al[2][4], bfr[4][4];
#pragma unroll
        for (int mi = 0; mi < 2; mi++) {
            uint32_t aoff = (uint32_t)((a_row + mi * 16) * FLDK + k0 + a_col) * 2;
            ldsm_x4(ah[mi], ush + aoff);
            ldsm_x4(al[mi], usl + aoff);
        }
#pragma unroll
        for (int pr = 0; pr < 4; pr++)
            ldsm_x4(bfr[pr], psh + (uint32_t)((b_row + pr * 16) * FLDK + k0 + b_col) * 2);
#pragma unroll
        for (int mi = 0; mi < 2; mi++)
#pragma unroll
            for (int pr = 0; pr < 4; pr++) {
                mma16816(acc[mi][2 * pr],     ah[mi], bfr[pr][0], bfr[pr][1]);
                mma16816(acc[mi][2 * pr + 1], ah[mi], bfr[pr][2], bfr[pr][3]);
            }
#pragma unroll
        for (int mi = 0; mi < 2; mi++)
#pragma unroll
            for (int pr = 0; pr < 4; pr++) {
                mma16816(acc[mi][2 * pr],     al[mi], bfr[pr][0], bfr[pr][1]);
                mma16816(acc[mi][2 * pr + 1], al[mi], bfr[pr][2], bfr[pr][3]);
            }
#pragma unroll
        for (int pr = 0; pr < 4; pr++)
            ldsm_x4(bfr[pr], psl + (uint32_t)((b_row + pr * 16) * FLDK + k0 + b_col) * 2);
#pragma unroll
        for (int mi = 0; mi < 2; mi++)
#pragma unroll
            for (int pr = 0; pr < 4; pr++) {
                mma16816(acc[mi][2 * pr],     ah[mi], bfr[pr][0], bfr[pr][1]);
                mma16816(acc[mi][2 * pr + 1], ah[mi], bfr[pr][2], bfr[pr][3]);
            }
    }

    // per-thread row maxima -> quad shuffle -> smem partials per n-warp
    float tmax[2][2];
#pragma unroll
    for (int mi = 0; mi < 2; mi++) {
        float m0 = -1e30f, m1 = -1e30f;
#pragma unroll
        for (int ni = 0; ni < 8; ni++) {
            m0 = fmaxf(m0, fmaxf(acc[mi][ni][0], acc[mi][ni][1]));
            m1 = fmaxf(m1, fmaxf(acc[mi][ni][2], acc[mi][ni][3]));
        }
#pragma unroll
        for (int off = 1; off <= 2; off <<= 1) {
            m0 = fmaxf(m0, __shfl_xor_sync(0xffffffffu, m0, off));
            m1 = fmaxf(m1, __shfl_xor_sync(0xffffffffu, m1, off));
        }
        tmax[mi][0] = m0; tmax[mi][1] = m1;
    }
    if ((lane & 3) == 0) {
        const int slab = wid & 3;
#pragma unroll
        for (int mi = 0; mi < 2; mi++) {
            int r = wm + mi * 16 + (lane >> 2);
            rmaxp[slab * 64 + r]     = tmax[mi][0];
            rmaxp[slab * 64 + r + 8] = tmax[mi][1];
        }
    }
    if (OMODE == 2) colsum[tid] = 0.f;
    __syncthreads();

    float base[2][2];
#pragma unroll
    for (int mi = 0; mi < 2; mi++) {
        const int r0 = wm + mi * 16 + (lane >> 2);
        const int r1 = r0 + 8;
        float rm0 = fmaxf(fmaxf(rmaxp[r0], rmaxp[64 + r0]),
                          fmaxf(rmaxp[128 + r0], rmaxp[192 + r0]));
        float rm1 = fmaxf(fmaxf(rmaxp[r1], rmaxp[64 + r1]),
                          fmaxf(rmaxp[128 + r1], rmaxp[192 + r1]));
        base[mi][0] = -diag[r0] - rm0;
        base[mi][1] = -diag[r1] - rm1;
    }

    if (OMODE == 1) {
#pragma unroll
        for (int mi = 0; mi < 2; mi++) {
            const int r0 = wm + mi * 16 + (lane >> 2);
            const size_t o0 = ((size_t)bh * Lc + l0 + r0) * Mc;
            const size_t o1 = ((size_t)bh * Lc + l0 + r0 + 8) * Mc;
            const int c0 = wn + ((lane & 3) << 1);
#pragma unroll
            for (int ni = 0; ni < 8; ni++) {
                int c = c0 + ni * 8;
                float f0 = __expf(acc[mi][ni][0] + base[mi][0]) * 0.0625f;
                float f1 = __expf(acc[mi][ni][1] + base[mi][0]) * 0.0625f;
                float f2 = __expf(acc[mi][ni][2] + base[mi][1]) * 0.0625f;
                float f3 = __expf(acc[mi][ni][3] + base[mi][1]) * 0.0625f;
                bf16 h0,l0b,h1,l1b,h2,l2b,h3,l3b;
                split2(f0, h0, l0b); split2(f1, h1, l1b);
                split2(f2, h2, l2b); split2(f3, h3, l3b);
                *(__nv_bfloat162*)&Fhi[o0 + c] = __halves2bfloat162(h0, h1);
                *(__nv_bfloat162*)&Fhi[o1 + c] = __halves2bfloat162(h2, h3);
                *(__nv_bfloat162*)&Flo[o0 + c] = __halves2bfloat162(l0b, l1b);
                *(__nv_bfloat162*)&Flo[o1 + c] = __halves2bfloat162(l2b, l3b);
            }
        }
    } else {
        const int lr = lane >> 2;
#pragma unroll
        for (int ni = 0; ni < 8; ni++) {
            const int c = wn + ((lane & 3) << 1) + ni * 8;
            float s0 = 0.f, s1 = 0.f;
#pragma unroll
            for (int mi = 0; mi < 2; mi++) {
                const int r0 = wm + mi * 16 + lr;
                float f0 = __expf(acc[mi][ni][0] + base[mi][0]) * 0.0625f;
                float f1 = __expf(acc[mi][ni][1] + base[mi][0]) * 0.0625f;
                float f2 = __expf(acc[mi][ni][2] + base[mi][1]) * 0.0625f;
                float f3 = __expf(acc[mi][ni][3] + base[mi][1]) * 0.0625f;
                s0 += f0 + f2; s1 += f1 + f3;
                const size_t t0 = ((size_t)bh * Mc + c) * Lc + l0;
                const size_t t1 = t0 + Lc;
                bf16 hh, ll;
                split2(f0, hh, ll); Fhi[t0 + r0] = hh;     Flo[t0 + r0] = ll;
                split2(f2, hh, ll); Fhi[t0 + r0 + 8] = hh; Flo[t0 + r0 + 8] = ll;
                split2(f1, hh, ll); Fhi[t1 + r0] = hh;     Flo[t1 + r0] = ll;
                split2(f3, hh, ll); Fhi[t1 + r0 + 8] = hh; Flo[t1 + r0 + 8] = ll;
            }
            atomicAdd(&colsum[c], s0);
            atomicAdd(&colsum[c + 1], s1);
        }
        __syncthreads();
        atomicAdd(&ksum[bh * Mc + tid], colsum[tid]);
    }
}

// ============================================================
// kv via mma bf16x3 — fused-pass (unchanged)
// ============================================================
#define KVNITF 16
#define KV_AMS (64 * LDT * 2)
#define KV_BMS (256 * LDT * 2)
#define KV_STAGEF (2 * KV_AMS + 2 * KV_BMS)
#define KV_SMEMF (2 * KV_STAGEF)

__global__ __launch_bounds__(256, 2) void kv_mma_kernel(
    const bf16* __restrict__ vthi, const bf16* __restrict__ vtlo,
    const bf16* __restrict__ kfthi, const bf16* __restrict__ kftlo,
    float* __restrict__ kvtf)
{
    extern __shared__ char ksm[];
    const int bh = blockIdx.y;
    const int l0 = blockIdx.x * 512;
    const int tid = threadIdx.x;
    const int lane = tid & 31, wid = tid >> 5;
    const int wn = wid * 32;

    uint32_t ah_b[2], al_b[2], bh_b[2], bl_b[2];
#pragma unroll
    for (int s = 0; s < 2; s++) {
        uint32_t base = smem_u32(ksm + s * KV_STAGEF);
        ah_b[s] = base;
        al_b[s] = base + KV_AMS;
        bh_b[s] = base + 2 * KV_AMS;
        bl_b[s] = base + 2 * KV_AMS + KV_BMS;
    }

    const int a_row = (lane & 15);
    const int a_col = (lane >> 4) << 3;
    const int b_row = wn + (lane & 7) + ((lane >> 4) << 3);
    const int b_col = ((lane >> 3) & 1) << 3;

    const size_t abase = (size_t)bh * DHc * Lc + l0;
    const size_t bbase = (size_t)bh * Mc * Lc + l0;

    const int ga_row = tid >> 2, ga_c8 = (tid & 3) << 3;

    auto stage = [&](int kt) {
        const int s  = kt & 1;
        const int kk = kt << 5;
        uint32_t asoff = (uint32_t)(ga_row * LDT + ga_c8) * 2;
        const size_t ga = abase + (size_t)ga_row * Lc + kk + ga_c8;
        cp_async16(ah_b[s] + asoff, vthi + ga);
        cp_async16(al_b[s] + asoff, vtlo + ga);
#pragma unroll
        for (int i = 0; i < 4; i++) {
            int row = ga_row + i * 64;
            uint32_t bsoff = (uint32_t)(row * LDT + ga_c8) * 2;
            const size_t gb = bbase + (size_t)row * Lc + kk + ga_c8;
            cp_async16(bh_b[s] + bsoff, kfthi + gb);
            cp_async16(bl_b[s] + bsoff, kftlo + gb);
        }
        CP_COMMIT();
    };

    float acc[4][4][4];
#pragma unroll
    for (int mi = 0; mi < 4; mi++)
#pragma unroll
        for (int ni = 0; ni < 4; ni++)
#pragma unroll
            for (int e = 0; e < 4; e++) acc[mi][ni][e] = 0.f;

    stage(0); stage(1);

    for (int kt = 0; kt < KVNITF; kt++) {
        const int s = kt & 1;
        if (kt + 1 < KVNITF) CP_WAIT(1); else CP_WAIT(0);
        __syncthreads();

#pragma unroll
        for (int k0 = 0; k0 < 32; k0 += 16) {
            uint32_t bh_[2][4], bl_[2][4];
#pragma unroll
            for (int pr = 0; pr < 2; pr++) {
                uint32_t boff = (uint32_t)((b_row + pr * 16) * LDT + k0 + b_col) * 2;
                ldsm_x4(bh_[pr], bh_b[s] + boff);
                ldsm_x4(bl_[pr], bl_b[s] + boff);
            }
            uint32_t a[4][4];
#pragma unroll
            for (int mi = 0; mi < 4; mi++)
                ldsm_x4(a[mi], ah_b[s] +
                        (uint32_t)((a_row + mi * 16) * LDT + k0 + a_col) * 2);
#pragma unroll
            for (int mi = 0; mi < 4; mi++) {
                mma16816(acc[mi][0], a[mi], bh_[0][0], bh_[0][1]);
                mma16816(acc[mi][1], a[mi], bh_[0][2], bh_[0][3]);
                mma16816(acc[mi][2], a[mi], bh_[1][0], bh_[1][1]);
                mma16816(acc[mi][3], a[mi], bh_[1][2], bh_[1][3]);
            }
#pragma unroll
            for (int mi = 0; mi < 4; mi++) {
                mma16816(acc[mi][0], a[mi], bl_[0][0], bl_[0][1]);
                mma16816(acc[mi][1], a[mi], bl_[0][2], bl_[0][3]);
                mma16816(acc[mi][2], a[mi], bl_[1][0], bl_[1][1]);
                mma16816(acc[mi][3], a[mi], bl_[1][2], bl_[1][3]);
            }
#pragma unroll
            for (int mi = 0; mi < 4; mi++)
                ldsm_x4(a[mi], al_b[s] +
                        (uint32_t)((a_row + mi * 16) * LDT + k0 + a_col) * 2);
#pragma unroll
            for (int mi = 0; mi < 4; mi++) {
                mma16816(acc[mi][0], a[mi], bh_[0][0], bh_[0][1]);
                mma16816(acc[mi][1], a[mi], bh_[0][2], bh_[0][3]);
                mma16816(acc[mi][2], a[mi], bh_[1][0], bh_[1][1]);
                mma16816(acc[mi][3], a[mi], bh_[1][2], bh_[1][3]);
            }
        }
        __syncthreads();
        if (kt + 2 < KVNITF) stage(kt + 2);
    }

    const int lr = lane >> 2;
    const int c0 = wn + ((lane & 3) << 1);
    float* dst = kvtf + (size_t)bh * DHc * Mc;
#pragma unroll
    for (int mi = 0; mi < 4; mi++) {
        const int d0 = mi * 16 + lr;
        const int d1 = d0 + 8;
#pragma unroll
        for (int ni = 0; ni < 4; ni++) {
            int c = c0 + ni * 8;
            atomicAdd(&dst[d0 * Mc + c],     acc[mi][ni][0]);
            atomicAdd(&dst[d0 * Mc + c + 1], acc[mi][ni][1]);
            atomicAdd(&dst[d1 * Mc + c],     acc[mi][ni][2]);
            atomicAdd(&dst[d1 * Mc + c + 1], acc[mi][ni][3]);
        }
    }
}

// ============================================================
// kvtf fp32 -> kvthi/kvtlo
// ============================================================
__global__ __launch_bounds__(256) void kvsplit_kernel(
    const float* __restrict__ kvtf, bf16* __restrict__ Thi, bf16* __restrict__ Tlo)
{
    int i = blockIdx.x * 256 + threadIdx.x;
    float v = kvtf[i];
    bf16 h, l; split2(v, h, l);
    Thi[i] = h; Tlo[i] = l;
}

// ============================================================
// attn via mma bf16x3 — fused-pass + fused z (unchanged)
// ============================================================
#define ANITF 8
#define ATT_AMS (256 * LDT * 2)
#define ATT_BMS (64 * LDT * 2)
#define ATT_STAGEF (2 * ATT_AMS + 2 * ATT_BMS)
#define ATT_SMEMF (2 * ATT_STAGEF + 512 * 4)

__global__ __launch_bounds__(256, 2) void attn_mma_kernel(
    const bf16* __restrict__ qfhi, const bf16* __restrict__ qflo,
    const bf16* __restrict__ kvthi, const bf16* __restrict__ kvtlo,
    const float* __restrict__ ksum,
    bf16* __restrict__ Ohi, bf16* __restrict__ Olo)
{
    extern __shared__ char asm_[];
    const int bh = blockIdx.y;
    const int b = bh >> 4, h = bh & 15;
    const int l0 = blockIdx.x * 256;
    const int tid = threadIdx.x;
    const int lane = tid & 31, wid = tid >> 5;
    const int wm = (wid >> 1) * 64;
    const int wn = (wid & 1) * 32;

    uint32_t ah_b[2], al_b[2], bh_b[2], bl_b[2];
#pragma unroll
    for (int s = 0; s < 2; s++) {
        uint32_t base = smem_u32(asm_ + s * ATT_STAGEF);
        ah_b[s] = base;
        al_b[s] = base + ATT_AMS;
        bh_b[s] = base + 2 * ATT_AMS;
        bl_b[s] = base + 2 * ATT_AMS + ATT_BMS;
    }
    float* ksum_s = (float*)(asm_ + 2 * ATT_STAGEF);
    float* zden   = ksum_s + 256;

    const int a_row = wm + (lane & 15);
    const int a_col = (lane >> 4) << 3;
    const int b_row = wn + (lane & 7) + ((lane >> 4) << 3);
    const int b_col = ((lane >> 3) & 1) << 3;

    const size_t qbase = ((size_t)bh * Lc + l0) * Mc;
    const size_t kbase = (size_t)bh * DHc * Mc;

    const int ga_row = tid >> 2, ga_c8 = (tid & 3) << 3;

    ksum_s[tid] = ksum[bh * Mc + tid];

    auto stage = [&](int kt) {
        const int s  = kt & 1;
        const int kk = kt << 5;
#pragma unroll
        for (int i = 0; i < 4; i++) {
            int row = ga_row + i * 64;
            uint32_t soff = (uint32_t)(row * LDT + ga_c8) * 2;
            const size_t ga = qbase + (size_t)row * Mc + kk + ga_c8;
            cp_async16(ah_b[s] + soff, qfhi + ga);
            cp_async16(al_b[s] + soff, qflo + ga);
        }
        uint32_t bsoff = (uint32_t)(ga_row * LDT + ga_c8) * 2;
        const size_t gb = kbase + (size_t)ga_row * Mc + kk + ga_c8;
        cp_async16(bh_b[s] + bsoff, kvthi + gb);
        cp_async16(bl_b[s] + bsoff, kvtlo + gb);
        CP_COMMIT();
    };

    float acc[4][4][4];
#pragma unroll
    for (int mi = 0; mi < 4; mi++)
#pragma unroll
        for (int ni = 0; ni < 4; ni++)
#pragma unroll
            for (int e = 0; e < 4; e++) acc[mi][ni][e] = 0.f;
    float den = 0.f;

    stage(0); stage(1);

    for (int kt = 0; kt < ANITF; kt++) {
        const int s = kt & 1;
        if (kt + 1 < ANITF) CP_WAIT(1); else CP_WAIT(0);
        __syncthreads();

        {
            const bf16* ah_row = (const bf16*)(asm_ + s * ATT_STAGEF) + tid * LDT;
            const bf16* al_row = (const bf16*)(asm_ + s * ATT_STAGEF + ATT_AMS) + tid * LDT;
            const float* ks = ksum_s + (kt << 5);
#pragma unroll
            for (int c2 = 0; c2 < 16; c2++) {
                __nv_bfloat162 hh = *(const __nv_bfloat162*)&ah_row[c2 * 2];
                __nv_bfloat162 ll = *(const __nv_bfloat162*)&al_row[c2 * 2];
                den += (__bfloat162float(hh.x) + __bfloat162float(ll.x)) * ks[c2 * 2];
                den += (__bfloat162float(hh.y) + __bfloat162float(ll.y)) * ks[c2 * 2 + 1];
            }
        }

#pragma unroll
        for (int k0 = 0; k0 < 32; k0 += 16) {
            uint32_t bh_[2][4], bl_[2][4];
#pragma unroll
            for (int pr = 0; pr < 2; pr++) {
                uint32_t boff = (uint32_t)((b_row + pr * 16) * LDT + k0 + b_col) * 2;
                ldsm_x4(bh_[pr], bh_b[s] + boff);
                ldsm_x4(bl_[pr], bl_b[s] + boff);
            }
            uint32_t a[4][4];
#pragma unroll
            for (int mi = 0; mi < 4; mi++)
                ldsm_x4(a[mi], ah_b[s] +
                        (uint32_t)((a_row + mi * 16) * LDT + k0 + a_col) * 2);
#pragma unroll
            for (int mi = 0; mi < 4; mi++) {
                mma16816(acc[mi][0], a[mi], bh_[0][0], bh_[0][1]);
                mma16816(acc[mi][1], a[mi], bh_[0][2], bh_[0][3]);
                mma16816(acc[mi][2], a[mi], bh_[1][0], bh_[1][1]);
                mma16816(acc[mi][3], a[mi], bh_[1][2], bh_[1][3]);
            }
#pragma unroll
            for (int mi = 0; mi < 4; mi++) {
                mma16816(acc[mi][0], a[mi], bl_[0][0], bl_[0][1]);
                mma16816(acc[mi][1], a[mi], bl_[0][2], bl_[0][3]);
                mma16816(acc[mi][2], a[mi], bl_[1][0], bl_[1][1]);
                mma16816(acc[mi][3], a[mi], bl_[1][2], bl_[1][3]);
            }
#pragma unroll
            for (int mi = 0; mi < 4; mi++)
                ldsm_x4(a[mi], al_b[s] +
                        (uint32_t)((a_row + mi * 16) * LDT + k0 + a_col) * 2);
#pragma unroll
            for (int mi = 0; mi < 4; mi++) {
                mma16816(acc[mi][0], a[mi], bh_[0][0], bh_[0][1]);
                mma16816(acc[mi][1], a[mi], bh_[0][2], bh_[0][3]);
                mma16816(acc[mi][2], a[mi], bh_[1][0], bh_[1][1]);
                mma16816(acc[mi][3], a[mi], bh_[1][2], bh_[1][3]);
            }
        }
        __syncthreads();
        if (kt + 2 < ANITF) stage(kt + 2);
    }

    zden[tid] = 1.0f / (den + 1e-6f);
    __syncthreads();

    const int lr = lane >> 2;
    const int occ0 = wn + ((lane & 3) << 1);
#pragma unroll
    for (int mi = 0; mi < 4; mi++) {
        const int r0 = wm + mi * 16 + lr;
        const int r1 = r0 + 8;
        const float z0 = zden[r0];
        const float z1 = zden[r1];
        const size_t i0 = (size_t)(b * Lc + l0 + r0) * Dc + h * DHc;
        const size_t i1 = (size_t)(b * Lc + l0 + r1) * Dc + h * DHc;
#pragma unroll
        for (int ni = 0; ni < 4; ni++) {
            int c = occ0 + ni * 8;
            bf16 h0,l0b,h1,l1b,h2,l2b,h3,l3b;
            split2(acc[mi][ni][0] * z0, h0, l0b);
            split2(acc[mi][ni][1] * z0, h1, l1b);
            split2(acc[mi][ni][2] * z1, h2, l2b);
            split2(acc[mi][ni][3] * z1, h3, l3b);
            *(__nv_bfloat162*)&Ohi[i0 + c] = __halves2bfloat162(h0, h1);
            *(__nv_bfloat162*)&Ohi[i1 + c] = __halves2bfloat162(h2, h3);
            *(__nv_bfloat162*)&Olo[i0 + c] = __halves2bfloat162(l0b, l1b);
            *(__nv_bfloat162*)&Olo[i1 + c] = __halves2bfloat162(l2b, l3b);
        }
    }
}

// ============================================================
// LayerNorm + duplicate rows
// ============================================================
__global__ __launch_bounds__(256) void ln_dup_kernel(
    const float* __restrict__ y, const float* __restrict__ g,
    const float* __restrict__ beta, float* __restrict__ out)
{
    __shared__ float red[18];
    const int row = blockIdx.x;
    const int b = row >> 12, l = row & 4095;
    const int tid = threadIdx.x;
    const float* yr = y + (size_t)row * Dc;

    float v[4];
    float s = 0.f, ss = 0.f;
#pragma unroll
    for (int i = 0; i < 4; i++) {
        float t = yr[tid + i * 256];
        v[i] = t; s += t; ss += t * t;
    }
#pragma unroll
    for (int off = 16; off; off >>= 1) {
        s  += __shfl_xor_sync(0xffffffffu, s, off);
        ss += __shfl_xor_sync(0xffffffffu, ss, off);
    }
    const int w = tid >> 5, lane = tid & 31;
    if (lane == 0) { red[w] = s; red[8 + w] = ss; }
    __syncthreads();
    if (tid == 0) {
        float ts = 0.f, tss = 0.f;
#pragma unroll
        for (int i = 0; i < 8; i++) { ts += red[i]; tss += red[8 + i]; }
        float mean = ts * (1.0f / 1024.0f);
        float var = tss * (1.0f / 1024.0f) - mean * mean;
        red[16] = mean;
        red[17] = rsqrtf(var + 1e-5f);
    }
    __syncthreads();
    const float mean = red[16], rstd = red[17];
    float* o0 = out + ((size_t)b * 8192 + 2 * (size_t)l) * Dc;
#pragma unroll
    for (int i = 0; i < 4; i++) {
        int c = tid + i * 256;
        float o = (v[i] - mean) * rstd * g[c] + beta[c];
        o0[c] = o;
        o0[Dc + c] = o;
    }
}

// ============================================================
// host launch
// ============================================================
extern "C" void kernel_launch(void* const* d_in, const int* in_sizes, int n_in,
                              void* d_out, int out_size)
{
    const float* x    = (const float*)d_in[0];
    const float* Wq   = (const float*)d_in[1];
    const float* Wk   = (const float*)d_in[2];
    const float* Wv   = (const float*)d_in[3];
    const float* Wo   = (const float*)d_in[4];
    const float* proj = (const float*)d_in[5];
    const float* ln_g = (const float*)d_in[6];
    const float* ln_b = (const float*)d_in[7];
    float* out = (float*)d_out;

    float *v, *kvtf, *ksum, *y;
    bf16 *qfhi, *qflo, *kfthi, *kftlo, *vthi, *vtlo, *kvthi, *kvtlo;
    bf16 *ahi, *alo, *bthi, *btlo, *qhi, *qlo, *khi, *klo, *phi, *plo;
    cudaGetSymbolAddress((void**)&v,     g_v);
    cudaGetSymbolAddress((void**)&qfhi,  g_qfhi);
    cudaGetSymbolAddress((void**)&qflo,  g_qflo);
    cudaGetSymbolAddress((void**)&kfthi, g_kfthi);
    cudaGetSymbolAddress((void**)&kftlo, g_kftlo);
    cudaGetSymbolAddress((void**)&vthi,  g_vthi);
    cudaGetSymbolAddress((void**)&vtlo,  g_vtlo);
    cudaGetSymbolAddress((void**)&kvtf,  g_kvtf);
    cudaGetSymbolAddress((void**)&kvthi, g_kvthi);
    cudaGetSymbolAddress((void**)&kvtlo, g_kvtlo);
    cudaGetSymbolAddress((void**)&ksum,  g_ksum);
    cudaGetSymbolAddress((void**)&y,     g_y);
    cudaGetSymbolAddress((void**)&ahi,   g_ahi);
    cudaGetSymbolAddress((void**)&alo,   g_alo);
    cudaGetSymbolAddress((void**)&bthi,  g_bthi);
    cudaGetSymbolAddress((void**)&btlo,  g_btlo);
    cudaGetSymbolAddress((void**)&qhi,   g_qhi);
    cudaGetSymbolAddress((void**)&qlo,   g_qlo);
    cudaGetSymbolAddress((void**)&khi,   g_khi);
    cudaGetSymbolAddress((void**)&klo,   g_klo);
    cudaGetSymbolAddress((void**)&phi,   g_phi);
    cudaGetSymbolAddress((void**)&plo,   g_plo);

    const float qscale = 0.35355339059327379f;  // 64^-0.25

    cudaFuncSetAttribute(mma_gemm_kernel<0>,
                         cudaFuncAttributeMaxDynamicSharedMemorySize, GEMM_SMEMF);
    cudaFuncSetAttribute(mma_gemm_kernel<1>,
                         cudaFuncAttributeMaxDynamicSharedMemorySize, GEMM_SMEMF);
    cudaFuncSetAttribute(feature_mma_kernel<1>,
                         cudaFuncAttributeMaxDynamicSharedMemorySize, FEAT3_SMEM);
    cudaFuncSetAttribute(feature_mma_kernel<2>,
                         cudaFuncAttributeMaxDynamicSharedMemorySize, FEAT3_SMEM);
    cudaFuncSetAttribute(kv_mma_kernel,
                         cudaFuncAttributeMaxDynamicSharedMemorySize, KV_SMEMF);
    cudaFuncSetAttribute(attn_mma_kernel,
                         cudaFuncAttributeMaxDynamicSharedMemorySize, ATT_SMEMF);

    // prep: x/proj splits + ksum/kvtf zero in ONE launch
    prep_kernel<<<PREP_BLOCKS, 256>>>(x, ahi, alo, proj, phi, plo, ksum, kvtf);
    tsplit4_kernel<<<dim3(32, 32, 4), dim3(32, 8)>>>(Wq, Wk, Wv, Wo, bthi, btlo);

    // fused QKV GEMM (V -> fp32)
    mma_gemm_kernel<0><<<dim3(24, 64), 256, GEMM_SMEMF>>>(
        ahi, alo, bthi, btlo, v, qhi, qlo, khi, klo, qscale);

    // features (64-row tiles, 2 CTAs/SM)
    feature_mma_kernel<1><<<dim3(Lc / 64, BHc), 256, FEAT3_SMEM>>>(
        qhi, qlo, phi, plo, qfhi, qflo, nullptr);
    feature_mma_kernel<2><<<dim3(Lc / 64, BHc), 256, FEAT3_SMEM>>>(
        khi, klo, phi, plo, kfthi, kftlo, ksum);

    // v transpose+split, then kv via tensor cores
    vt_kernel<<<dim3(Lc / 32, BHc), 256>>>(v, vthi, vtlo);
    kv_mma_kernel<<<dim3(8, BHc), 256, KV_SMEMF>>>(vthi, vtlo, kfthi, kftlo, kvtf);
    kvsplit_kernel<<<(BHc * DHc * Mc) / 256, 256>>>(kvtf, kvthi, kvtlo);

    // attn (z fused) -> hi/lo directly into O-GEMM A buffers
    attn_mma_kernel<<<dim3(Lc / 256, BHc), 256, ATT_SMEMF>>>(
        qfhi, qflo, kvthi, kvtlo, ksum, ahi, alo);

    // O projection + exact GELU (weights at offset 3)
    mma_gemm_kernel<1><<<dim3(8, 64), 256, GEMM_SMEMF>>>(
        ahi, alo, bthi + (size_t)3 * Dc * Dc, btlo + (size_t)3 * Dc * Dc,
        y, nullptr, nullptr, nullptr, nullptr, 1.0f);

    ln_dup_kernel<<<ROWS, 256>>>(y, ln_g, ln_b, out);
}